// round 11
// baseline (speedup 1.0000x reference)
#include <cuda_runtime.h>
#include <cuda_fp16.h>
#include <math.h>
#include <stdint.h>

#define HID 128
#define NN 20000
#define NE 640000
#define ND 100000

// scratch (device globals: allocation-free contract)
__device__ float g_hn0[(size_t)NN * HID];
__device__ float g_hn1[(size_t)NN * HID];
__device__ float g_agg[(size_t)NN * HID];
__device__ float g_P1 [(size_t)NN * HID];
__device__ float g_P3 [(size_t)NN * HID];
// fp16 weight images, [n][k] row-major
__device__ __align__(16) __half g_Wh [2][128 * 128];       // W_mid (single)
__device__ __align__(16) __half g_Wp1[2][128 * 128];       // layer P1 (single)
__device__ __align__(16) __half g_Wp3[2][128 * 128];       // layer P3 (single)
__device__ __align__(16) __half g_Wuh[2][2][128 * 128];    // W_upd hi, [layer][kphase]
__device__ __align__(16) __half g_Wul[2][2][128 * 128];    // W_upd lo
__device__ __align__(16) __half g_Wq1h[128 * 128];         // readout Q1 hi/lo
__device__ __align__(16) __half g_Wq1l[128 * 128];
__device__ __align__(16) __half g_Wq3h[128 * 128];
__device__ __align__(16) __half g_Wq3l[128 * 128];
// edge sort-by-dst (+ pre-permuted fp16 edge features)
__device__ int g_cnt[NN + 1];
__device__ int g_srcp[NE];
__device__ int g_dstp[NE];
__device__ __align__(16) __half g_efh[(size_t)NE * 16];

// ======================= helpers =======================
__device__ __forceinline__ uint32_t smem_u32(const void* p) {
    uint32_t a;
    asm("{ .reg .u64 t; cvta.to.shared.u64 t, %1; cvt.u32.u64 %0, t; }" : "=r"(a) : "l"(p));
    return a;
}
__device__ __forceinline__ void ldsm4(uint32_t& r0, uint32_t& r1, uint32_t& r2, uint32_t& r3,
                                      uint32_t addr) {
    asm volatile("ldmatrix.sync.aligned.m8n8.x4.shared.b16 {%0,%1,%2,%3}, [%4];"
                 : "=r"(r0), "=r"(r1), "=r"(r2), "=r"(r3) : "r"(addr));
}
__device__ __forceinline__ void mma16816h(float* c, uint32_t a0, uint32_t a1, uint32_t a2,
                                          uint32_t a3, uint32_t b0, uint32_t b1) {
    asm volatile("mma.sync.aligned.m16n8k16.row.col.f32.f16.f16.f32 "
                 "{%0,%1,%2,%3}, {%4,%5,%6,%7}, {%8,%9}, {%0,%1,%2,%3};"
                 : "+f"(c[0]), "+f"(c[1]), "+f"(c[2]), "+f"(c[3])
                 : "r"(a0), "r"(a1), "r"(a2), "r"(a3), "r"(b0), "r"(b1));
}
__device__ __forceinline__ uint32_t pack2h(float v0, float v1) {
    __half h0 = __float2half_rn(v0);
    __half h1 = __float2half_rn(v1);
    return (uint32_t)__half_as_ushort(h0) | ((uint32_t)__half_as_ushort(h1) << 16);
}
__device__ __forceinline__ void split2h(float v0, float v1, uint32_t& hi, uint32_t& lo) {
    __half h0 = __float2half_rn(v0);
    __half h1 = __float2half_rn(v1);
    __half m0 = __float2half_rn(v0 - __half2float(h0));
    __half m1 = __float2half_rn(v1 - __half2float(h1));
    hi = (uint32_t)__half_as_ushort(h0) | ((uint32_t)__half_as_ushort(h1) << 16);
    lo = (uint32_t)__half_as_ushort(m0) | ((uint32_t)__half_as_ushort(m1) << 16);
}
__device__ __forceinline__ void cp16(uint32_t smem_dst, const void* gsrc) {
    asm volatile("cp.async.cg.shared.global [%0], [%1], 16;"
                 :: "r"(smem_dst), "l"(gsrc) : "memory");
}
#define CP_COMMIT()  asm volatile("cp.async.commit_group;" ::: "memory")
#define CP_WAIT(N)   asm volatile("cp.async.wait_group %0;" :: "n"(N) : "memory")

// ---------------------------------------------------------------- sort by dst
__global__ void zcnt()
{
    int i = blockIdx.x * 256 + threadIdx.x;
    if (i <= NN) g_cnt[i] = 0;
}
__global__ void hist(const int* __restrict__ eidx)
{
    int e = blockIdx.x * 256 + threadIdx.x;
    atomicAdd(&g_cnt[eidx[NE + e]], 1);
}
__global__ void scan20k()
{
    __shared__ int part[1024];
    __shared__ int wsum[32];
    const int tid = threadIdx.x;
    const int CH = 20;
    int base = tid * CH;
    int loc[CH];
    int s = 0;
#pragma unroll
    for (int i = 0; i < CH; i++) {
        int v = (base + i <= NN) ? g_cnt[base + i] : 0;
        loc[i] = s; s += v;
    }
    part[tid] = s;
    __syncthreads();
    int lane = tid & 31, w = tid >> 5;
    int v = part[tid];
#pragma unroll
    for (int o = 1; o < 32; o <<= 1) { int t = __shfl_up_sync(~0u, v, o); if (lane >= o) v += t; }
    if (lane == 31) wsum[w] = v;
    __syncthreads();
    if (w == 0) {
        int x = wsum[lane];
#pragma unroll
        for (int o = 1; o < 32; o <<= 1) { int t = __shfl_up_sync(~0u, x, o); if (lane >= o) x += t; }
        wsum[lane] = x;
    }
    __syncthreads();
    int excl = v - part[tid] + (w ? wsum[w - 1] : 0);
#pragma unroll
    for (int i = 0; i < CH; i++)
        if (base + i <= NN) g_cnt[base + i] = excl + loc[i];
}
__global__ void scatter(const int* __restrict__ eidx, const float* __restrict__ ef)
{
    int e = blockIdx.x * 256 + threadIdx.x;
    int s = eidx[e], d = eidx[NE + e];
    int p = atomicAdd(&g_cnt[d], 1);
    g_srcp[p] = s; g_dstp[p] = d;
    const float4* eg = (const float4*)(ef + (size_t)e * 16);
    float4 v0 = eg[0], v1 = eg[1], v2 = eg[2], v3 = eg[3];
    uint4* dh = (uint4*)(g_efh + (size_t)p * 16);
    dh[0] = make_uint4(pack2h(v0.x, v0.y), pack2h(v0.z, v0.w),
                       pack2h(v1.x, v1.y), pack2h(v1.z, v1.w));
    dh[1] = make_uint4(pack2h(v2.x, v2.y), pack2h(v2.z, v2.w),
                       pack2h(v3.x, v3.y), pack2h(v3.z, v3.w));
}

// ---------------------------------------------------------------- node embed
__global__ void node_embed(const float* __restrict__ x, const float* __restrict__ W,
                           const float* __restrict__ b)
{
    __shared__ float Ws[32 * HID];
    __shared__ float xs[16][33];
    int tid = threadIdx.x; // 128
    for (int i = tid; i < 32 * HID; i += 128) Ws[i] = W[i];
    int row0 = blockIdx.x * 16;
    for (int i = tid; i < 16 * 32; i += 128) xs[i >> 5][i & 31] = x[(size_t)row0 * 32 + i];
    float bb = b[tid];
    __syncthreads();
#pragma unroll 4
    for (int r = 0; r < 16; r++) {
        float acc = bb;
#pragma unroll
        for (int k = 0; k < 32; k++) acc = fmaf(xs[r][k], Ws[k * HID + tid], acc);
        g_hn0[(size_t)(row0 + r) * HID + tid] = fmaxf(acc, 0.f);
    }
}

// ------------------------------ weight prep: fp16 [n][k] images
__global__ void prep_all(const float* __restrict__ Wm0, const float* __restrict__ Wm1,
                         const float* __restrict__ Wu0, const float* __restrict__ Wu1,
                         const float* __restrict__ Wr1)
{
    int b = blockIdx.x;
    if (b < 6) {
        const float* src; __half* dst;
        switch (b) {
            case 0: src = Wm0 + 128 * 128; dst = g_Wh[0];  break;
            case 1: src = Wm1 + 128 * 128; dst = g_Wh[1];  break;
            case 2: src = Wm0;             dst = g_Wp1[0]; break;
            case 3: src = Wm1;             dst = g_Wp1[1]; break;
            case 4: src = Wm0 + 256 * 128; dst = g_Wp3[0]; break;
            default: src = Wm1 + 256 * 128; dst = g_Wp3[1]; break;
        }
        for (int idx = threadIdx.x; idx < 128 * 128; idx += 256) {
            int n = idx >> 7, k = idx & 127;
            dst[idx] = __float2half_rn(src[k * 128 + n]);
        }
    } else if (b < 10) {
        int l = (b - 6) >> 1, p = (b - 6) & 1;
        const float* src = (l ? Wu1 : Wu0) + p * 128 * 128;
        __half* dh = g_Wuh[l][p];
        __half* dl = g_Wul[l][p];
        for (int idx = threadIdx.x; idx < 128 * 128; idx += 256) {
            int n = idx >> 7, k = idx & 127;
            float w = src[k * 128 + n];
            __half h = __float2half_rn(w);
            dh[idx] = h;
            dl[idx] = __float2half_rn(w - __half2float(h));
        }
    } else {
        const float* src = (b == 10) ? Wr1 : (Wr1 + 128 * 128);
        __half* dh = (b == 10) ? g_Wq1h : g_Wq3h;
        __half* dl = (b == 10) ? g_Wq1l : g_Wq3l;
        for (int idx = threadIdx.x; idx < 128 * 128; idx += 256) {
            int n = idx >> 7, k = idx & 127;
            float w = src[k * 128 + n];
            __half h = __float2half_rn(w);
            dh[idx] = h;
            dl[idx] = __float2half_rn(w - __half2float(h));
        }
    }
}

// ---------------- fp16 node-level dual GEMM: P1 = A@W1, P3 = A@W3 (+agg zero)
#define GX_A 0
#define GX_W 34816            // [256 rows][136 fp16]
#define GX_TOTAL 104448
#define GXST 272

__global__ void __launch_bounds__(256)
gemmx2h(int asel, int img, int zflag)
{
    extern __shared__ __align__(16) char smem[];
    const uint32_t sb = smem_u32(smem);
    const float* __restrict__ A = asel ? g_hn1 : g_hn0;
    const int tid = threadIdx.x;
    const int wid = tid >> 5, lane = tid & 31;
    const int nBase = blockIdx.x * 128;

    {
        int r = tid >> 1, u = tid & 1;
        int nrow = min(nBase + r, NN - 1);
        const float4* src = (const float4*)(A + (size_t)nrow * HID) + u * 16;
        uint32_t dst = (uint32_t)(GX_A + r * GXST + u * 128);
#pragma unroll
        for (int q = 0; q < 8; q++) {
            float4 a = src[2 * q], bv = src[2 * q + 1];
            *(uint4*)(smem + dst + q * 16) =
                make_uint4(pack2h(a.x, a.y), pack2h(a.z, a.w),
                           pack2h(bv.x, bv.y), pack2h(bv.z, bv.w));
        }
    }
    {
        const uint4* w1 = (const uint4*)g_Wp1[img];
        const uint4* w3 = (const uint4*)g_Wp3[img];
#pragma unroll
        for (int i = 0; i < 8; i++) {
            int g = tid + i * 256;
            int n = g >> 4, q = g & 15;
            *(uint4*)(smem + GX_W + n * GXST + q * 16) = w1[g];
            *(uint4*)(smem + GX_W + (n + 128) * GXST + q * 16) = w3[g];
        }
    }
    if (zflag) {
#pragma unroll
        for (int i = 0; i < 16; i++) {
            int g = tid + i * 256;
            int r = g >> 5, c = (g & 31) * 4;
            int row = nBase + r;
            if (row < NN)
                *(float4*)&g_agg[(size_t)row * HID + c] = make_float4(0.f, 0.f, 0.f, 0.f);
        }
    }
    __syncthreads();

    const int wm = wid * 16;
    const uint32_t aA = sb + GX_A + (uint32_t)((wm + (lane & 7) + ((lane >> 3) & 1) * 8) * GXST
                                               + (lane >> 4) * 16);
    const uint32_t bOff = (uint32_t)(((lane & 7) + (lane >> 4) * 8) * GXST
                                     + (((lane >> 3) & 1) * 8) * 2);
    const int er0 = wm + (lane >> 2);
    const int cb  = (lane & 3) * 2;
    const int row0 = nBase + er0, row1 = row0 + 8;

    uint32_t aH[8][4];
#pragma unroll
    for (int ks = 0; ks < 8; ks++)
        ldsm4(aH[ks][0], aH[ks][1], aH[ks][2], aH[ks][3], aA + ks * 32);

#pragma unroll
    for (int half = 0; half < 2; half++) {
        const uint32_t bA = sb + GX_W + half * (128 * GXST) + bOff;
        float acc[16][4];
#pragma unroll
        for (int n = 0; n < 16; n++)
#pragma unroll
            for (int j = 0; j < 4; j++) acc[n][j] = 0.f;
#pragma unroll
        for (int ks = 0; ks < 8; ks++) {
#pragma unroll
            for (int np = 0; np < 8; np++) {
                uint32_t b0, b1, b2, b3;
                ldsm4(b0, b1, b2, b3, bA + np * (16 * GXST) + ks * 32);
                mma16816h(acc[2 * np],     aH[ks][0], aH[ks][1], aH[ks][2], aH[ks][3], b0, b1);
                mma16816h(acc[2 * np + 1], aH[ks][0], aH[ks][1], aH[ks][2], aH[ks][3], b2, b3);
            }
        }
        float* out = half ? g_P3 : g_P1;
#pragma unroll
        for (int nt = 0; nt < 16; nt++) {
            int col = nt * 8 + cb;
            if (row0 < NN)
                *(float2*)&out[(size_t)row0 * HID + col] = make_float2(acc[nt][0], acc[nt][1]);
            if (row1 < NN)
                *(float2*)&out[(size_t)row1 * HID + col] = make_float2(acc[nt][2], acc[nt][3]);
        }
    }
}

// ---------------- exact (3-product) update GEMM, split-K; layer1 chains Q GEMMs
#define UX_AH 0
#define UX_AL 34816
#define UX_WH 69632
#define UX_WL 104448
#define UX_B  139264
#define UX_TOTAL 139776
#define UXST 272

__global__ void __launch_bounds__(256)
upd_x(int layer, const float* __restrict__ bias)
{
    extern __shared__ __align__(16) char smem[];
    const uint32_t sb = smem_u32(smem);
    const float* __restrict__ hn   = layer ? g_hn1 : g_hn0;
    float*       __restrict__ hout = layer ? g_hn0 : g_hn1;
    const int tid = threadIdx.x;
    const int wid = tid >> 5, lane = tid & 31;
    const int nBase = blockIdx.x * 128;
    float* sB = (float*)(smem + UX_B);
    if (tid < 128) sB[tid] = bias[tid];

    const int wm = wid * 16;
    const uint32_t aOff = (uint32_t)((wm + (lane & 7) + ((lane >> 3) & 1) * 8) * UXST
                                     + (lane >> 4) * 16);
    const uint32_t bOff = (uint32_t)(((lane & 7) + (lane >> 4) * 8) * UXST
                                     + (((lane >> 3) & 1) * 8) * 2);
    const int er0 = wm + (lane >> 2);
    const int cb  = (lane & 3) * 2;
    const int row0 = nBase + er0, row1 = row0 + 8;

    float acc[16][4];
#pragma unroll
    for (int n = 0; n < 16; n++)
#pragma unroll
        for (int j = 0; j < 4; j++) acc[n][j] = 0.f;

    for (int p = 0; p < 2; p++) {
        // stage A (fp32 -> fp16 hi/lo)
        {
            int r = tid >> 1, u = tid & 1;
            int nrow = min(nBase + r, NN - 1);
            const float4* src = (const float4*)((p ? g_agg : hn) + (size_t)nrow * HID) + u * 16;
            uint32_t da = (uint32_t)(UX_AH + r * UXST + u * 128);
            uint32_t dl = (uint32_t)(UX_AL + r * UXST + u * 128);
#pragma unroll
            for (int q = 0; q < 8; q++) {
                float4 a = src[2 * q], bv = src[2 * q + 1];
                uint32_t h0, l0, h1, l1, h2, l2, h3, l3;
                split2h(a.x, a.y, h0, l0);  split2h(a.z, a.w, h1, l1);
                split2h(bv.x, bv.y, h2, l2); split2h(bv.z, bv.w, h3, l3);
                *(uint4*)(smem + da + q * 16) = make_uint4(h0, h1, h2, h3);
                *(uint4*)(smem + dl + q * 16) = make_uint4(l0, l1, l2, l3);
            }
        }
        // stage W hi/lo images
        {
            const uint4* wh = (const uint4*)g_Wuh[layer][p];
            const uint4* wl = (const uint4*)g_Wul[layer][p];
#pragma unroll
            for (int i = 0; i < 8; i++) {
                int g = tid + i * 256;
                int n = g >> 4, q = g & 15;
                *(uint4*)(smem + UX_WH + n * UXST + q * 16) = wh[g];
                *(uint4*)(smem + UX_WL + n * UXST + q * 16) = wl[g];
            }
        }
        __syncthreads();

#pragma unroll
        for (int ks = 0; ks < 8; ks++) {
            uint32_t ah0, ah1, ah2, ah3, al0, al1, al2, al3;
            ldsm4(ah0, ah1, ah2, ah3, sb + UX_AH + aOff + ks * 32);
            ldsm4(al0, al1, al2, al3, sb + UX_AL + aOff + ks * 32);
#pragma unroll
            for (int np = 0; np < 8; np++) {
                uint32_t bh0, bh1, bh2, bh3, bl0, bl1, bl2, bl3;
                ldsm4(bh0, bh1, bh2, bh3, sb + UX_WH + bOff + np * (16 * UXST) + ks * 32);
                ldsm4(bl0, bl1, bl2, bl3, sb + UX_WL + bOff + np * (16 * UXST) + ks * 32);
                mma16816h(acc[2 * np],     ah0, ah1, ah2, ah3, bh0, bh1);
                mma16816h(acc[2 * np],     ah0, ah1, ah2, ah3, bl0, bl1);
                mma16816h(acc[2 * np],     al0, al1, al2, al3, bh0, bh1);
                mma16816h(acc[2 * np + 1], ah0, ah1, ah2, ah3, bh2, bh3);
                mma16816h(acc[2 * np + 1], ah0, ah1, ah2, ah3, bl2, bl3);
                mma16816h(acc[2 * np + 1], al0, al1, al2, al3, bh2, bh3);
            }
        }
        __syncthreads();
    }

    // epilogue: bias + relu (in place), write hout
#pragma unroll
    for (int nt = 0; nt < 16; nt++) {
        int col = nt * 8 + cb;
        float b0 = sB[col], b1 = sB[col + 1];
        acc[nt][0] = fmaxf(acc[nt][0] + b0, 0.f);
        acc[nt][1] = fmaxf(acc[nt][1] + b1, 0.f);
        acc[nt][2] = fmaxf(acc[nt][2] + b0, 0.f);
        acc[nt][3] = fmaxf(acc[nt][3] + b1, 0.f);
        if (row0 < NN)
            *(float2*)&hout[(size_t)row0 * HID + col] = make_float2(acc[nt][0], acc[nt][1]);
        if (row1 < NN)
            *(float2*)&hout[(size_t)row1 * HID + col] = make_float2(acc[nt][2], acc[nt][3]);
    }

    if (layer == 1) {
        // split hn2 (exact, in regs) into A fragments via acc->Afrag identity
        uint32_t aH[8][4], aL[8][4];
#pragma unroll
        for (int nt = 0; nt < 16; nt++) {
            int ks = nt >> 1, j0 = (nt & 1) * 2;
            split2h(acc[nt][0], acc[nt][1], aH[ks][j0],     aL[ks][j0]);
            split2h(acc[nt][2], acc[nt][3], aH[ks][j0 + 1], aL[ks][j0 + 1]);
        }
        // restage Q weights over dead A/W regions
        {
            const uint4* q1h = (const uint4*)g_Wq1h;
            const uint4* q1l = (const uint4*)g_Wq1l;
            const uint4* q3h = (const uint4*)g_Wq3h;
            const uint4* q3l = (const uint4*)g_Wq3l;
#pragma unroll
            for (int i = 0; i < 8; i++) {
                int g = tid + i * 256;
                int n = g >> 4, q = g & 15;
                *(uint4*)(smem + UX_AH + n * UXST + q * 16) = q1h[g];
                *(uint4*)(smem + UX_AL + n * UXST + q * 16) = q1l[g];
                *(uint4*)(smem + UX_WH + n * UXST + q * 16) = q3h[g];
                *(uint4*)(smem + UX_WL + n * UXST + q * 16) = q3l[g];
            }
        }
        __syncthreads();

#pragma unroll
        for (int o = 0; o < 2; o++) {
            const uint32_t bHA = sb + (o ? UX_WH : UX_AH) + bOff;
            const uint32_t bLA = sb + (o ? UX_WL : UX_AL) + bOff;
            float q[16][4];
#pragma unroll
            for (int n = 0; n < 16; n++)
#pragma unroll
                for (int j = 0; j < 4; j++) q[n][j] = 0.f;
#pragma unroll
            for (int ks = 0; ks < 8; ks++) {
#pragma unroll
                for (int np = 0; np < 8; np++) {
                    uint32_t bh0, bh1, bh2, bh3, bl0, bl1, bl2, bl3;
                    ldsm4(bh0, bh1, bh2, bh3, bHA + np * (16 * UXST) + ks * 32);
                    ldsm4(bl0, bl1, bl2, bl3, bLA + np * (16 * UXST) + ks * 32);
                    mma16816h(q[2 * np],     aH[ks][0], aH[ks][1], aH[ks][2], aH[ks][3], bh0, bh1);
                    mma16816h(q[2 * np],     aH[ks][0], aH[ks][1], aH[ks][2], aH[ks][3], bl0, bl1);
                    mma16816h(q[2 * np],     aL[ks][0], aL[ks][1], aL[ks][2], aL[ks][3], bh0, bh1);
                    mma16816h(q[2 * np + 1], aH[ks][0], aH[ks][1], aH[ks][2], aH[ks][3], bh2, bh3);
                    mma16816h(q[2 * np + 1], aH[ks][0], aH[ks][1], aH[ks][2], aH[ks][3], bl2, bl3);
                    mma16816h(q[2 * np + 1], aL[ks][0], aL[ks][1], aL[ks][2], aL[ks][3], bh2, bh3);
                }
            }
            float* out = o ? g_P3 : g_P1;
#pragma unroll
            for (int nt = 0; nt < 16; nt++) {
                int col = nt * 8 + cb;
                if (row0 < NN)
                    *(float2*)&out[(size_t)row0 * HID + col] = make_float2(q[nt][0], q[nt][1]);
                if (row1 < NN)
                    *(float2*)&out[(size_t)row1 * HID + col] = make_float2(q[nt][2], q[nt][3]);
            }
        }
    }
}

// ====================== pipelined fp16 MMA-chain edge kernel ================
#define SM_BM    0
#define SM_BE    512
#define SM_IDX   1024
#define SM_WEH   2048
#define SM_EFH0  8192
#define SM_EFH1  11264
#define SM_BW    14336
#define SM_OUT   49152
#define SM_TOTAL 82944
#define TSTRIDE  272
#define EFST     48

__global__ void __launch_bounds__(128, 2)
msg_v10(int layer, const float* __restrict__ We, const float* __restrict__ be,
        const float* __restrict__ bm)
{
    extern __shared__ __align__(16) char smem[];
    const uint32_t sb = smem_u32(smem);
    const int tid = threadIdx.x;
    const int wid = tid >> 5, lane = tid & 31;

    float* sBm = (float*)(smem + SM_BM);
    float* beS = (float*)(smem + SM_BE);
    float* OUT = (float*)(smem + SM_OUT);

    sBm[tid] = bm[tid]; beS[tid] = be[tid];
    {
        int n = tid;
        uint32_t h8[8];
#pragma unroll
        for (int p = 0; p < 8; p++)
            h8[p] = pack2h(We[(2 * p) * 128 + n], We[(2 * p + 1) * 128 + n]);
        *(uint4*)(smem + SM_WEH + n * EFST)      = make_uint4(h8[0], h8[1], h8[2], h8[3]);
        *(uint4*)(smem + SM_WEH + n * EFST + 16) = make_uint4(h8[4], h8[5], h8[6], h8[7]);
    }
    {
        const uint4* wsrc = (const uint4*)g_Wh[layer];
#pragma unroll
        for (int u = 0; u < 16; u++) {
            int g = tid + u * 128;
            int n = g >> 4, q = g & 15;
            *(uint4*)(smem + SM_BW + n * TSTRIDE + q * 16) = wsrc[g];
        }
    }

    const int wm = wid * 16;
    const uint32_t aEfOff = (uint32_t)((wm + (lane & 7) + ((lane >> 3) & 1) * 8) * EFST
                                       + (lane >> 4) * 16);
    const uint32_t bEfOff = (uint32_t)(((lane & 7) + (lane >> 4) * 8) * EFST
                                       + ((lane >> 3) & 1) * 16);
    const uint32_t bMnOff = (uint32_t)(((lane & 7) + (lane >> 4) * 8) * TSTRIDE
                                       + (((lane >> 3) & 1) * 8) * 2);
    const uint32_t wehA = sb + SM_WEH + bEfOff;
    const uint32_t bwA  = sb + SM_BW + bMnOff;

    const int er0 = wm + (lane >> 2);
    const int cb  = (lane & 3) * 2;
    const int NT = NE / 64;

    auto stage_async = [&](int t, int b) {
        const int eBase = t * 64;
        uint32_t efh = sb + (b ? SM_EFH1 : SM_EFH0);
        {
            int r = tid >> 1, u = tid & 1;
            cp16(efh + r * EFST + u * 16, (const char*)(g_efh + (size_t)(eBase + r) * 16) + u * 16);
        }
        if (tid < 16)
            cp16(sb + SM_IDX + b * 512 + tid * 16, (const char*)(g_srcp + eBase) + tid * 16);
        else if (tid < 32)
            cp16(sb + SM_IDX + b * 512 + 256 + (tid - 16) * 16, (const char*)(g_dstp + eBase) + (tid - 16) * 16);
    };

    int t = blockIdx.x;
    int buf = 0;
    if (t < NT) stage_async(t, 0);
    CP_COMMIT();

    for (; t < NT; t += gridDim.x, buf ^= 1) {
        CP_WAIT(0);
        __syncthreads();

        int* sSrc = (int*)(smem + SM_IDX + buf * 512);
        int* sDst = (int*)(smem + SM_IDX + buf * 512 + 256);

        {
#pragma unroll
            for (int i = 0; i < 16; i++) {
                int g = tid + i * 128;
                int r = g >> 5, c = g & 31;
                const char* src = (const char*)(g_P1 + (size_t)sSrc[r] * HID) + c * 16;
                cp16(sb + SM_OUT + r * 528 + c * 16, src);
            }
        }
        CP_COMMIT();

        int tn = t + gridDim.x;
        if (tn < NT) stage_async(tn, buf ^ 1);
        CP_COMMIT();

        const uint32_t efhA = sb + (buf ? SM_EFH1 : SM_EFH0) + aEfOff;
        float acc2[16][4];
#pragma unroll
        for (int n = 0; n < 16; n++)
#pragma unroll
            for (int j = 0; j < 4; j++) acc2[n][j] = 0.f;
        {
            uint32_t eh0, eh1, eh2, eh3;
            ldsm4(eh0, eh1, eh2, eh3, efhA);
#pragma unroll
            for (int g = 0; g < 8; g++) {
                uint32_t wh0, wh1, wh2, wh3;
                ldsm4(wh0, wh1, wh2, wh3, wehA + g * (16 * EFST));
                mma16816h(acc2[2 * g],     eh0, eh1, eh2, eh3, wh0, wh1);
                mma16816h(acc2[2 * g + 1], eh0, eh1, eh2, eh3, wh2, wh3);
            }
        }

        uint32_t aH[8][4];
#pragma unroll
        for (int nt = 0; nt < 16; nt++) {
            int col = nt * 8 + cb;
            float be0 = beS[col], be1 = beS[col + 1];
            float v0 = fmaxf(acc2[nt][0] + be0, 0.f);
            float v1 = fmaxf(acc2[nt][1] + be1, 0.f);
            float v2 = fmaxf(acc2[nt][2] + be0, 0.f);
            float v3 = fmaxf(acc2[nt][3] + be1, 0.f);
            int ks = nt >> 1, j0 = (nt & 1) * 2;
            aH[ks][j0]     = pack2h(v0, v1);
            aH[ks][j0 + 1] = pack2h(v2, v3);
        }

        float acc[16][4];
#pragma unroll
        for (int n = 0; n < 16; n++)
#pragma unroll
            for (int j = 0; j < 4; j++) acc[n][j] = 0.f;
#pragma unroll
        for (int ks = 0; ks < 8; ks++) {
#pragma unroll
            for (int np = 0; np < 8; np++) {
                uint32_t b0, b1, b2, b3;
                ldsm4(b0, b1, b2, b3, bwA + np * (16 * TSTRIDE) + ks * 32);
                mma16816h(acc[2 * np],     aH[ks][0], aH[ks][1], aH[ks][2], aH[ks][3], b0, b1);
                mma16816h(acc[2 * np + 1], aH[ks][0], aH[ks][1], aH[ks][2], aH[ks][3], b2, b3);
            }
        }

        CP_WAIT(1);
        __syncthreads();

        {
            int d0 = sDst[er0], d1 = sDst[er0 + 8];
            const float* p3a = g_P3 + (size_t)d0 * HID;
            const float* p3b = g_P3 + (size_t)d1 * HID;
            const float* p1a = &OUT[er0 * 132];
            const float* p1b = &OUT[(er0 + 8) * 132];
#pragma unroll
            for (int nt = 0; nt < 16; nt++) {
                int col = nt * 8 + cb;
                float2 q1 = *(const float2*)(p1a + col);
                float2 q3 = *(const float2*)(p3a + col);
                float2 o0;
                o0.x = fmaxf(acc[nt][0] + sBm[col]     + q1.x + q3.x, 0.f);
                o0.y = fmaxf(acc[nt][1] + sBm[col + 1] + q1.y + q3.y, 0.f);
                *(float2*)&OUT[er0 * 132 + col] = o0;
                float2 r1 = *(const float2*)(p1b + col);
                float2 r3 = *(const float2*)(p3b + col);
                float2 o1;
                o1.x = fmaxf(acc[nt][2] + sBm[col]     + r1.x + r3.x, 0.f);
                o1.y = fmaxf(acc[nt][3] + sBm[col + 1] + r1.y + r3.y, 0.f);
                *(float2*)&OUT[(er0 + 8) * 132 + col] = o1;
            }
        }
        __syncthreads();

        {
            int col = tid;
            float s = 0.f;
            int cur = sDst[0];
#pragma unroll 4
            for (int r2 = 0; r2 < 64; r2++) {
                int dn = sDst[r2];
                if (dn != cur) {
                    if (s != 0.f) atomicAdd(&g_agg[(size_t)cur * HID + col], s);
                    cur = dn; s = 0.f;
                }
                s += OUT[r2 * 132 + col];
            }
            if (s != 0.f) atomicAdd(&g_agg[(size_t)cur * HID + col], s);
        }
        __syncthreads();
    }
}

// --------------------------------------------- fused demand readout
__global__ void __launch_bounds__(256)
dem_v2(const int* __restrict__ pairs, const float* __restrict__ dfeat,
       const float* __restrict__ Wd, const float* __restrict__ br1,
       const float* __restrict__ w2, const float* __restrict__ b2,
       float* __restrict__ out)
{
    __shared__ __align__(16) float Wds[8][132];
    __shared__ float w2s[128], bs[128];
    int tid = threadIdx.x;
    if (tid < 128) { w2s[tid] = w2[tid]; bs[tid] = br1[tid]; }
    {
        int row = tid >> 5, c = (tid & 31) * 4;
        *(float4*)&Wds[row][c] = ((const float4*)Wd)[tid];
    }
    __syncthreads();

    int w = tid >> 5, lane = tid & 31;
    int d = blockIdx.x * 8 + w;
    int ds = pairs[2 * d], dd = pairs[2 * d + 1];
    int c0 = lane * 4;

    float4 q1 = *(const float4*)(g_P1 + (size_t)ds * HID + c0);
    float4 q2 = *(const float4*)(g_P3 + (size_t)dd * HID + c0);
    float s0 = bs[c0 + 0] + q1.x + q2.x;
    float s1 = bs[c0 + 1] + q1.y + q2.y;
    float s2 = bs[c0 + 2] + q1.z + q2.z;
    float s3 = bs[c0 + 3] + q1.w + q2.w;
#pragma unroll
    for (int q = 0; q < 8; q++) {
        float e = dfeat[(size_t)d * 8 + q];
        float4 wv = *(const float4*)&Wds[q][c0];
        s0 = fmaf(e, wv.x, s0); s1 = fmaf(e, wv.y, s1);
        s2 = fmaf(e, wv.z, s2); s3 = fmaf(e, wv.w, s3);
    }
    float p = fmaxf(s0, 0.f) * w2s[c0 + 0] + fmaxf(s1, 0.f) * w2s[c0 + 1]
            + fmaxf(s2, 0.f) * w2s[c0 + 2] + fmaxf(s3, 0.f) * w2s[c0 + 3];
#pragma unroll
    for (int o = 16; o > 0; o >>= 1) p += __shfl_xor_sync(0xffffffffu, p, o);
    if (lane == 0) out[d] = 1.f / (1.f + expf(-(p + b2[0])));
}

// ---------------------------------------------------------------- launch
extern "C" void kernel_launch(void* const* d_in, const int* in_sizes, int n_in,
                              void* d_out, int out_size)
{
    const float* node_feats = (const float*)d_in[0];
    const float* edge_feats = (const float*)d_in[1];
    const float* dem_feats  = (const float*)d_in[2];
    const int*   eidx       = (const int*)d_in[3];
    const int*   pairs      = (const int*)d_in[4];
    const float* W_node = (const float*)d_in[5];
    const float* b_node = (const float*)d_in[6];
    const float* W_edge = (const float*)d_in[7];
    const float* b_edge = (const float*)d_in[8];
    const float* W_msg0 = (const float*)d_in[9];
    const float* b_msg0 = (const float*)d_in[10];
    const float* W_upd0 = (const float*)d_in[11];
    const float* b_upd0 = (const float*)d_in[12];
    const float* W_msg1 = (const float*)d_in[13];
    const float* b_msg1 = (const float*)d_in[14];
    const float* W_upd1 = (const float*)d_in[15];
    const float* b_upd1 = (const float*)d_in[16];
    const float* W_r1   = (const float*)d_in[17];
    const float* b_r1   = (const float*)d_in[18];
    const float* W_r2   = (const float*)d_in[19];
    const float* b_r2   = (const float*)d_in[20];
    float* out = (float*)d_out;

    const int nTiles = (NN + 127) / 128;

    cudaFuncSetAttribute(msg_v10, cudaFuncAttributeMaxDynamicSharedMemorySize, SM_TOTAL);
    cudaFuncSetAttribute(gemmx2h, cudaFuncAttributeMaxDynamicSharedMemorySize, GX_TOTAL);
    cudaFuncSetAttribute(upd_x,   cudaFuncAttributeMaxDynamicSharedMemorySize, UX_TOTAL);

    // ---- edge sort by dst + ef fp16 pre-permute
    zcnt<<<(NN + 256) / 256, 256>>>();
    hist<<<NE / 256, 256>>>(eidx);
    scan20k<<<1, 1024>>>();
    scatter<<<NE / 256, 256>>>(eidx, edge_feats);

    node_embed<<<NN / 16, 128>>>(node_feats, W_node, b_node);
    prep_all<<<12, 256>>>(W_msg0, W_msg1, W_upd0, W_upd1, W_r1);

    // ---- layer 0
    gemmx2h<<<nTiles, 256, GX_TOTAL>>>(0, 0, 1);
    msg_v10<<<304, 128, SM_TOTAL>>>(0, W_edge, b_edge, b_msg0);
    upd_x<<<nTiles, 256, UX_TOTAL>>>(0, b_upd0);

    // ---- layer 1
    gemmx2h<<<nTiles, 256, GX_TOTAL>>>(1, 1, 1);
    msg_v10<<<304, 128, SM_TOTAL>>>(1, W_edge, b_edge, b_msg1);
    upd_x<<<nTiles, 256, UX_TOTAL>>>(1, b_upd1);   // also emits Q1/Q3 -> g_P1/g_P3

    // ---- readout
    dem_v2<<<ND / 8, 256>>>(pairs, dem_feats, W_r1 + 256 * HID, b_r1, W_r2, b_r2, out);
}

// round 12
// speedup vs baseline: 1.0325x; 1.0325x over previous
#include <cuda_runtime.h>
#include <cuda_fp16.h>
#include <math.h>
#include <stdint.h>

#define HID 128
#define NN 20000
#define NE 640000
#define NEP 640032            // padded to multiple of 96
#define ND 100000

// scratch (device globals: allocation-free contract)
__device__ float g_hn0[(size_t)NN * HID];
__device__ float g_hn1[(size_t)NN * HID];
__device__ float g_agg[(size_t)(NN + 1) * HID];   // +1 sentinel row
__device__ float g_P1 [(size_t)NN * HID];
__device__ float g_P3 [(size_t)(NN + 1) * HID];   // +1 sentinel row (stays 0)
// fp16 weight images, [n][k] row-major
__device__ __align__(16) __half g_Wh [2][128 * 128];
__device__ __align__(16) __half g_Wp1[2][128 * 128];
__device__ __align__(16) __half g_Wp3[2][128 * 128];
__device__ __align__(16) __half g_Wuh[2][2][128 * 128];
__device__ __align__(16) __half g_Wul[2][2][128 * 128];
__device__ __align__(16) __half g_Wq1h[128 * 128];
__device__ __align__(16) __half g_Wq1l[128 * 128];
__device__ __align__(16) __half g_Wq3h[128 * 128];
__device__ __align__(16) __half g_Wq3l[128 * 128];
// edge sort-by-dst (+ pre-permuted fp16 edge features), padded
__device__ int g_cnt[NN + 1];
__device__ int g_srcp[NEP];
__device__ int g_dstp[NEP];
__device__ __align__(16) __half g_efh[(size_t)NEP * 16];

// ======================= helpers =======================
__device__ __forceinline__ uint32_t smem_u32(const void* p) {
    uint32_t a;
    asm("{ .reg .u64 t; cvta.to.shared.u64 t, %1; cvt.u32.u64 %0, t; }" : "=r"(a) : "l"(p));
    return a;
}
__device__ __forceinline__ void ldsm4(uint32_t& r0, uint32_t& r1, uint32_t& r2, uint32_t& r3,
                                      uint32_t addr) {
    asm volatile("ldmatrix.sync.aligned.m8n8.x4.shared.b16 {%0,%1,%2,%3}, [%4];"
                 : "=r"(r0), "=r"(r1), "=r"(r2), "=r"(r3) : "r"(addr));
}
__device__ __forceinline__ void mma16816h(float* c, uint32_t a0, uint32_t a1, uint32_t a2,
                                          uint32_t a3, uint32_t b0, uint32_t b1) {
    asm volatile("mma.sync.aligned.m16n8k16.row.col.f32.f16.f16.f32 "
                 "{%0,%1,%2,%3}, {%4,%5,%6,%7}, {%8,%9}, {%0,%1,%2,%3};"
                 : "+f"(c[0]), "+f"(c[1]), "+f"(c[2]), "+f"(c[3])
                 : "r"(a0), "r"(a1), "r"(a2), "r"(a3), "r"(b0), "r"(b1));
}
__device__ __forceinline__ uint32_t pack2h(float v0, float v1) {
    __half h0 = __float2half_rn(v0);
    __half h1 = __float2half_rn(v1);
    return (uint32_t)__half_as_ushort(h0) | ((uint32_t)__half_as_ushort(h1) << 16);
}
__device__ __forceinline__ void split2h(float v0, float v1, uint32_t& hi, uint32_t& lo) {
    __half h0 = __float2half_rn(v0);
    __half h1 = __float2half_rn(v1);
    __half m0 = __float2half_rn(v0 - __half2float(h0));
    __half m1 = __float2half_rn(v1 - __half2float(h1));
    hi = (uint32_t)__half_as_ushort(h0) | ((uint32_t)__half_as_ushort(h1) << 16);
    lo = (uint32_t)__half_as_ushort(m0) | ((uint32_t)__half_as_ushort(m1) << 16);
}
__device__ __forceinline__ void cp16(uint32_t smem_dst, const void* gsrc) {
    asm volatile("cp.async.cg.shared.global [%0], [%1], 16;"
                 :: "r"(smem_dst), "l"(gsrc) : "memory");
}
#define CP_COMMIT()  asm volatile("cp.async.commit_group;" ::: "memory")
#define CP_WAIT(N)   asm volatile("cp.async.wait_group %0;" :: "n"(N) : "memory")

// ---------------------------------------------------------------- sort by dst
__global__ void zcnt()
{
    int i = blockIdx.x * 256 + threadIdx.x;
    if (i <= NN) g_cnt[i] = 0;
}
__global__ void hist(const int* __restrict__ eidx)
{
    int e = blockIdx.x * 256 + threadIdx.x;
    atomicAdd(&g_cnt[eidx[NE + e]], 1);
}
__global__ void scan20k()
{
    __shared__ int part[1024];
    __shared__ int wsum[32];
    const int tid = threadIdx.x;
    const int CH = 20;
    int base = tid * CH;
    int loc[CH];
    int s = 0;
#pragma unroll
    for (int i = 0; i < CH; i++) {
        int v = (base + i <= NN) ? g_cnt[base + i] : 0;
        loc[i] = s; s += v;
    }
    part[tid] = s;
    __syncthreads();
    int lane = tid & 31, w = tid >> 5;
    int v = part[tid];
#pragma unroll
    for (int o = 1; o < 32; o <<= 1) { int t = __shfl_up_sync(~0u, v, o); if (lane >= o) v += t; }
    if (lane == 31) wsum[w] = v;
    __syncthreads();
    if (w == 0) {
        int x = wsum[lane];
#pragma unroll
        for (int o = 1; o < 32; o <<= 1) { int t = __shfl_up_sync(~0u, x, o); if (lane >= o) x += t; }
        wsum[lane] = x;
    }
    __syncthreads();
    int excl = v - part[tid] + (w ? wsum[w - 1] : 0);
#pragma unroll
    for (int i = 0; i < CH; i++)
        if (base + i <= NN) g_cnt[base + i] = excl + loc[i];
}
__global__ void scatter(const int* __restrict__ eidx, const float* __restrict__ ef)
{
    int e = blockIdx.x * 256 + threadIdx.x;
    int s = eidx[e], d = eidx[NE + e];
    int p = atomicAdd(&g_cnt[d], 1);
    g_srcp[p] = s; g_dstp[p] = d;
    const float4* eg = (const float4*)(ef + (size_t)e * 16);
    float4 v0 = eg[0], v1 = eg[1], v2 = eg[2], v3 = eg[3];
    uint4* dh = (uint4*)(g_efh + (size_t)p * 16);
    dh[0] = make_uint4(pack2h(v0.x, v0.y), pack2h(v0.z, v0.w),
                       pack2h(v1.x, v1.y), pack2h(v1.z, v1.w));
    dh[1] = make_uint4(pack2h(v2.x, v2.y), pack2h(v2.z, v2.w),
                       pack2h(v3.x, v3.y), pack2h(v3.z, v3.w));
}
// pad entries (deterministic every launch): ef=0, src=0, dst=sentinel NN
__global__ void pad_init()
{
    int i = threadIdx.x;   // 32
    g_srcp[NE + i] = 0;
    g_dstp[NE + i] = NN;
    uint4 z = make_uint4(0, 0, 0, 0);
    uint4* dh = (uint4*)(g_efh + (size_t)(NE + i) * 16);
    dh[0] = z; dh[1] = z;
}

// ---------------------------------------------------------------- node embed
__global__ void node_embed(const float* __restrict__ x, const float* __restrict__ W,
                           const float* __restrict__ b)
{
    __shared__ float Ws[32 * HID];
    __shared__ float xs[16][33];
    int tid = threadIdx.x; // 128
    for (int i = tid; i < 32 * HID; i += 128) Ws[i] = W[i];
    int row0 = blockIdx.x * 16;
    for (int i = tid; i < 16 * 32; i += 128) xs[i >> 5][i & 31] = x[(size_t)row0 * 32 + i];
    float bb = b[tid];
    __syncthreads();
#pragma unroll 4
    for (int r = 0; r < 16; r++) {
        float acc = bb;
#pragma unroll
        for (int k = 0; k < 32; k++) acc = fmaf(xs[r][k], Ws[k * HID + tid], acc);
        g_hn0[(size_t)(row0 + r) * HID + tid] = fmaxf(acc, 0.f);
    }
}

// ------------------------------ weight prep: fp16 [n][k] images
__global__ void prep_all(const float* __restrict__ Wm0, const float* __restrict__ Wm1,
                         const float* __restrict__ Wu0, const float* __restrict__ Wu1,
                         const float* __restrict__ Wr1)
{
    int b = blockIdx.x;
    if (b < 6) {
        const float* src; __half* dst;
        switch (b) {
            case 0: src = Wm0 + 128 * 128; dst = g_Wh[0];  break;
            case 1: src = Wm1 + 128 * 128; dst = g_Wh[1];  break;
            case 2: src = Wm0;             dst = g_Wp1[0]; break;
            case 3: src = Wm1;             dst = g_Wp1[1]; break;
            case 4: src = Wm0 + 256 * 128; dst = g_Wp3[0]; break;
            default: src = Wm1 + 256 * 128; dst = g_Wp3[1]; break;
        }
        for (int idx = threadIdx.x; idx < 128 * 128; idx += 256) {
            int n = idx >> 7, k = idx & 127;
            dst[idx] = __float2half_rn(src[k * 128 + n]);
        }
    } else if (b < 10) {
        int l = (b - 6) >> 1, p = (b - 6) & 1;
        const float* src = (l ? Wu1 : Wu0) + p * 128 * 128;
        __half* dh = g_Wuh[l][p];
        __half* dl = g_Wul[l][p];
        for (int idx = threadIdx.x; idx < 128 * 128; idx += 256) {
            int n = idx >> 7, k = idx & 127;
            float w = src[k * 128 + n];
            __half h = __float2half_rn(w);
            dh[idx] = h;
            dl[idx] = __float2half_rn(w - __half2float(h));
        }
    } else {
        const float* src = (b == 10) ? Wr1 : (Wr1 + 128 * 128);
        __half* dh = (b == 10) ? g_Wq1h : g_Wq3h;
        __half* dl = (b == 10) ? g_Wq1l : g_Wq3l;
        for (int idx = threadIdx.x; idx < 128 * 128; idx += 256) {
            int n = idx >> 7, k = idx & 127;
            float w = src[k * 128 + n];
            __half h = __float2half_rn(w);
            dh[idx] = h;
            dl[idx] = __float2half_rn(w - __half2float(h));
        }
    }
}

// ---------------- fp16 node-level dual GEMM: P1 = A@W1, P3 = A@W3 (+agg zero)
#define GX_A 0
#define GX_W 34816
#define GX_TOTAL 104448
#define GXST 272

__global__ void __launch_bounds__(256)
gemmx2h(int asel, int img, int zflag)
{
    extern __shared__ __align__(16) char smem[];
    const uint32_t sb = smem_u32(smem);
    const float* __restrict__ A = asel ? g_hn1 : g_hn0;
    const int tid = threadIdx.x;
    const int wid = tid >> 5, lane = tid & 31;
    const int nBase = blockIdx.x * 128;

    {
        int r = tid >> 1, u = tid & 1;
        int nrow = min(nBase + r, NN - 1);
        const float4* src = (const float4*)(A + (size_t)nrow * HID) + u * 16;
        uint32_t dst = (uint32_t)(GX_A + r * GXST + u * 128);
#pragma unroll
        for (int q = 0; q < 8; q++) {
            float4 a = src[2 * q], bv = src[2 * q + 1];
            *(uint4*)(smem + dst + q * 16) =
                make_uint4(pack2h(a.x, a.y), pack2h(a.z, a.w),
                           pack2h(bv.x, bv.y), pack2h(bv.z, bv.w));
        }
    }
    {
        const uint4* w1 = (const uint4*)g_Wp1[img];
        const uint4* w3 = (const uint4*)g_Wp3[img];
#pragma unroll
        for (int i = 0; i < 8; i++) {
            int g = tid + i * 256;
            int n = g >> 4, q = g & 15;
            *(uint4*)(smem + GX_W + n * GXST + q * 16) = w1[g];
            *(uint4*)(smem + GX_W + (n + 128) * GXST + q * 16) = w3[g];
        }
    }
    if (zflag) {
#pragma unroll
        for (int i = 0; i < 16; i++) {
            int g = tid + i * 256;
            int r = g >> 5, c = (g & 31) * 4;
            int row = nBase + r;
            if (row < NN)
                *(float4*)&g_agg[(size_t)row * HID + c] = make_float4(0.f, 0.f, 0.f, 0.f);
        }
    }
    __syncthreads();

    const int wm = wid * 16;
    const uint32_t aA = sb + GX_A + (uint32_t)((wm + (lane & 7) + ((lane >> 3) & 1) * 8) * GXST
                                               + (lane >> 4) * 16);
    const uint32_t bOff = (uint32_t)(((lane & 7) + (lane >> 4) * 8) * GXST
                                     + (((lane >> 3) & 1) * 8) * 2);
    const int er0 = wm + (lane >> 2);
    const int cb  = (lane & 3) * 2;
    const int row0 = nBase + er0, row1 = row0 + 8;

    uint32_t aH[8][4];
#pragma unroll
    for (int ks = 0; ks < 8; ks++)
        ldsm4(aH[ks][0], aH[ks][1], aH[ks][2], aH[ks][3], aA + ks * 32);

#pragma unroll
    for (int half = 0; half < 2; half++) {
        const uint32_t bA = sb + GX_W + half * (128 * GXST) + bOff;
        float acc[16][4];
#pragma unroll
        for (int n = 0; n < 16; n++)
#pragma unroll
            for (int j = 0; j < 4; j++) acc[n][j] = 0.f;
#pragma unroll
        for (int ks = 0; ks < 8; ks++) {
#pragma unroll
            for (int np = 0; np < 8; np++) {
                uint32_t b0, b1, b2, b3;
                ldsm4(b0, b1, b2, b3, bA + np * (16 * GXST) + ks * 32);
                mma16816h(acc[2 * np],     aH[ks][0], aH[ks][1], aH[ks][2], aH[ks][3], b0, b1);
                mma16816h(acc[2 * np + 1], aH[ks][0], aH[ks][1], aH[ks][2], aH[ks][3], b2, b3);
            }
        }
        float* out = half ? g_P3 : g_P1;
#pragma unroll
        for (int nt = 0; nt < 16; nt++) {
            int col = nt * 8 + cb;
            if (row0 < NN)
                *(float2*)&out[(size_t)row0 * HID + col] = make_float2(acc[nt][0], acc[nt][1]);
            if (row1 < NN)
                *(float2*)&out[(size_t)row1 * HID + col] = make_float2(acc[nt][2], acc[nt][3]);
        }
    }
}

// ---------------- exact (3-product) update GEMM, split-K; layer1 chains Q GEMMs
#define UX_AH 0
#define UX_AL 34816
#define UX_WH 69632
#define UX_WL 104448
#define UX_B  139264
#define UX_TOTAL 139776
#define UXST 272

__global__ void __launch_bounds__(256)
upd_x(int layer, const float* __restrict__ bias)
{
    extern __shared__ __align__(16) char smem[];
    const uint32_t sb = smem_u32(smem);
    const float* __restrict__ hn   = layer ? g_hn1 : g_hn0;
    float*       __restrict__ hout = layer ? g_hn0 : g_hn1;
    const int tid = threadIdx.x;
    const int wid = tid >> 5, lane = tid & 31;
    const int nBase = blockIdx.x * 128;
    float* sB = (float*)(smem + UX_B);
    if (tid < 128) sB[tid] = bias[tid];

    const int wm = wid * 16;
    const uint32_t aOff = (uint32_t)((wm + (lane & 7) + ((lane >> 3) & 1) * 8) * UXST
                                     + (lane >> 4) * 16);
    const uint32_t bOff = (uint32_t)(((lane & 7) + (lane >> 4) * 8) * UXST
                                     + (((lane >> 3) & 1) * 8) * 2);
    const int er0 = wm + (lane >> 2);
    const int cb  = (lane & 3) * 2;
    const int row0 = nBase + er0, row1 = row0 + 8;

    float acc[16][4];
#pragma unroll
    for (int n = 0; n < 16; n++)
#pragma unroll
        for (int j = 0; j < 4; j++) acc[n][j] = 0.f;

    for (int p = 0; p < 2; p++) {
        {
            int r = tid >> 1, u = tid & 1;
            int nrow = min(nBase + r, NN - 1);
            const float4* src = (const float4*)((p ? g_agg : hn) + (size_t)nrow * HID) + u * 16;
            uint32_t da = (uint32_t)(UX_AH + r * UXST + u * 128);
            uint32_t dl = (uint32_t)(UX_AL + r * UXST + u * 128);
#pragma unroll
            for (int q = 0; q < 8; q++) {
                float4 a = src[2 * q], bv = src[2 * q + 1];
                uint32_t h0, l0, h1, l1, h2, l2, h3, l3;
                split2h(a.x, a.y, h0, l0);  split2h(a.z, a.w, h1, l1);
                split2h(bv.x, bv.y, h2, l2); split2h(bv.z, bv.w, h3, l3);
                *(uint4*)(smem + da + q * 16) = make_uint4(h0, h1, h2, h3);
                *(uint4*)(smem + dl + q * 16) = make_uint4(l0, l1, l2, l3);
            }
        }
        {
            const uint4* wh = (const uint4*)g_Wuh[layer][p];
            const uint4* wl = (const uint4*)g_Wul[layer][p];
#pragma unroll
            for (int i = 0; i < 8; i++) {
                int g = tid + i * 256;
                int n = g >> 4, q = g & 15;
                *(uint4*)(smem + UX_WH + n * UXST + q * 16) = wh[g];
                *(uint4*)(smem + UX_WL + n * UXST + q * 16) = wl[g];
            }
        }
        __syncthreads();

#pragma unroll
        for (int ks = 0; ks < 8; ks++) {
            uint32_t ah0, ah1, ah2, ah3, al0, al1, al2, al3;
            ldsm4(ah0, ah1, ah2, ah3, sb + UX_AH + aOff + ks * 32);
            ldsm4(al0, al1, al2, al3, sb + UX_AL + aOff + ks * 32);
#pragma unroll
            for (int np = 0; np < 8; np++) {
                uint32_t bh0, bh1, bh2, bh3, bl0, bl1, bl2, bl3;
                ldsm4(bh0, bh1, bh2, bh3, sb + UX_WH + bOff + np * (16 * UXST) + ks * 32);
                ldsm4(bl0, bl1, bl2, bl3, sb + UX_WL + bOff + np * (16 * UXST) + ks * 32);
                mma16816h(acc[2 * np],     ah0, ah1, ah2, ah3, bh0, bh1);
                mma16816h(acc[2 * np],     ah0, ah1, ah2, ah3, bl0, bl1);
                mma16816h(acc[2 * np],     al0, al1, al2, al3, bh0, bh1);
                mma16816h(acc[2 * np + 1], ah0, ah1, ah2, ah3, bh2, bh3);
                mma16816h(acc[2 * np + 1], ah0, ah1, ah2, ah3, bl2, bl3);
                mma16816h(acc[2 * np + 1], al0, al1, al2, al3, bh2, bh3);
            }
        }
        __syncthreads();
    }

#pragma unroll
    for (int nt = 0; nt < 16; nt++) {
        int col = nt * 8 + cb;
        float b0 = sB[col], b1 = sB[col + 1];
        acc[nt][0] = fmaxf(acc[nt][0] + b0, 0.f);
        acc[nt][1] = fmaxf(acc[nt][1] + b1, 0.f);
        acc[nt][2] = fmaxf(acc[nt][2] + b0, 0.f);
        acc[nt][3] = fmaxf(acc[nt][3] + b1, 0.f);
        if (row0 < NN)
            *(float2*)&hout[(size_t)row0 * HID + col] = make_float2(acc[nt][0], acc[nt][1]);
        if (row1 < NN)
            *(float2*)&hout[(size_t)row1 * HID + col] = make_float2(acc[nt][2], acc[nt][3]);
    }

    if (layer == 1) {
        uint32_t aH[8][4], aL[8][4];
#pragma unroll
        for (int nt = 0; nt < 16; nt++) {
            int ks = nt >> 1, j0 = (nt & 1) * 2;
            split2h(acc[nt][0], acc[nt][1], aH[ks][j0],     aL[ks][j0]);
            split2h(acc[nt][2], acc[nt][3], aH[ks][j0 + 1], aL[ks][j0 + 1]);
        }
        {
            const uint4* q1h = (const uint4*)g_Wq1h;
            const uint4* q1l = (const uint4*)g_Wq1l;
            const uint4* q3h = (const uint4*)g_Wq3h;
            const uint4* q3l = (const uint4*)g_Wq3l;
#pragma unroll
            for (int i = 0; i < 8; i++) {
                int g = tid + i * 256;
                int n = g >> 4, q = g & 15;
                *(uint4*)(smem + UX_AH + n * UXST + q * 16) = q1h[g];
                *(uint4*)(smem + UX_AL + n * UXST + q * 16) = q1l[g];
                *(uint4*)(smem + UX_WH + n * UXST + q * 16) = q3h[g];
                *(uint4*)(smem + UX_WL + n * UXST + q * 16) = q3l[g];
            }
        }
        __syncthreads();

#pragma unroll
        for (int o = 0; o < 2; o++) {
            const uint32_t bHA = sb + (o ? UX_WH : UX_AH) + bOff;
            const uint32_t bLA = sb + (o ? UX_WL : UX_AL) + bOff;
            float q[16][4];
#pragma unroll
            for (int n = 0; n < 16; n++)
#pragma unroll
                for (int j = 0; j < 4; j++) q[n][j] = 0.f;
#pragma unroll
            for (int ks = 0; ks < 8; ks++) {
#pragma unroll
                for (int np = 0; np < 8; np++) {
                    uint32_t bh0, bh1, bh2, bh3, bl0, bl1, bl2, bl3;
                    ldsm4(bh0, bh1, bh2, bh3, bHA + np * (16 * UXST) + ks * 32);
                    ldsm4(bl0, bl1, bl2, bl3, bLA + np * (16 * UXST) + ks * 32);
                    mma16816h(q[2 * np],     aH[ks][0], aH[ks][1], aH[ks][2], aH[ks][3], bh0, bh1);
                    mma16816h(q[2 * np],     aH[ks][0], aH[ks][1], aH[ks][2], aH[ks][3], bl0, bl1);
                    mma16816h(q[2 * np],     aL[ks][0], aL[ks][1], aL[ks][2], aL[ks][3], bh0, bh1);
                    mma16816h(q[2 * np + 1], aH[ks][0], aH[ks][1], aH[ks][2], aH[ks][3], bh2, bh3);
                    mma16816h(q[2 * np + 1], aH[ks][0], aH[ks][1], aH[ks][2], aH[ks][3], bl2, bl3);
                    mma16816h(q[2 * np + 1], aL[ks][0], aL[ks][1], aL[ks][2], aL[ks][3], bh2, bh3);
                }
            }
            float* out = o ? g_P3 : g_P1;
#pragma unroll
            for (int nt = 0; nt < 16; nt++) {
                int col = nt * 8 + cb;
                if (row0 < NN)
                    *(float2*)&out[(size_t)row0 * HID + col] = make_float2(q[nt][0], q[nt][1]);
                if (row1 < NN)
                    *(float2*)&out[(size_t)row1 * HID + col] = make_float2(q[nt][2], q[nt][3]);
            }
        }
    }
}

// ====================== pipelined fp16 MMA-chain edge kernel (M=96) =========
// 192 threads (6 warps), 2 CTAs/SM -> 3 warps/SMSP
#define SM_BM    0
#define SM_BE    512
#define SM_IDX   1024           // 2 bufs x (src 384 + dst 384)
#define SM_WEH   2560           // fp16 [128][24] (48B stride)
#define SM_EFH0  8704           // fp16 [96][24] x2 bufs (4608 each)
#define SM_EFH1  13312
#define SM_BW    17920          // fp16 [128][136] W_mid image (34816)
#define SM_OUT   52736          // fp32 [96][132] (50688) — doubles as P1 buffer
#define SM_TOTAL 103424
#define TSTRIDE  272
#define EFST     48

__global__ void __launch_bounds__(192, 2)
msg_v11(int layer, const float* __restrict__ We, const float* __restrict__ be,
        const float* __restrict__ bm)
{
    extern __shared__ __align__(16) char smem[];
    const uint32_t sb = smem_u32(smem);
    const int tid = threadIdx.x;
    const int wid = tid >> 5, lane = tid & 31;

    float* sBm = (float*)(smem + SM_BM);
    float* beS = (float*)(smem + SM_BE);
    float* OUT = (float*)(smem + SM_OUT);

    // ---- one-time setup
    if (tid < 128) {
        sBm[tid] = bm[tid]; beS[tid] = be[tid];
        int n = tid;
        uint32_t h8[8];
#pragma unroll
        for (int p = 0; p < 8; p++)
            h8[p] = pack2h(We[(2 * p) * 128 + n], We[(2 * p + 1) * 128 + n]);
        *(uint4*)(smem + SM_WEH + n * EFST)      = make_uint4(h8[0], h8[1], h8[2], h8[3]);
        *(uint4*)(smem + SM_WEH + n * EFST + 16) = make_uint4(h8[4], h8[5], h8[6], h8[7]);
    }
    {   // stage W_mid fp16 image [n][136]: 2048 uint4 chunks
        const uint4* wsrc = (const uint4*)g_Wh[layer];
#pragma unroll
        for (int u = 0; u < 11; u++) {
            int g = tid + u * 192;
            if (g < 2048) {
                int n = g >> 4, q = g & 15;
                *(uint4*)(smem + SM_BW + n * TSTRIDE + q * 16) = wsrc[g];
            }
        }
    }

    const int wm = wid * 16;                 // 0..80
    const uint32_t aEfOff = (uint32_t)((wm + (lane & 7) + ((lane >> 3) & 1) * 8) * EFST
                                       + (lane >> 4) * 16);
    const uint32_t bEfOff = (uint32_t)(((lane & 7) + (lane >> 4) * 8) * EFST
                                       + ((lane >> 3) & 1) * 16);
    const uint32_t bMnOff = (uint32_t)(((lane & 7) + (lane >> 4) * 8) * TSTRIDE
                                       + (((lane >> 3) & 1) * 8) * 2);
    const uint32_t wehA = sb + SM_WEH + bEfOff;
    const uint32_t bwA  = sb + SM_BW + bMnOff;

    const int er0 = wm + (lane >> 2);        // rows er0, er0+8 (0..95)
    const int cb  = (lane & 3) * 2;
    const int NT = NEP / 96;                 // 6667

    auto stage_async = [&](int t, int b) {
        const int eBase = t * 96;
        uint32_t efh = sb + (b ? SM_EFH1 : SM_EFH0);
        {
            int r = tid >> 1, u = tid & 1;   // rows 0..95
            cp16(efh + r * EFST + u * 16, (const char*)(g_efh + (size_t)(eBase + r) * 16) + u * 16);
        }
        if (tid < 24)
            cp16(sb + SM_IDX + b * 768 + tid * 16, (const char*)(g_srcp + eBase) + tid * 16);
        else if (tid < 48)
            cp16(sb + SM_IDX + b * 768 + 384 + (tid - 24) * 16, (const char*)(g_dstp + eBase) + (tid - 24) * 16);
    };

    int t = blockIdx.x;
    int buf = 0;
    if (t < NT) stage_async(t, 0);
    CP_COMMIT();

    for (; t < NT; t += gridDim.x, buf ^= 1) {
        CP_WAIT(0);
        __syncthreads();

        int* sSrc = (int*)(smem + SM_IDX + buf * 768);
        int* sDst = (int*)(smem + SM_IDX + buf * 768 + 384);

        // ---- P1 gather prefetch into OUT (96 rows x 32 chunks = 3072)
        {
#pragma unroll
            for (int i = 0; i < 16; i++) {
                int g = tid + i * 192;
                int r = g >> 5, c = g & 31;
                const char* src = (const char*)(g_P1 + (size_t)sSrc[r] * HID) + c * 16;
                cp16(sb + SM_OUT + r * 528 + c * 16, src);
            }
        }
        CP_COMMIT();

        int tn = t + gridDim.x;
        if (tn < NT) stage_async(tn, buf ^ 1);
        CP_COMMIT();

        // ---- he GEMM (K=16, single fp16 product)
        const uint32_t efhA = sb + (buf ? SM_EFH1 : SM_EFH0) + aEfOff;
        float acc2[16][4];
#pragma unroll
        for (int n = 0; n < 16; n++)
#pragma unroll
            for (int j = 0; j < 4; j++) acc2[n][j] = 0.f;
        {
            uint32_t eh0, eh1, eh2, eh3;
            ldsm4(eh0, eh1, eh2, eh3, efhA);
#pragma unroll
            for (int g = 0; g < 8; g++) {
                uint32_t wh0, wh1, wh2, wh3;
                ldsm4(wh0, wh1, wh2, wh3, wehA + g * (16 * EFST));
                mma16816h(acc2[2 * g],     eh0, eh1, eh2, eh3, wh0, wh1);
                mma16816h(acc2[2 * g + 1], eh0, eh1, eh2, eh3, wh2, wh3);
            }
        }

        // ---- bias + relu + fp16 round -> main-GEMM A fragments
        uint32_t aH[8][4];
#pragma unroll
        for (int nt = 0; nt < 16; nt++) {
            int col = nt * 8 + cb;
            float be0 = beS[col], be1 = beS[col + 1];
            float v0 = fmaxf(acc2[nt][0] + be0, 0.f);
            float v1 = fmaxf(acc2[nt][1] + be1, 0.f);
            float v2 = fmaxf(acc2[nt][2] + be0, 0.f);
            float v3 = fmaxf(acc2[nt][3] + be1, 0.f);
            int ks = nt >> 1, j0 = (nt & 1) * 2;
            aH[ks][j0]     = pack2h(v0, v1);
            aH[ks][j0 + 1] = pack2h(v2, v3);
        }

        // ---- main GEMM: D = Ah*W
        float acc[16][4];
#pragma unroll
        for (int n = 0; n < 16; n++)
#pragma unroll
            for (int j = 0; j < 4; j++) acc[n][j] = 0.f;
#pragma unroll
        for (int ks = 0; ks < 8; ks++) {
#pragma unroll
            for (int np = 0; np < 8; np++) {
                uint32_t b0, b1, b2, b3;
                ldsm4(b0, b1, b2, b3, bwA + np * (16 * TSTRIDE) + ks * 32);
                mma16816h(acc[2 * np],     aH[ks][0], aH[ks][1], aH[ks][2], aH[ks][3], b0, b1);
                mma16816h(acc[2 * np + 1], aH[ks][0], aH[ks][1], aH[ks][2], aH[ks][3], b2, b3);
            }
        }

        CP_WAIT(1);
        __syncthreads();

        // ---- epilogue: P1 from smem, P3 from global (L1-hot), write OUT
        {
            int d0 = sDst[er0], d1 = sDst[er0 + 8];
            const float* p3a = g_P3 + (size_t)d0 * HID;
            const float* p3b = g_P3 + (size_t)d1 * HID;
            const float* p1a = &OUT[er0 * 132];
            const float* p1b = &OUT[(er0 + 8) * 132];
#pragma unroll
            for (int nt = 0; nt < 16; nt++) {
                int col = nt * 8 + cb;
                float2 q1 = *(const float2*)(p1a + col);
                float2 q3 = *(const float2*)(p3a + col);
                float2 o0;
                o0.x = fmaxf(acc[nt][0] + sBm[col]     + q1.x + q3.x, 0.f);
                o0.y = fmaxf(acc[nt][1] + sBm[col + 1] + q1.y + q3.y, 0.f);
                *(float2*)&OUT[er0 * 132 + col] = o0;
                float2 r1 = *(const float2*)(p1b + col);
                float2 r3 = *(const float2*)(p3b + col);
                float2 o1;
                o1.x = fmaxf(acc[nt][2] + sBm[col]     + r1.x + r3.x, 0.f);
                o1.y = fmaxf(acc[nt][3] + sBm[col + 1] + r1.y + r3.y, 0.f);
                *(float2*)&OUT[(er0 + 8) * 132 + col] = o1;
            }
        }
        __syncthreads();

        // ---- segmented reduction (dst-sorted): threads 0..127, 96 rows
        if (tid < 128) {
            int col = tid;
            float s = 0.f;
            int cur = sDst[0];
#pragma unroll 4
            for (int r2 = 0; r2 < 96; r2++) {
                int dn = sDst[r2];
                if (dn != cur) {
                    if (s != 0.f) atomicAdd(&g_agg[(size_t)cur * HID + col], s);
                    cur = dn; s = 0.f;
                }
                s += OUT[r2 * 132 + col];
            }
            if (s != 0.f) atomicAdd(&g_agg[(size_t)cur * HID + col], s);
        }
        __syncthreads();
    }
}

// --------------------------------------------- fused demand readout
__global__ void __launch_bounds__(256)
dem_v2(const int* __restrict__ pairs, const float* __restrict__ dfeat,
       const float* __restrict__ Wd, const float* __restrict__ br1,
       const float* __restrict__ w2, const float* __restrict__ b2,
       float* __restrict__ out)
{
    __shared__ __align__(16) float Wds[8][132];
    __shared__ float w2s[128], bs[128];
    int tid = threadIdx.x;
    if (tid < 128) { w2s[tid] = w2[tid]; bs[tid] = br1[tid]; }
    {
        int row = tid >> 5, c = (tid & 31) * 4;
        *(float4*)&Wds[row][c] = ((const float4*)Wd)[tid];
    }
    __syncthreads();

    int w = tid >> 5, lane = tid & 31;
    int d = blockIdx.x * 8 + w;
    int ds = pairs[2 * d], dd = pairs[2 * d + 1];
    int c0 = lane * 4;

    float4 q1 = *(const float4*)(g_P1 + (size_t)ds * HID + c0);
    float4 q2 = *(const float4*)(g_P3 + (size_t)dd * HID + c0);
    float s0 = bs[c0 + 0] + q1.x + q2.x;
    float s1 = bs[c0 + 1] + q1.y + q2.y;
    float s2 = bs[c0 + 2] + q1.z + q2.z;
    float s3 = bs[c0 + 3] + q1.w + q2.w;
#pragma unroll
    for (int q = 0; q < 8; q++) {
        float e = dfeat[(size_t)d * 8 + q];
        float4 wv = *(const float4*)&Wds[q][c0];
        s0 = fmaf(e, wv.x, s0); s1 = fmaf(e, wv.y, s1);
        s2 = fmaf(e, wv.z, s2); s3 = fmaf(e, wv.w, s3);
    }
    float p = fmaxf(s0, 0.f) * w2s[c0 + 0] + fmaxf(s1, 0.f) * w2s[c0 + 1]
            + fmaxf(s2, 0.f) * w2s[c0 + 2] + fmaxf(s3, 0.f) * w2s[c0 + 3];
#pragma unroll
    for (int o = 16; o > 0; o >>= 1) p += __shfl_xor_sync(0xffffffffu, p, o);
    if (lane == 0) out[d] = 1.f / (1.f + expf(-(p + b2[0])));
}

// ---------------------------------------------------------------- launch
extern "C" void kernel_launch(void* const* d_in, const int* in_sizes, int n_in,
                              void* d_out, int out_size)
{
    const float* node_feats = (const float*)d_in[0];
    const float* edge_feats = (const float*)d_in[1];
    const float* dem_feats  = (const float*)d_in[2];
    const int*   eidx       = (const int*)d_in[3];
    const int*   pairs      = (const int*)d_in[4];
    const float* W_node = (const float*)d_in[5];
    const float* b_node = (const float*)d_in[6];
    const float* W_edge = (const float*)d_in[7];
    const float* b_edge = (const float*)d_in[8];
    const float* W_msg0 = (const float*)d_in[9];
    const float* b_msg0 = (const float*)d_in[10];
    const float* W_upd0 = (const float*)d_in[11];
    const float* b_upd0 = (const float*)d_in[12];
    const float* W_msg1 = (const float*)d_in[13];
    const float* b_msg1 = (const float*)d_in[14];
    const float* W_upd1 = (const float*)d_in[15];
    const float* b_upd1 = (const float*)d_in[16];
    const float* W_r1   = (const float*)d_in[17];
    const float* b_r1   = (const float*)d_in[18];
    const float* W_r2   = (const float*)d_in[19];
    const float* b_r2   = (const float*)d_in[20];
    float* out = (float*)d_out;

    const int nTiles = (NN + 127) / 128;

    cudaFuncSetAttribute(msg_v11, cudaFuncAttributeMaxDynamicSharedMemorySize, SM_TOTAL);
    cudaFuncSetAttribute(gemmx2h, cudaFuncAttributeMaxDynamicSharedMemorySize, GX_TOTAL);
    cudaFuncSetAttribute(upd_x,   cudaFuncAttributeMaxDynamicSharedMemorySize, UX_TOTAL);

    // ---- edge sort by dst + ef fp16 pre-permute + padding
    zcnt<<<(NN + 256) / 256, 256>>>();
    hist<<<NE / 256, 256>>>(eidx);
    scan20k<<<1, 1024>>>();
    scatter<<<NE / 256, 256>>>(eidx, edge_feats);
    pad_init<<<1, 32>>>();

    node_embed<<<NN / 16, 128>>>(node_feats, W_node, b_node);
    prep_all<<<12, 256>>>(W_msg0, W_msg1, W_upd0, W_upd1, W_r1);

    // ---- layer 0
    gemmx2h<<<nTiles, 256, GX_TOTAL>>>(0, 0, 1);
    msg_v11<<<304, 192, SM_TOTAL>>>(0, W_edge, b_edge, b_msg0);
    upd_x<<<nTiles, 256, UX_TOTAL>>>(0, b_upd0);

    // ---- layer 1
    gemmx2h<<<nTiles, 256, GX_TOTAL>>>(1, 1, 1);
    msg_v11<<<304, 192, SM_TOTAL>>>(1, W_edge, b_edge, b_msg1);
    upd_x<<<nTiles, 256, UX_TOTAL>>>(1, b_upd1);   // also emits Q1/Q3 -> g_P1/g_P3

    // ---- readout
    dem_v2<<<ND / 8, 256>>>(pairs, dem_feats, W_r1 + 256 * HID, b_r1, W_r2, b_r2, out);
}

// round 13
// speedup vs baseline: 1.0742x; 1.0403x over previous
#include <cuda_runtime.h>
#include <cuda_fp16.h>
#include <math.h>
#include <stdint.h>

#define HID 128
#define NN 20000
#define NE 640000
#define NEP 640032
#define ND 100000

// scratch (device globals: allocation-free contract)
__device__ float g_hn0[(size_t)NN * HID];
__device__ float g_hn1[(size_t)NN * HID];
__device__ float g_agg[(size_t)(NN + 1) * HID];
__device__ float g_P1 [(size_t)NN * HID];
__device__ float g_P3 [(size_t)(NN + 1) * HID];   // sentinel row stays 0
// fp16 weight images, [n][k] row-major
__device__ __align__(16) __half g_Wh [2][128 * 128];
__device__ __align__(16) __half g_Wp1[2][128 * 128];
__device__ __align__(16) __half g_Wp3[2][128 * 128];
__device__ __align__(16) __half g_Wuh[2][2][128 * 128];
__device__ __align__(16) __half g_Wul[2][2][128 * 128];
__device__ __align__(16) __half g_Wq1h[128 * 128];
__device__ __align__(16) __half g_Wq1l[128 * 128];
__device__ __align__(16) __half g_Wq3h[128 * 128];
__device__ __align__(16) __half g_Wq3l[128 * 128];
__device__ __align__(16) __half g_Wnh[128 * 32];   // W_node^T hi/lo, [n][k=32]
__device__ __align__(16) __half g_Wnl[128 * 32];
// edge sort-by-dst (+ pre-permuted fp16 edge features), padded
__device__ int g_cnt[NN + 1];
__device__ int g_srcp[NEP];
__device__ int g_dstp[NEP];
__device__ __align__(16) __half g_efh[(size_t)NEP * 16];

// ======================= helpers =======================
__device__ __forceinline__ uint32_t smem_u32(const void* p) {
    uint32_t a;
    asm("{ .reg .u64 t; cvta.to.shared.u64 t, %1; cvt.u32.u64 %0, t; }" : "=r"(a) : "l"(p));
    return a;
}
__device__ __forceinline__ void ldsm4(uint32_t& r0, uint32_t& r1, uint32_t& r2, uint32_t& r3,
                                      uint32_t addr) {
    asm volatile("ldmatrix.sync.aligned.m8n8.x4.shared.b16 {%0,%1,%2,%3}, [%4];"
                 : "=r"(r0), "=r"(r1), "=r"(r2), "=r"(r3) : "r"(addr));
}
__device__ __forceinline__ void mma16816h(float* c, uint32_t a0, uint32_t a1, uint32_t a2,
                                          uint32_t a3, uint32_t b0, uint32_t b1) {
    asm volatile("mma.sync.aligned.m16n8k16.row.col.f32.f16.f16.f32 "
                 "{%0,%1,%2,%3}, {%4,%5,%6,%7}, {%8,%9}, {%0,%1,%2,%3};"
                 : "+f"(c[0]), "+f"(c[1]), "+f"(c[2]), "+f"(c[3])
                 : "r"(a0), "r"(a1), "r"(a2), "r"(a3), "r"(b0), "r"(b1));
}
__device__ __forceinline__ uint32_t pack2h(float v0, float v1) {
    __half h0 = __float2half_rn(v0);
    __half h1 = __float2half_rn(v1);
    return (uint32_t)__half_as_ushort(h0) | ((uint32_t)__half_as_ushort(h1) << 16);
}
__device__ __forceinline__ void split2h(float v0, float v1, uint32_t& hi, uint32_t& lo) {
    __half h0 = __float2half_rn(v0);
    __half h1 = __float2half_rn(v1);
    __half m0 = __float2half_rn(v0 - __half2float(h0));
    __half m1 = __float2half_rn(v1 - __half2float(h1));
    hi = (uint32_t)__half_as_ushort(h0) | ((uint32_t)__half_as_ushort(h1) << 16);
    lo = (uint32_t)__half_as_ushort(m0) | ((uint32_t)__half_as_ushort(m1) << 16);
}
__device__ __forceinline__ void cp16(uint32_t smem_dst, const void* gsrc) {
    asm volatile("cp.async.cg.shared.global [%0], [%1], 16;"
                 :: "r"(smem_dst), "l"(gsrc) : "memory");
}
#define CP_COMMIT()  asm volatile("cp.async.commit_group;" ::: "memory")
#define CP_WAIT(N)   asm volatile("cp.async.wait_group %0;" :: "n"(N) : "memory")

// ---------------------------------------------------------------- sort by dst
__global__ void zcnt()
{
    int i = blockIdx.x * 256 + threadIdx.x;
    if (i <= NN) g_cnt[i] = 0;
}
__global__ void hist(const int* __restrict__ eidx)
{
    int e = blockIdx.x * 256 + threadIdx.x;
    atomicAdd(&g_cnt[eidx[NE + e]], 1);
}
__global__ void scan20k()
{
    __shared__ int part[1024];
    __shared__ int wsum[32];
    const int tid = threadIdx.x;
    const int CH = 20;
    int base = tid * CH;
    int loc[CH];
    int s = 0;
#pragma unroll
    for (int i = 0; i < CH; i++) {
        int v = (base + i <= NN) ? g_cnt[base + i] : 0;
        loc[i] = s; s += v;
    }
    part[tid] = s;
    __syncthreads();
    int lane = tid & 31, w = tid >> 5;
    int v = part[tid];
#pragma unroll
    for (int o = 1; o < 32; o <<= 1) { int t = __shfl_up_sync(~0u, v, o); if (lane >= o) v += t; }
    if (lane == 31) wsum[w] = v;
    __syncthreads();
    if (w == 0) {
        int x = wsum[lane];
#pragma unroll
        for (int o = 1; o < 32; o <<= 1) { int t = __shfl_up_sync(~0u, x, o); if (lane >= o) x += t; }
        wsum[lane] = x;
    }
    __syncthreads();
    int excl = v - part[tid] + (w ? wsum[w - 1] : 0);
#pragma unroll
    for (int i = 0; i < CH; i++)
        if (base + i <= NN) g_cnt[base + i] = excl + loc[i];
}
__global__ void scatter(const int* __restrict__ eidx, const float* __restrict__ ef)
{
    int e = blockIdx.x * 256 + threadIdx.x;
    int s = eidx[e], d = eidx[NE + e];
    int p = atomicAdd(&g_cnt[d], 1);
    g_srcp[p] = s; g_dstp[p] = d;
    const float4* eg = (const float4*)(ef + (size_t)e * 16);
    float4 v0 = eg[0], v1 = eg[1], v2 = eg[2], v3 = eg[3];
    uint4* dh = (uint4*)(g_efh + (size_t)p * 16);
    dh[0] = make_uint4(pack2h(v0.x, v0.y), pack2h(v0.z, v0.w),
                       pack2h(v1.x, v1.y), pack2h(v1.z, v1.w));
    dh[1] = make_uint4(pack2h(v2.x, v2.y), pack2h(v2.z, v2.w),
                       pack2h(v3.x, v3.y), pack2h(v3.z, v3.w));
}
__global__ void pad_init()
{
    int i = threadIdx.x;   // 32
    g_srcp[NE + i] = 0;
    g_dstp[NE + i] = NN;
    uint4 z = make_uint4(0, 0, 0, 0);
    uint4* dh = (uint4*)(g_efh + (size_t)(NE + i) * 16);
    dh[0] = z; dh[1] = z;
}

// ------------------------------ weight prep: fp16 [n][k] images
__global__ void prep_all(const float* __restrict__ Wm0, const float* __restrict__ Wm1,
                         const float* __restrict__ Wu0, const float* __restrict__ Wu1,
                         const float* __restrict__ Wr1, const float* __restrict__ Wn)
{
    int b = blockIdx.x;
    if (b < 6) {
        const float* src; __half* dst;
        switch (b) {
            case 0: src = Wm0 + 128 * 128; dst = g_Wh[0];  break;
            case 1: src = Wm1 + 128 * 128; dst = g_Wh[1];  break;
            case 2: src = Wm0;             dst = g_Wp1[0]; break;
            case 3: src = Wm1;             dst = g_Wp1[1]; break;
            case 4: src = Wm0 + 256 * 128; dst = g_Wp3[0]; break;
            default: src = Wm1 + 256 * 128; dst = g_Wp3[1]; break;
        }
        for (int idx = threadIdx.x; idx < 128 * 128; idx += 256) {
            int n = idx >> 7, k = idx & 127;
            dst[idx] = __float2half_rn(src[k * 128 + n]);
        }
    } else if (b < 10) {
        int l = (b - 6) >> 1, p = (b - 6) & 1;
        const float* src = (l ? Wu1 : Wu0) + p * 128 * 128;
        __half* dh = g_Wuh[l][p];
        __half* dl = g_Wul[l][p];
        for (int idx = threadIdx.x; idx < 128 * 128; idx += 256) {
            int n = idx >> 7, k = idx & 127;
            float w = src[k * 128 + n];
            __half h = __float2half_rn(w);
            dh[idx] = h;
            dl[idx] = __float2half_rn(w - __half2float(h));
        }
    } else if (b < 12) {
        const float* src = (b == 10) ? Wr1 : (Wr1 + 128 * 128);
        __half* dh = (b == 10) ? g_Wq1h : g_Wq3h;
        __half* dl = (b == 10) ? g_Wq1l : g_Wq3l;
        for (int idx = threadIdx.x; idx < 128 * 128; idx += 256) {
            int n = idx >> 7, k = idx & 127;
            float w = src[k * 128 + n];
            __half h = __float2half_rn(w);
            dh[idx] = h;
            dl[idx] = __float2half_rn(w - __half2float(h));
        }
    } else {
        for (int idx = threadIdx.x; idx < 128 * 32; idx += 256) {
            int n = idx >> 5, k = idx & 31;
            float w = Wn[k * 128 + n];
            __half h = __float2half_rn(w);
            g_Wnh[idx] = h;
            g_Wnl[idx] = __float2half_rn(w - __half2float(h));
        }
    }
}

// ---------------- fused node embed + layer0 P1/P3 chain (+agg zero)
// hn0 = relu(x@Wn + b) via exact 3-product (K=32), kept in accs;
// then P1 = hn0@Wp1[0], P3 = hn0@Wp3[0] single-product from fragments.
#define EB_AH 0
#define EB_AL 10240
#define EB_WH 20480
#define EB_WL 30720
#define EB_P  40960              // Wp1[0] image then Wp3[0], stride 272 each
#define EB_B  110592
#define EB_TOTAL 111104
#define EBST  80

__global__ void __launch_bounds__(256)
embed_p(const float* __restrict__ x, const float* __restrict__ b)
{
    extern __shared__ __align__(16) char smem[];
    const uint32_t sb = smem_u32(smem);
    const int tid = threadIdx.x;
    const int wid = tid >> 5, lane = tid & 31;
    const int nBase = blockIdx.x * 128;
    float* sB = (float*)(smem + EB_B);
    if (tid < 128) sB[tid] = b[tid];

    // stage x fp16 hi/lo [128][40 fp16 padded]
    {
        int r = tid >> 1, u = tid & 1;
        int nrow = min(nBase + r, NN - 1);
        const float4* src = (const float4*)(x + (size_t)nrow * 32) + u * 4;
        uint32_t hi[8], lo[8];
#pragma unroll
        for (int q = 0; q < 4; q++) {
            float4 a = src[q];
            split2h(a.x, a.y, hi[2 * q], lo[2 * q]);
            split2h(a.z, a.w, hi[2 * q + 1], lo[2 * q + 1]);
        }
        uint32_t off = (uint32_t)(r * EBST + u * 32);
        *(uint4*)(smem + EB_AH + off)      = make_uint4(hi[0], hi[1], hi[2], hi[3]);
        *(uint4*)(smem + EB_AH + off + 16) = make_uint4(hi[4], hi[5], hi[6], hi[7]);
        *(uint4*)(smem + EB_AL + off)      = make_uint4(lo[0], lo[1], lo[2], lo[3]);
        *(uint4*)(smem + EB_AL + off + 16) = make_uint4(lo[4], lo[5], lo[6], lo[7]);
    }
    // stage Wn^T hi/lo [128][40]
    {
        int r = tid >> 1, u = tid & 1;
        const uint4* wh = (const uint4*)(g_Wnh + r * 32) + u * 2;
        const uint4* wl = (const uint4*)(g_Wnl + r * 32) + u * 2;
        uint32_t off = (uint32_t)(r * EBST + u * 32);
        *(uint4*)(smem + EB_WH + off)      = wh[0];
        *(uint4*)(smem + EB_WH + off + 16) = wh[1];
        *(uint4*)(smem + EB_WL + off)      = wl[0];
        *(uint4*)(smem + EB_WL + off + 16) = wl[1];
    }
    // stage Wp1[0]/Wp3[0] images [n][136], stride 272
    {
        const uint4* w1 = (const uint4*)g_Wp1[0];
        const uint4* w3 = (const uint4*)g_Wp3[0];
#pragma unroll
        for (int i = 0; i < 8; i++) {
            int g = tid + i * 256;
            int n = g >> 4, q = g & 15;
            *(uint4*)(smem + EB_P + n * 272 + q * 16) = w1[g];
            *(uint4*)(smem + EB_P + 34816 + n * 272 + q * 16) = w3[g];
        }
    }
    // zero agg rows for this tile (layer 0)
    {
#pragma unroll
        for (int i = 0; i < 16; i++) {
            int g = tid + i * 256;
            int r = g >> 5, c = (g & 31) * 4;
            int row = nBase + r;
            if (row < NN)
                *(float4*)&g_agg[(size_t)row * HID + c] = make_float4(0.f, 0.f, 0.f, 0.f);
        }
    }
    __syncthreads();

    const int wm = wid * 16;
    const uint32_t aOff = (uint32_t)((wm + (lane & 7) + ((lane >> 3) & 1) * 8) * EBST
                                     + (lane >> 4) * 16);
    const uint32_t bOffW = (uint32_t)(((lane & 7) + (lane >> 4) * 8) * EBST
                                      + ((lane >> 3) & 1) * 16);
    const uint32_t bOffP = (uint32_t)(((lane & 7) + (lane >> 4) * 8) * 272
                                      + (((lane >> 3) & 1) * 8) * 2);
    const int er0 = wm + (lane >> 2);
    const int cb  = (lane & 3) * 2;
    const int row0 = nBase + er0, row1 = row0 + 8;

    // hn0 GEMM (K=32, 3-product exact)
    float acc[16][4];
#pragma unroll
    for (int n = 0; n < 16; n++)
#pragma unroll
        for (int j = 0; j < 4; j++) acc[n][j] = 0.f;
#pragma unroll
    for (int ks = 0; ks < 2; ks++) {
        uint32_t ah0, ah1, ah2, ah3, al0, al1, al2, al3;
        ldsm4(ah0, ah1, ah2, ah3, sb + EB_AH + aOff + ks * 32);
        ldsm4(al0, al1, al2, al3, sb + EB_AL + aOff + ks * 32);
#pragma unroll
        for (int np = 0; np < 8; np++) {
            uint32_t bh0, bh1, bh2, bh3, bl0, bl1, bl2, bl3;
            ldsm4(bh0, bh1, bh2, bh3, sb + EB_WH + bOffW + np * (16 * EBST) + ks * 32);
            ldsm4(bl0, bl1, bl2, bl3, sb + EB_WL + bOffW + np * (16 * EBST) + ks * 32);
            mma16816h(acc[2 * np],     ah0, ah1, ah2, ah3, bh0, bh1);
            mma16816h(acc[2 * np],     ah0, ah1, ah2, ah3, bl0, bl1);
            mma16816h(acc[2 * np],     al0, al1, al2, al3, bh0, bh1);
            mma16816h(acc[2 * np + 1], ah0, ah1, ah2, ah3, bh2, bh3);
            mma16816h(acc[2 * np + 1], ah0, ah1, ah2, ah3, bl2, bl3);
            mma16816h(acc[2 * np + 1], al0, al1, al2, al3, bh2, bh3);
        }
    }

    // bias + relu, write hn0, build A fragments
    uint32_t aH[8][4];
#pragma unroll
    for (int nt = 0; nt < 16; nt++) {
        int col = nt * 8 + cb;
        float b0 = sB[col], b1 = sB[col + 1];
        float v0 = fmaxf(acc[nt][0] + b0, 0.f);
        float v1 = fmaxf(acc[nt][1] + b1, 0.f);
        float v2 = fmaxf(acc[nt][2] + b0, 0.f);
        float v3 = fmaxf(acc[nt][3] + b1, 0.f);
        if (row0 < NN)
            *(float2*)&g_hn0[(size_t)row0 * HID + col] = make_float2(v0, v1);
        if (row1 < NN)
            *(float2*)&g_hn0[(size_t)row1 * HID + col] = make_float2(v2, v3);
        int ks = nt >> 1, j0 = (nt & 1) * 2;
        aH[ks][j0]     = pack2h(v0, v1);
        aH[ks][j0 + 1] = pack2h(v2, v3);
    }

    // P1/P3 layer-0 GEMMs (single product)
#pragma unroll
    for (int o = 0; o < 2; o++) {
        const uint32_t bA = sb + EB_P + o * 34816 + bOffP;
        float q[16][4];
#pragma unroll
        for (int n = 0; n < 16; n++)
#pragma unroll
            for (int j = 0; j < 4; j++) q[n][j] = 0.f;
#pragma unroll
        for (int ks = 0; ks < 8; ks++) {
#pragma unroll
            for (int np = 0; np < 8; np++) {
                uint32_t b0, b1, b2, b3;
                ldsm4(b0, b1, b2, b3, bA + np * (16 * 272) + ks * 32);
                mma16816h(q[2 * np],     aH[ks][0], aH[ks][1], aH[ks][2], aH[ks][3], b0, b1);
                mma16816h(q[2 * np + 1], aH[ks][0], aH[ks][1], aH[ks][2], aH[ks][3], b2, b3);
            }
        }
        float* out = o ? g_P3 : g_P1;
#pragma unroll
        for (int nt = 0; nt < 16; nt++) {
            int col = nt * 8 + cb;
            if (row0 < NN)
                *(float2*)&out[(size_t)row0 * HID + col] = make_float2(q[nt][0], q[nt][1]);
            if (row1 < NN)
                *(float2*)&out[(size_t)row1 * HID + col] = make_float2(q[nt][2], q[nt][3]);
        }
    }
}

// ---------------- exact (3-product) update GEMM, split-K
// layer 0: chains layer-1 P1/P3 (single product) + zeroes agg
// layer 1: chains readout Q1/Q3 (3-product)
#define UX_AH 0
#define UX_AL 34816
#define UX_WH 69632
#define UX_WL 104448
#define UX_B  139264
#define UX_TOTAL 139776
#define UXST 272

__global__ void __launch_bounds__(256)
upd_x(int layer, const float* __restrict__ bias)
{
    extern __shared__ __align__(16) char smem[];
    const uint32_t sb = smem_u32(smem);
    const float* __restrict__ hn   = layer ? g_hn1 : g_hn0;
    float*       __restrict__ hout = layer ? g_hn0 : g_hn1;
    const int tid = threadIdx.x;
    const int wid = tid >> 5, lane = tid & 31;
    const int nBase = blockIdx.x * 128;
    float* sB = (float*)(smem + UX_B);
    if (tid < 128) sB[tid] = bias[tid];

    const int wm = wid * 16;
    const uint32_t aOff = (uint32_t)((wm + (lane & 7) + ((lane >> 3) & 1) * 8) * UXST
                                     + (lane >> 4) * 16);
    const uint32_t bOff = (uint32_t)(((lane & 7) + (lane >> 4) * 8) * UXST
                                     + (((lane >> 3) & 1) * 8) * 2);
    const int er0 = wm + (lane >> 2);
    const int cb  = (lane & 3) * 2;
    const int row0 = nBase + er0, row1 = row0 + 8;

    float acc[16][4];
#pragma unroll
    for (int n = 0; n < 16; n++)
#pragma unroll
        for (int j = 0; j < 4; j++) acc[n][j] = 0.f;

    for (int p = 0; p < 2; p++) {
        {
            int r = tid >> 1, u = tid & 1;
            int nrow = min(nBase + r, NN - 1);
            const float4* src = (const float4*)((p ? g_agg : hn) + (size_t)nrow * HID) + u * 16;
            uint32_t da = (uint32_t)(UX_AH + r * UXST + u * 128);
            uint32_t dl = (uint32_t)(UX_AL + r * UXST + u * 128);
#pragma unroll
            for (int q = 0; q < 8; q++) {
                float4 a = src[2 * q], bv = src[2 * q + 1];
                uint32_t h0, l0, h1, l1, h2, l2, h3, l3;
                split2h(a.x, a.y, h0, l0);  split2h(a.z, a.w, h1, l1);
                split2h(bv.x, bv.y, h2, l2); split2h(bv.z, bv.w, h3, l3);
                *(uint4*)(smem + da + q * 16) = make_uint4(h0, h1, h2, h3);
                *(uint4*)(smem + dl + q * 16) = make_uint4(l0, l1, l2, l3);
            }
        }
        {
            const uint4* wh = (const uint4*)g_Wuh[layer][p];
            const uint4* wl = (const uint4*)g_Wul[layer][p];
#pragma unroll
            for (int i = 0; i < 8; i++) {
                int g = tid + i * 256;
                int n = g >> 4, q = g & 15;
                *(uint4*)(smem + UX_WH + n * UXST + q * 16) = wh[g];
                *(uint4*)(smem + UX_WL + n * UXST + q * 16) = wl[g];
            }
        }
        __syncthreads();

#pragma unroll
        for (int ks = 0; ks < 8; ks++) {
            uint32_t ah0, ah1, ah2, ah3, al0, al1, al2, al3;
            ldsm4(ah0, ah1, ah2, ah3, sb + UX_AH + aOff + ks * 32);
            ldsm4(al0, al1, al2, al3, sb + UX_AL + aOff + ks * 32);
#pragma unroll
            for (int np = 0; np < 8; np++) {
                uint32_t bh0, bh1, bh2, bh3, bl0, bl1, bl2, bl3;
                ldsm4(bh0, bh1, bh2, bh3, sb + UX_WH + bOff + np * (16 * UXST) + ks * 32);
                ldsm4(bl0, bl1, bl2, bl3, sb + UX_WL + bOff + np * (16 * UXST) + ks * 32);
                mma16816h(acc[2 * np],     ah0, ah1, ah2, ah3, bh0, bh1);
                mma16816h(acc[2 * np],     ah0, ah1, ah2, ah3, bl0, bl1);
                mma16816h(acc[2 * np],     al0, al1, al2, al3, bh0, bh1);
                mma16816h(acc[2 * np + 1], ah0, ah1, ah2, ah3, bh2, bh3);
                mma16816h(acc[2 * np + 1], ah0, ah1, ah2, ah3, bl2, bl3);
                mma16816h(acc[2 * np + 1], al0, al1, al2, al3, bh2, bh3);
            }
        }
        __syncthreads();
    }

    // bias + relu (in place), write hout
#pragma unroll
    for (int nt = 0; nt < 16; nt++) {
        int col = nt * 8 + cb;
        float b0 = sB[col], b1 = sB[col + 1];
        acc[nt][0] = fmaxf(acc[nt][0] + b0, 0.f);
        acc[nt][1] = fmaxf(acc[nt][1] + b1, 0.f);
        acc[nt][2] = fmaxf(acc[nt][2] + b0, 0.f);
        acc[nt][3] = fmaxf(acc[nt][3] + b1, 0.f);
        if (row0 < NN)
            *(float2*)&hout[(size_t)row0 * HID + col] = make_float2(acc[nt][0], acc[nt][1]);
        if (row1 < NN)
            *(float2*)&hout[(size_t)row1 * HID + col] = make_float2(acc[nt][2], acc[nt][3]);
    }

    if (layer == 0) {
        // zero agg rows for layer 1
#pragma unroll
        for (int i = 0; i < 16; i++) {
            int g = tid + i * 256;
            int r = g >> 5, c = (g & 31) * 4;
            int row = nBase + r;
            if (row < NN)
                *(float4*)&g_agg[(size_t)row * HID + c] = make_float4(0.f, 0.f, 0.f, 0.f);
        }
        // chain layer-1 P1/P3 (single product) from hn1 accs
        uint32_t aH[8][4];
#pragma unroll
        for (int nt = 0; nt < 16; nt++) {
            int ks = nt >> 1, j0 = (nt & 1) * 2;
            aH[ks][j0]     = pack2h(acc[nt][0], acc[nt][1]);
            aH[ks][j0 + 1] = pack2h(acc[nt][2], acc[nt][3]);
        }
        {
            const uint4* w1 = (const uint4*)g_Wp1[1];
            const uint4* w3 = (const uint4*)g_Wp3[1];
#pragma unroll
            for (int i = 0; i < 8; i++) {
                int g = tid + i * 256;
                int n = g >> 4, q = g & 15;
                *(uint4*)(smem + UX_AH + n * UXST + q * 16) = w1[g];
                *(uint4*)(smem + UX_WH + n * UXST + q * 16) = w3[g];
            }
        }
        __syncthreads();
#pragma unroll
        for (int o = 0; o < 2; o++) {
            const uint32_t bA = sb + (o ? UX_WH : UX_AH) + bOff;
            float q[16][4];
#pragma unroll
            for (int n = 0; n < 16; n++)
#pragma unroll
                for (int j = 0; j < 4; j++) q[n][j] = 0.f;
#pragma unroll
            for (int ks = 0; ks < 8; ks++) {
#pragma unroll
                for (int np = 0; np < 8; np++) {
                    uint32_t b0, b1, b2, b3;
                    ldsm4(b0, b1, b2, b3, bA + np * (16 * UXST) + ks * 32);
                    mma16816h(q[2 * np],     aH[ks][0], aH[ks][1], aH[ks][2], aH[ks][3], b0, b1);
                    mma16816h(q[2 * np + 1], aH[ks][0], aH[ks][1], aH[ks][2], aH[ks][3], b2, b3);
                }
            }
            float* out = o ? g_P3 : g_P1;
#pragma unroll
            for (int nt = 0; nt < 16; nt++) {
                int col = nt * 8 + cb;
                if (row0 < NN)
                    *(float2*)&out[(size_t)row0 * HID + col] = make_float2(q[nt][0], q[nt][1]);
                if (row1 < NN)
                    *(float2*)&out[(size_t)row1 * HID + col] = make_float2(q[nt][2], q[nt][3]);
            }
        }
    } else {
        // chain readout Q1/Q3 (3-product exact on hn2)
        uint32_t aH[8][4], aL[8][4];
#pragma unroll
        for (int nt = 0; nt < 16; nt++) {
            int ks = nt >> 1, j0 = (nt & 1) * 2;
            split2h(acc[nt][0], acc[nt][1], aH[ks][j0],     aL[ks][j0]);
            split2h(acc[nt][2], acc[nt][3], aH[ks][j0 + 1], aL[ks][j0 + 1]);
        }
        {
            const uint4* q1h = (const uint4*)g_Wq1h;
            const uint4* q1l = (const uint4*)g_Wq1l;
            const uint4* q3h = (const uint4*)g_Wq3h;
            const uint4* q3l = (const uint4*)g_Wq3l;
#pragma unroll
            for (int i = 0; i < 8; i++) {
                int g = tid + i * 256;
                int n = g >> 4, q = g & 15;
                *(uint4*)(smem + UX_AH + n * UXST + q * 16) = q1h[g];
                *(uint4*)(smem + UX_AL + n * UXST + q * 16) = q1l[g];
                *(uint4*)(smem + UX_WH + n * UXST + q * 16) = q3h[g];
                *(uint4*)(smem + UX_WL + n * UXST + q * 16) = q3l[g];
            }
        }
        __syncthreads();
#pragma unroll
        for (int o = 0; o < 2; o++) {
            const uint32_t bHA = sb + (o ? UX_WH : UX_AH) + bOff;
            const uint32_t bLA = sb + (o ? UX_WL : UX_AL) + bOff;
            float q[16][4];
#pragma unroll
            for (int n = 0; n < 16; n++)
#pragma unroll
                for (int j = 0; j < 4; j++) q[n][j] = 0.f;
#pragma unroll
            for (int ks = 0; ks < 8; ks++) {
#pragma unroll
                for (int np = 0; np < 8; np++) {
                    uint32_t bh0, bh1, bh2, bh3, bl0, bl1, bl2, bl3;
                    ldsm4(bh0, bh1, bh2, bh3, bHA + np * (16 * UXST) + ks * 32);
                    ldsm4(bl0, bl1, bl2, bl3, bLA + np * (16 * UXST) + ks * 32);
                    mma16816h(q[2 * np],     aH[ks][0], aH[ks][1], aH[ks][2], aH[ks][3], bh0, bh1);
                    mma16816h(q[2 * np],     aH[ks][0], aH[ks][1], aH[ks][2], aH[ks][3], bl0, bl1);
                    mma16816h(q[2 * np],     aL[ks][0], aL[ks][1], aL[ks][2], aL[ks][3], bh0, bh1);
                    mma16816h(q[2 * np + 1], aH[ks][0], aH[ks][1], aH[ks][2], aH[ks][3], bh2, bh3);
                    mma16816h(q[2 * np + 1], aH[ks][0], aH[ks][1], aH[ks][2], aH[ks][3], bl2, bl3);
                    mma16816h(q[2 * np + 1], aL[ks][0], aL[ks][1], aL[ks][2], aL[ks][3], bh2, bh3);
                }
            }
            float* out = o ? g_P3 : g_P1;
#pragma unroll
            for (int nt = 0; nt < 16; nt++) {
                int col = nt * 8 + cb;
                if (row0 < NN)
                    *(float2*)&out[(size_t)row0 * HID + col] = make_float2(q[nt][0], q[nt][1]);
                if (row1 < NN)
                    *(float2*)&out[(size_t)row1 * HID + col] = make_float2(q[nt][2], q[nt][3]);
            }
        }
    }
}

// ====================== pipelined fp16 MMA-chain edge kernel (M=96) =========
#define SM_BM    0
#define SM_BE    512
#define SM_IDX   1024
#define SM_WEH   2560
#define SM_EFH0  8704
#define SM_EFH1  13312
#define SM_BW    17920
#define SM_OUT   52736
#define SM_TOTAL 103424
#define TSTRIDE  272
#define EFST     48

__global__ void __launch_bounds__(192, 2)
msg_v11(int layer, const float* __restrict__ We, const float* __restrict__ be,
        const float* __restrict__ bm)
{
    extern __shared__ __align__(16) char smem[];
    const uint32_t sb = smem_u32(smem);
    const int tid = threadIdx.x;
    const int wid = tid >> 5, lane = tid & 31;

    float* sBm = (float*)(smem + SM_BM);
    float* beS = (float*)(smem + SM_BE);
    float* OUT = (float*)(smem + SM_OUT);

    if (tid < 128) {
        sBm[tid] = bm[tid]; beS[tid] = be[tid];
        int n = tid;
        uint32_t h8[8];
#pragma unroll
        for (int p = 0; p < 8; p++)
            h8[p] = pack2h(We[(2 * p) * 128 + n], We[(2 * p + 1) * 128 + n]);
        *(uint4*)(smem + SM_WEH + n * EFST)      = make_uint4(h8[0], h8[1], h8[2], h8[3]);
        *(uint4*)(smem + SM_WEH + n * EFST + 16) = make_uint4(h8[4], h8[5], h8[6], h8[7]);
    }
    {
        const uint4* wsrc = (const uint4*)g_Wh[layer];
#pragma unroll
        for (int u = 0; u < 11; u++) {
            int g = tid + u * 192;
            if (g < 2048) {
                int n = g >> 4, q = g & 15;
                *(uint4*)(smem + SM_BW + n * TSTRIDE + q * 16) = wsrc[g];
            }
        }
    }

    const int wm = wid * 16;
    const uint32_t aEfOff = (uint32_t)((wm + (lane & 7) + ((lane >> 3) & 1) * 8) * EFST
                                       + (lane >> 4) * 16);
    const uint32_t bEfOff = (uint32_t)(((lane & 7) + (lane >> 4) * 8) * EFST
                                       + ((lane >> 3) & 1) * 16);
    const uint32_t bMnOff = (uint32_t)(((lane & 7) + (lane >> 4) * 8) * TSTRIDE
                                       + (((lane >> 3) & 1) * 8) * 2);
    const uint32_t wehA = sb + SM_WEH + bEfOff;
    const uint32_t bwA  = sb + SM_BW + bMnOff;

    const int er0 = wm + (lane >> 2);
    const int cb  = (lane & 3) * 2;
    const int NT = NEP / 96;

    auto stage_async = [&](int t, int b) {
        const int eBase = t * 96;
        uint32_t efh = sb + (b ? SM_EFH1 : SM_EFH0);
        {
            int r = tid >> 1, u = tid & 1;
            cp16(efh + r * EFST + u * 16, (const char*)(g_efh + (size_t)(eBase + r) * 16) + u * 16);
        }
        if (tid < 24)
            cp16(sb + SM_IDX + b * 768 + tid * 16, (const char*)(g_srcp + eBase) + tid * 16);
        else if (tid < 48)
            cp16(sb + SM_IDX + b * 768 + 384 + (tid - 24) * 16, (const char*)(g_dstp + eBase) + (tid - 24) * 16);
    };

    int t = blockIdx.x;
    int buf = 0;
    if (t < NT) stage_async(t, 0);
    CP_COMMIT();

    for (; t < NT; t += gridDim.x, buf ^= 1) {
        CP_WAIT(0);
        __syncthreads();

        int* sSrc = (int*)(smem + SM_IDX + buf * 768);
        int* sDst = (int*)(smem + SM_IDX + buf * 768 + 384);

        {
#pragma unroll
            for (int i = 0; i < 16; i++) {
                int g = tid + i * 192;
                int r = g >> 5, c = g & 31;
                const char* src = (const char*)(g_P1 + (size_t)sSrc[r] * HID) + c * 16;
                cp16(sb + SM_OUT + r * 528 + c * 16, src);
            }
        }
        CP_COMMIT();

        int tn = t + gridDim.x;
        if (tn < NT) stage_async(tn, buf ^ 1);
        CP_COMMIT();

        const uint32_t efhA = sb + (buf ? SM_EFH1 : SM_EFH0) + aEfOff;
        float acc2[16][4];
#pragma unroll
        for (int n = 0; n < 16; n++)
#pragma unroll
            for (int j = 0; j < 4; j++) acc2[n][j] = 0.f;
        {
            uint32_t eh0, eh1, eh2, eh3;
            ldsm4(eh0, eh1, eh2, eh3, efhA);
#pragma unroll
            for (int g = 0; g < 8; g++) {
                uint32_t wh0, wh1, wh2, wh3;
                ldsm4(wh0, wh1, wh2, wh3, wehA + g * (16 * EFST));
                mma16816h(acc2[2 * g],     eh0, eh1, eh2, eh3, wh0, wh1);
                mma16816h(acc2[2 * g + 1], eh0, eh1, eh2, eh3, wh2, wh3);
            }
        }

        uint32_t aH[8][4];
#pragma unroll
        for (int nt = 0; nt < 16; nt++) {
            int col = nt * 8 + cb;
            float be0 = beS[col], be1 = beS[col + 1];
            float v0 = fmaxf(acc2[nt][0] + be0, 0.f);
            float v1 = fmaxf(acc2[nt][1] + be1, 0.f);
            float v2 = fmaxf(acc2[nt][2] + be0, 0.f);
            float v3 = fmaxf(acc2[nt][3] + be1, 0.f);
            int ks = nt >> 1, j0 = (nt & 1) * 2;
            aH[ks][j0]     = pack2h(v0, v1);
            aH[ks][j0 + 1] = pack2h(v2, v3);
        }

        float acc[16][4];
#pragma unroll
        for (int n = 0; n < 16; n++)
#pragma unroll
            for (int j = 0; j < 4; j++) acc[n][j] = 0.f;
#pragma unroll
        for (int ks = 0; ks < 8; ks++) {
#pragma unroll
            for (int np = 0; np < 8; np++) {
                uint32_t b0, b1, b2, b3;
                ldsm4(b0, b1, b2, b3, bwA + np * (16 * TSTRIDE) + ks * 32);
                mma16816h(acc[2 * np],     aH[ks][0], aH[ks][1], aH[ks][2], aH[ks][3], b0, b1);
                mma16816h(acc[2 * np + 1], aH[ks][0], aH[ks][1], aH[ks][2], aH[ks][3], b2, b3);
            }
        }

        CP_WAIT(1);
        __syncthreads();

        {
            int d0 = sDst[er0], d1 = sDst[er0 + 8];
            const float* p3a = g_P3 + (size_t)d0 * HID;
            const float* p3b = g_P3 + (size_t)d1 * HID;
            const float* p1a = &OUT[er0 * 132];
            const float* p1b = &OUT[(er0 + 8) * 132];
#pragma unroll
            for (int nt = 0; nt < 16; nt++) {
                int col = nt * 8 + cb;
                float2 q1 = *(const float2*)(p1a + col);
                float2 q3 = *(const float2*)(p3a + col);
                float2 o0;
                o0.x = fmaxf(acc[nt][0] + sBm[col]     + q1.x + q3.x, 0.f);
                o0.y = fmaxf(acc[nt][1] + sBm[col + 1] + q1.y + q3.y, 0.f);
                *(float2*)&OUT[er0 * 132 + col] = o0;
                float2 r1 = *(const float2*)(p1b + col);
                float2 r3 = *(const float2*)(p3b + col);
                float2 o1;
                o1.x = fmaxf(acc[nt][2] + sBm[col]     + r1.x + r3.x, 0.f);
                o1.y = fmaxf(acc[nt][3] + sBm[col + 1] + r1.y + r3.y, 0.f);
                *(float2*)&OUT[(er0 + 8) * 132 + col] = o1;
            }
        }
        __syncthreads();

        if (tid < 128) {
            int col = tid;
            float s = 0.f;
            int cur = sDst[0];
#pragma unroll 4
            for (int r2 = 0; r2 < 96; r2++) {
                int dn = sDst[r2];
                if (dn != cur) {
                    if (s != 0.f) atomicAdd(&g_agg[(size_t)cur * HID + col], s);
                    cur = dn; s = 0.f;
                }
                s += OUT[r2 * 132 + col];
            }
            if (s != 0.f) atomicAdd(&g_agg[(size_t)cur * HID + col], s);
        }
        __syncthreads();
    }
}

// --------------------------------------------- fused demand readout
__global__ void __launch_bounds__(256)
dem_v2(const int* __restrict__ pairs, const float* __restrict__ dfeat,
       const float* __restrict__ Wd, const float* __restrict__ br1,
       const float* __restrict__ w2, const float* __restrict__ b2,
       float* __restrict__ out)
{
    __shared__ __align__(16) float Wds[8][132];
    __shared__ float w2s[128], bs[128];
    int tid = threadIdx.x;
    if (tid < 128) { w2s[tid] = w2[tid]; bs[tid] = br1[tid]; }
    {
        int row = tid >> 5, c = (tid & 31) * 4;
        *(float4*)&Wds[row][c] = ((const float4*)Wd)[tid];
    }
    __syncthreads();

    int w = tid >> 5, lane = tid & 31;
    int d = blockIdx.x * 8 + w;
    int ds = pairs[2 * d], dd = pairs[2 * d + 1];
    int c0 = lane * 4;

    float4 q1 = *(const float4*)(g_P1 + (size_t)ds * HID + c0);
    float4 q2 = *(const float4*)(g_P3 + (size_t)dd * HID + c0);
    float s0 = bs[c0 + 0] + q1.x + q2.x;
    float s1 = bs[c0 + 1] + q1.y + q2.y;
    float s2 = bs[c0 + 2] + q1.z + q2.z;
    float s3 = bs[c0 + 3] + q1.w + q2.w;
#pragma unroll
    for (int q = 0; q < 8; q++) {
        float e = dfeat[(size_t)d * 8 + q];
        float4 wv = *(const float4*)&Wds[q][c0];
        s0 = fmaf(e, wv.x, s0); s1 = fmaf(e, wv.y, s1);
        s2 = fmaf(e, wv.z, s2); s3 = fmaf(e, wv.w, s3);
    }
    float p = fmaxf(s0, 0.f) * w2s[c0 + 0] + fmaxf(s1, 0.f) * w2s[c0 + 1]
            + fmaxf(s2, 0.f) * w2s[c0 + 2] + fmaxf(s3, 0.f) * w2s[c0 + 3];
#pragma unroll
    for (int o = 16; o > 0; o >>= 1) p += __shfl_xor_sync(0xffffffffu, p, o);
    if (lane == 0) out[d] = 1.f / (1.f + expf(-(p + b2[0])));
}

// ---------------------------------------------------------------- launch
extern "C" void kernel_launch(void* const* d_in, const int* in_sizes, int n_in,
                              void* d_out, int out_size)
{
    const float* node_feats = (const float*)d_in[0];
    const float* edge_feats = (const float*)d_in[1];
    const float* dem_feats  = (const float*)d_in[2];
    const int*   eidx       = (const int*)d_in[3];
    const int*   pairs      = (const int*)d_in[4];
    const float* W_node = (const float*)d_in[5];
    const float* b_node = (const float*)d_in[6];
    const float* W_edge = (const float*)d_in[7];
    const float* b_edge = (const float*)d_in[8];
    const float* W_msg0 = (const float*)d_in[9];
    const float* b_msg0 = (const float*)d_in[10];
    const float* W_upd0 = (const float*)d_in[11];
    const float* b_upd0 = (const float*)d_in[12];
    const float* W_msg1 = (const float*)d_in[13];
    const float* b_msg1 = (const float*)d_in[14];
    const float* W_upd1 = (const float*)d_in[15];
    const float* b_upd1 = (const float*)d_in[16];
    const float* W_r1   = (const float*)d_in[17];
    const float* b_r1   = (const float*)d_in[18];
    const float* W_r2   = (const float*)d_in[19];
    const float* b_r2   = (const float*)d_in[20];
    float* out = (float*)d_out;

    const int nTiles = (NN + 127) / 128;

    cudaFuncSetAttribute(msg_v11, cudaFuncAttributeMaxDynamicSharedMemorySize, SM_TOTAL);
    cudaFuncSetAttribute(embed_p, cudaFuncAttributeMaxDynamicSharedMemorySize, EB_TOTAL);
    cudaFuncSetAttribute(upd_x,   cudaFuncAttributeMaxDynamicSharedMemorySize, UX_TOTAL);

    // ---- edge sort by dst + ef fp16 pre-permute + padding
    zcnt<<<(NN + 256) / 256, 256>>>();
    hist<<<NE / 256, 256>>>(eidx);
    scan20k<<<1, 1024>>>();
    scatter<<<NE / 256, 256>>>(eidx, edge_feats);
    pad_init<<<1, 32>>>();

    prep_all<<<13, 256>>>(W_msg0, W_msg1, W_upd0, W_upd1, W_r1, W_node);

    // ---- fused embed + layer-0 P1/P3 + agg zero
    embed_p<<<nTiles, 256, EB_TOTAL>>>(node_feats, b_node);

    // ---- layer 0
    msg_v11<<<304, 192, SM_TOTAL>>>(0, W_edge, b_edge, b_msg0);
    upd_x<<<nTiles, 256, UX_TOTAL>>>(0, b_upd0);   // chains layer-1 P1/P3 + agg zero

    // ---- layer 1
    msg_v11<<<304, 192, SM_TOTAL>>>(1, W_edge, b_edge, b_msg1);
    upd_x<<<nTiles, 256, UX_TOTAL>>>(1, b_upd1);   // chains readout Q1/Q3

    // ---- readout
    dem_v2<<<ND / 8, 256>>>(pairs, dem_feats, W_r1 + 256 * HID, b_r1, W_r2, b_r2, out);
}

// round 14
// speedup vs baseline: 1.1061x; 1.0297x over previous
#include <cuda_runtime.h>
#include <cuda_fp16.h>
#include <math.h>
#include <stdint.h>

#define HID 128
#define NN 20000
#define NE 640000
#define NEP 640032
#define ND 100000

// scratch (device globals: allocation-free contract)
__device__ float g_hn0[(size_t)NN * HID];
__device__ float g_hn1[(size_t)NN * HID];
__device__ float g_agg[(size_t)(NN + 1) * HID];
__device__ float g_P1 [(size_t)NN * HID];
__device__ float g_P3 [(size_t)(NN + 1) * HID];   // sentinel row stays 0
// fp16 weight images, [n][k] row-major
__device__ __align__(16) __half g_Wh [2][128 * 128];
__device__ __align__(16) __half g_Wp1[2][128 * 128];
__device__ __align__(16) __half g_Wp3[2][128 * 128];
__device__ __align__(16) __half g_Wuh[2][2][128 * 128];
__device__ __align__(16) __half g_Wul[2][2][128 * 128];
__device__ __align__(16) __half g_Wq1h[128 * 128];
__device__ __align__(16) __half g_Wq1l[128 * 128];
__device__ __align__(16) __half g_Wq3h[128 * 128];
__device__ __align__(16) __half g_Wq3l[128 * 128];
__device__ __align__(16) __half g_Wnh[128 * 32];
__device__ __align__(16) __half g_Wnl[128 * 32];
// edge sort-by-dst (+ pre-permuted fp16 edge features), padded
__device__ int g_cnt[NN + 1];
__device__ int g_srcp[NEP];
__device__ int g_dstp[NEP];
__device__ __align__(16) __half g_efh[(size_t)NEP * 16];

// ======================= helpers =======================
__device__ __forceinline__ uint32_t smem_u32(const void* p) {
    uint32_t a;
    asm("{ .reg .u64 t; cvta.to.shared.u64 t, %1; cvt.u32.u64 %0, t; }" : "=r"(a) : "l"(p));
    return a;
}
__device__ __forceinline__ void ldsm4(uint32_t& r0, uint32_t& r1, uint32_t& r2, uint32_t& r3,
                                      uint32_t addr) {
    asm volatile("ldmatrix.sync.aligned.m8n8.x4.shared.b16 {%0,%1,%2,%3}, [%4];"
                 : "=r"(r0), "=r"(r1), "=r"(r2), "=r"(r3) : "r"(addr));
}
__device__ __forceinline__ void mma16816h(float* c, uint32_t a0, uint32_t a1, uint32_t a2,
                                          uint32_t a3, uint32_t b0, uint32_t b1) {
    asm volatile("mma.sync.aligned.m16n8k16.row.col.f32.f16.f16.f32 "
                 "{%0,%1,%2,%3}, {%4,%5,%6,%7}, {%8,%9}, {%0,%1,%2,%3};"
                 : "+f"(c[0]), "+f"(c[1]), "+f"(c[2]), "+f"(c[3])
                 : "r"(a0), "r"(a1), "r"(a2), "r"(a3), "r"(b0), "r"(b1));
}
__device__ __forceinline__ uint32_t pack2h(float v0, float v1) {
    __half h0 = __float2half_rn(v0);
    __half h1 = __float2half_rn(v1);
    return (uint32_t)__half_as_ushort(h0) | ((uint32_t)__half_as_ushort(h1) << 16);
}
__device__ __forceinline__ void split2h(float v0, float v1, uint32_t& hi, uint32_t& lo) {
    __half h0 = __float2half_rn(v0);
    __half h1 = __float2half_rn(v1);
    __half m0 = __float2half_rn(v0 - __half2float(h0));
    __half m1 = __float2half_rn(v1 - __half2float(h1));
    hi = (uint32_t)__half_as_ushort(h0) | ((uint32_t)__half_as_ushort(h1) << 16);
    lo = (uint32_t)__half_as_ushort(m0) | ((uint32_t)__half_as_ushort(m1) << 16);
}
__device__ __forceinline__ void cp16(uint32_t smem_dst, const void* gsrc) {
    asm volatile("cp.async.cg.shared.global [%0], [%1], 16;"
                 :: "r"(smem_dst), "l"(gsrc) : "memory");
}
#define CP_COMMIT()  asm volatile("cp.async.commit_group;" ::: "memory")
#define CP_WAIT(N)   asm volatile("cp.async.wait_group %0;" :: "n"(N) : "memory")

// ---------------------------------------------------------------- sort by dst
__global__ void zcnt()
{
    int i = blockIdx.x * 256 + threadIdx.x;
    if (i <= NN) g_cnt[i] = 0;
}
__global__ void hist(const int* __restrict__ eidx)
{
    int e = blockIdx.x * 256 + threadIdx.x;
    atomicAdd(&g_cnt[eidx[NE + e]], 1);
}
__global__ void scan20k()
{
    __shared__ int part[1024];
    __shared__ int wsum[32];
    const int tid = threadIdx.x;
    const int CH = 20;
    int base = tid * CH;
    int loc[CH];
    int s = 0;
#pragma unroll
    for (int i = 0; i < CH; i++) {
        int v = (base + i <= NN) ? g_cnt[base + i] : 0;
        loc[i] = s; s += v;
    }
    part[tid] = s;
    __syncthreads();
    int lane = tid & 31, w = tid >> 5;
    int v = part[tid];
#pragma unroll
    for (int o = 1; o < 32; o <<= 1) { int t = __shfl_up_sync(~0u, v, o); if (lane >= o) v += t; }
    if (lane == 31) wsum[w] = v;
    __syncthreads();
    if (w == 0) {
        int x = wsum[lane];
#pragma unroll
        for (int o = 1; o < 32; o <<= 1) { int t = __shfl_up_sync(~0u, x, o); if (lane >= o) x += t; }
        wsum[lane] = x;
    }
    __syncthreads();
    int excl = v - part[tid] + (w ? wsum[w - 1] : 0);
#pragma unroll
    for (int i = 0; i < CH; i++)
        if (base + i <= NN) g_cnt[base + i] = excl + loc[i];
}
// scatter: sort + ef fp16 pre-permute; block 0 also writes pad entries
__global__ void scatter(const int* __restrict__ eidx, const float* __restrict__ ef)
{
    if (blockIdx.x == 0 && threadIdx.x < 32) {
        int i = threadIdx.x;
        g_srcp[NE + i] = 0;
        g_dstp[NE + i] = NN;
        uint4 z = make_uint4(0, 0, 0, 0);
        uint4* dh = (uint4*)(g_efh + (size_t)(NE + i) * 16);
        dh[0] = z; dh[1] = z;
    }
    int e = blockIdx.x * 256 + threadIdx.x;
    int s = eidx[e], d = eidx[NE + e];
    int p = atomicAdd(&g_cnt[d], 1);
    g_srcp[p] = s; g_dstp[p] = d;
    const float4* eg = (const float4*)(ef + (size_t)e * 16);
    float4 v0 = eg[0], v1 = eg[1], v2 = eg[2], v3 = eg[3];
    uint4* dh = (uint4*)(g_efh + (size_t)p * 16);
    dh[0] = make_uint4(pack2h(v0.x, v0.y), pack2h(v0.z, v0.w),
                       pack2h(v1.x, v1.y), pack2h(v1.z, v1.w));
    dh[1] = make_uint4(pack2h(v2.x, v2.y), pack2h(v2.z, v2.w),
                       pack2h(v3.x, v3.y), pack2h(v3.z, v3.w));
}

// ------------------------------ weight prep: fp16 [n][k] images
__global__ void prep_all(const float* __restrict__ Wm0, const float* __restrict__ Wm1,
                         const float* __restrict__ Wu0, const float* __restrict__ Wu1,
                         const float* __restrict__ Wr1, const float* __restrict__ Wn)
{
    int b = blockIdx.x;
    if (b < 6) {
        const float* src; __half* dst;
        switch (b) {
            case 0: src = Wm0 + 128 * 128; dst = g_Wh[0];  break;
            case 1: src = Wm1 + 128 * 128; dst = g_Wh[1];  break;
            case 2: src = Wm0;             dst = g_Wp1[0]; break;
            case 3: src = Wm1;             dst = g_Wp1[1]; break;
            case 4: src = Wm0 + 256 * 128; dst = g_Wp3[0]; break;
            default: src = Wm1 + 256 * 128; dst = g_Wp3[1]; break;
        }
        for (int idx = threadIdx.x; idx < 128 * 128; idx += 256) {
            int n = idx >> 7, k = idx & 127;
            dst[idx] = __float2half_rn(src[k * 128 + n]);
        }
    } else if (b < 10) {
        int l = (b - 6) >> 1, p = (b - 6) & 1;
        const float* src = (l ? Wu1 : Wu0) + p * 128 * 128;
        __half* dh = g_Wuh[l][p];
        __half* dl = g_Wul[l][p];
        for (int idx = threadIdx.x; idx < 128 * 128; idx += 256) {
            int n = idx >> 7, k = idx & 127;
            float w = src[k * 128 + n];
            __half h = __float2half_rn(w);
            dh[idx] = h;
            dl[idx] = __float2half_rn(w - __half2float(h));
        }
    } else if (b < 12) {
        const float* src = (b == 10) ? Wr1 : (Wr1 + 128 * 128);
        __half* dh = (b == 10) ? g_Wq1h : g_Wq3h;
        __half* dl = (b == 10) ? g_Wq1l : g_Wq3l;
        for (int idx = threadIdx.x; idx < 128 * 128; idx += 256) {
            int n = idx >> 7, k = idx & 127;
            float w = src[k * 128 + n];
            __half h = __float2half_rn(w);
            dh[idx] = h;
            dl[idx] = __float2half_rn(w - __half2float(h));
        }
    } else {
        for (int idx = threadIdx.x; idx < 128 * 32; idx += 256) {
            int n = idx >> 5, k = idx & 31;
            float w = Wn[k * 128 + n];
            __half h = __float2half_rn(w);
            g_Wnh[idx] = h;
            g_Wnl[idx] = __float2half_rn(w - __half2float(h));
        }
    }
}

// ---------------- fused node embed + layer0 P1/P3 chain (+agg zero)
#define EB_AH 0
#define EB_AL 10240
#define EB_WH 20480
#define EB_WL 30720
#define EB_P  40960
#define EB_B  110592
#define EB_TOTAL 111104
#define EBST  80

__global__ void __launch_bounds__(256)
embed_p(const float* __restrict__ x, const float* __restrict__ b)
{
    extern __shared__ __align__(16) char smem[];
    const uint32_t sb = smem_u32(smem);
    const int tid = threadIdx.x;
    const int wid = tid >> 5, lane = tid & 31;
    const int nBase = blockIdx.x * 128;
    float* sB = (float*)(smem + EB_B);
    if (tid < 128) sB[tid] = b[tid];

    {
        int r = tid >> 1, u = tid & 1;
        int nrow = min(nBase + r, NN - 1);
        const float4* src = (const float4*)(x + (size_t)nrow * 32) + u * 4;
        uint32_t hi[8], lo[8];
#pragma unroll
        for (int q = 0; q < 4; q++) {
            float4 a = src[q];
            split2h(a.x, a.y, hi[2 * q], lo[2 * q]);
            split2h(a.z, a.w, hi[2 * q + 1], lo[2 * q + 1]);
        }
        uint32_t off = (uint32_t)(r * EBST + u * 32);
        *(uint4*)(smem + EB_AH + off)      = make_uint4(hi[0], hi[1], hi[2], hi[3]);
        *(uint4*)(smem + EB_AH + off + 16) = make_uint4(hi[4], hi[5], hi[6], hi[7]);
        *(uint4*)(smem + EB_AL + off)      = make_uint4(lo[0], lo[1], lo[2], lo[3]);
        *(uint4*)(smem + EB_AL + off + 16) = make_uint4(lo[4], lo[5], lo[6], lo[7]);
    }
    {
        int r = tid >> 1, u = tid & 1;
        const uint4* wh = (const uint4*)(g_Wnh + r * 32) + u * 2;
        const uint4* wl = (const uint4*)(g_Wnl + r * 32) + u * 2;
        uint32_t off = (uint32_t)(r * EBST + u * 32);
        *(uint4*)(smem + EB_WH + off)      = wh[0];
        *(uint4*)(smem + EB_WH + off + 16) = wh[1];
        *(uint4*)(smem + EB_WL + off)      = wl[0];
        *(uint4*)(smem + EB_WL + off + 16) = wl[1];
    }
    {
        const uint4* w1 = (const uint4*)g_Wp1[0];
        const uint4* w3 = (const uint4*)g_Wp3[0];
#pragma unroll
        for (int i = 0; i < 8; i++) {
            int g = tid + i * 256;
            int n = g >> 4, q = g & 15;
            *(uint4*)(smem + EB_P + n * 272 + q * 16) = w1[g];
            *(uint4*)(smem + EB_P + 34816 + n * 272 + q * 16) = w3[g];
        }
    }
    {
#pragma unroll
        for (int i = 0; i < 16; i++) {
            int g = tid + i * 256;
            int r = g >> 5, c = (g & 31) * 4;
            int row = nBase + r;
            if (row < NN)
                *(float4*)&g_agg[(size_t)row * HID + c] = make_float4(0.f, 0.f, 0.f, 0.f);
        }
    }
    __syncthreads();

    const int wm = wid * 16;
    const uint32_t aOff = (uint32_t)((wm + (lane & 7) + ((lane >> 3) & 1) * 8) * EBST
                                     + (lane >> 4) * 16);
    const uint32_t bOffW = (uint32_t)(((lane & 7) + (lane >> 4) * 8) * EBST
                                      + ((lane >> 3) & 1) * 16);
    const uint32_t bOffP = (uint32_t)(((lane & 7) + (lane >> 4) * 8) * 272
                                      + (((lane >> 3) & 1) * 8) * 2);
    const int er0 = wm + (lane >> 2);
    const int cb  = (lane & 3) * 2;
    const int row0 = nBase + er0, row1 = row0 + 8;

    float acc[16][4];
#pragma unroll
    for (int n = 0; n < 16; n++)
#pragma unroll
        for (int j = 0; j < 4; j++) acc[n][j] = 0.f;
#pragma unroll
    for (int ks = 0; ks < 2; ks++) {
        uint32_t ah0, ah1, ah2, ah3, al0, al1, al2, al3;
        ldsm4(ah0, ah1, ah2, ah3, sb + EB_AH + aOff + ks * 32);
        ldsm4(al0, al1, al2, al3, sb + EB_AL + aOff + ks * 32);
#pragma unroll
        for (int np = 0; np < 8; np++) {
            uint32_t bh0, bh1, bh2, bh3, bl0, bl1, bl2, bl3;
            ldsm4(bh0, bh1, bh2, bh3, sb + EB_WH + bOffW + np * (16 * EBST) + ks * 32);
            ldsm4(bl0, bl1, bl2, bl3, sb + EB_WL + bOffW + np * (16 * EBST) + ks * 32);
            mma16816h(acc[2 * np],     ah0, ah1, ah2, ah3, bh0, bh1);
            mma16816h(acc[2 * np],     ah0, ah1, ah2, ah3, bl0, bl1);
            mma16816h(acc[2 * np],     al0, al1, al2, al3, bh0, bh1);
            mma16816h(acc[2 * np + 1], ah0, ah1, ah2, ah3, bh2, bh3);
            mma16816h(acc[2 * np + 1], ah0, ah1, ah2, ah3, bl2, bl3);
            mma16816h(acc[2 * np + 1], al0, al1, al2, al3, bh2, bh3);
        }
    }

    uint32_t aH[8][4];
#pragma unroll
    for (int nt = 0; nt < 16; nt++) {
        int col = nt * 8 + cb;
        float b0 = sB[col], b1 = sB[col + 1];
        float v0 = fmaxf(acc[nt][0] + b0, 0.f);
        float v1 = fmaxf(acc[nt][1] + b1, 0.f);
        float v2 = fmaxf(acc[nt][2] + b0, 0.f);
        float v3 = fmaxf(acc[nt][3] + b1, 0.f);
        if (row0 < NN)
            *(float2*)&g_hn0[(size_t)row0 * HID + col] = make_float2(v0, v1);
        if (row1 < NN)
            *(float2*)&g_hn0[(size_t)row1 * HID + col] = make_float2(v2, v3);
        int ks = nt >> 1, j0 = (nt & 1) * 2;
        aH[ks][j0]     = pack2h(v0, v1);
        aH[ks][j0 + 1] = pack2h(v2, v3);
    }

#pragma unroll
    for (int o = 0; o < 2; o++) {
        const uint32_t bA = sb + EB_P + o * 34816 + bOffP;
        float q[16][4];
#pragma unroll
        for (int n = 0; n < 16; n++)
#pragma unroll
            for (int j = 0; j < 4; j++) q[n][j] = 0.f;
#pragma unroll
        for (int ks = 0; ks < 8; ks++) {
#pragma unroll
            for (int np = 0; np < 8; np++) {
                uint32_t b0, b1, b2, b3;
                ldsm4(b0, b1, b2, b3, bA + np * (16 * 272) + ks * 32);
                mma16816h(q[2 * np],     aH[ks][0], aH[ks][1], aH[ks][2], aH[ks][3], b0, b1);
                mma16816h(q[2 * np + 1], aH[ks][0], aH[ks][1], aH[ks][2], aH[ks][3], b2, b3);
            }
        }
        float* out = o ? g_P3 : g_P1;
#pragma unroll
        for (int nt = 0; nt < 16; nt++) {
            int col = nt * 8 + cb;
            if (row0 < NN)
                *(float2*)&out[(size_t)row0 * HID + col] = make_float2(q[nt][0], q[nt][1]);
            if (row1 < NN)
                *(float2*)&out[(size_t)row1 * HID + col] = make_float2(q[nt][2], q[nt][3]);
        }
    }
}

// ---------------- exact (3-product) update GEMM, split-K; chains P/Q GEMMs
#define UX_AH 0
#define UX_AL 34816
#define UX_WH 69632
#define UX_WL 104448
#define UX_B  139264
#define UX_TOTAL 139776
#define UXST 272

__global__ void __launch_bounds__(256)
upd_x(int layer, const float* __restrict__ bias)
{
    extern __shared__ __align__(16) char smem[];
    const uint32_t sb = smem_u32(smem);
    const float* __restrict__ hn   = layer ? g_hn1 : g_hn0;
    float*       __restrict__ hout = layer ? g_hn0 : g_hn1;
    const int tid = threadIdx.x;
    const int wid = tid >> 5, lane = tid & 31;
    const int nBase = blockIdx.x * 128;
    float* sB = (float*)(smem + UX_B);
    if (tid < 128) sB[tid] = bias[tid];

    const int wm = wid * 16;
    const uint32_t aOff = (uint32_t)((wm + (lane & 7) + ((lane >> 3) & 1) * 8) * UXST
                                     + (lane >> 4) * 16);
    const uint32_t bOff = (uint32_t)(((lane & 7) + (lane >> 4) * 8) * UXST
                                     + (((lane >> 3) & 1) * 8) * 2);
    const int er0 = wm + (lane >> 2);
    const int cb  = (lane & 3) * 2;
    const int row0 = nBase + er0, row1 = row0 + 8;

    float acc[16][4];
#pragma unroll
    for (int n = 0; n < 16; n++)
#pragma unroll
        for (int j = 0; j < 4; j++) acc[n][j] = 0.f;

    for (int p = 0; p < 2; p++) {
        {
            int r = tid >> 1, u = tid & 1;
            int nrow = min(nBase + r, NN - 1);
            const float4* src = (const float4*)((p ? g_agg : hn) + (size_t)nrow * HID) + u * 16;
            uint32_t da = (uint32_t)(UX_AH + r * UXST + u * 128);
            uint32_t dl = (uint32_t)(UX_AL + r * UXST + u * 128);
#pragma unroll
            for (int q = 0; q < 8; q++) {
                float4 a = src[2 * q], bv = src[2 * q + 1];
                uint32_t h0, l0, h1, l1, h2, l2, h3, l3;
                split2h(a.x, a.y, h0, l0);  split2h(a.z, a.w, h1, l1);
                split2h(bv.x, bv.y, h2, l2); split2h(bv.z, bv.w, h3, l3);
                *(uint4*)(smem + da + q * 16) = make_uint4(h0, h1, h2, h3);
                *(uint4*)(smem + dl + q * 16) = make_uint4(l0, l1, l2, l3);
            }
        }
        {
            const uint4* wh = (const uint4*)g_Wuh[layer][p];
            const uint4* wl = (const uint4*)g_Wul[layer][p];
#pragma unroll
            for (int i = 0; i < 8; i++) {
                int g = tid + i * 256;
                int n = g >> 4, q = g & 15;
                *(uint4*)(smem + UX_WH + n * UXST + q * 16) = wh[g];
                *(uint4*)(smem + UX_WL + n * UXST + q * 16) = wl[g];
            }
        }
        __syncthreads();

#pragma unroll
        for (int ks = 0; ks < 8; ks++) {
            uint32_t ah0, ah1, ah2, ah3, al0, al1, al2, al3;
            ldsm4(ah0, ah1, ah2, ah3, sb + UX_AH + aOff + ks * 32);
            ldsm4(al0, al1, al2, al3, sb + UX_AL + aOff + ks * 32);
#pragma unroll
            for (int np = 0; np < 8; np++) {
                uint32_t bh0, bh1, bh2, bh3, bl0, bl1, bl2, bl3;
                ldsm4(bh0, bh1, bh2, bh3, sb + UX_WH + bOff + np * (16 * UXST) + ks * 32);
                ldsm4(bl0, bl1, bl2, bl3, sb + UX_WL + bOff + np * (16 * UXST) + ks * 32);
                mma16816h(acc[2 * np],     ah0, ah1, ah2, ah3, bh0, bh1);
                mma16816h(acc[2 * np],     ah0, ah1, ah2, ah3, bl0, bl1);
                mma16816h(acc[2 * np],     al0, al1, al2, al3, bh0, bh1);
                mma16816h(acc[2 * np + 1], ah0, ah1, ah2, ah3, bh2, bh3);
                mma16816h(acc[2 * np + 1], ah0, ah1, ah2, ah3, bl2, bl3);
                mma16816h(acc[2 * np + 1], al0, al1, al2, al3, bh2, bh3);
            }
        }
        __syncthreads();
    }

#pragma unroll
    for (int nt = 0; nt < 16; nt++) {
        int col = nt * 8 + cb;
        float b0 = sB[col], b1 = sB[col + 1];
        acc[nt][0] = fmaxf(acc[nt][0] + b0, 0.f);
        acc[nt][1] = fmaxf(acc[nt][1] + b1, 0.f);
        acc[nt][2] = fmaxf(acc[nt][2] + b0, 0.f);
        acc[nt][3] = fmaxf(acc[nt][3] + b1, 0.f);
        if (row0 < NN)
            *(float2*)&hout[(size_t)row0 * HID + col] = make_float2(acc[nt][0], acc[nt][1]);
        if (row1 < NN)
            *(float2*)&hout[(size_t)row1 * HID + col] = make_float2(acc[nt][2], acc[nt][3]);
    }

    if (layer == 0) {
#pragma unroll
        for (int i = 0; i < 16; i++) {
            int g = tid + i * 256;
            int r = g >> 5, c = (g & 31) * 4;
            int row = nBase + r;
            if (row < NN)
                *(float4*)&g_agg[(size_t)row * HID + c] = make_float4(0.f, 0.f, 0.f, 0.f);
        }
        uint32_t aH[8][4];
#pragma unroll
        for (int nt = 0; nt < 16; nt++) {
            int ks = nt >> 1, j0 = (nt & 1) * 2;
            aH[ks][j0]     = pack2h(acc[nt][0], acc[nt][1]);
            aH[ks][j0 + 1] = pack2h(acc[nt][2], acc[nt][3]);
        }
        {
            const uint4* w1 = (const uint4*)g_Wp1[1];
            const uint4* w3 = (const uint4*)g_Wp3[1];
#pragma unroll
            for (int i = 0; i < 8; i++) {
                int g = tid + i * 256;
                int n = g >> 4, q = g & 15;
                *(uint4*)(smem + UX_AH + n * UXST + q * 16) = w1[g];
                *(uint4*)(smem + UX_WH + n * UXST + q * 16) = w3[g];
            }
        }
        __syncthreads();
#pragma unroll
        for (int o = 0; o < 2; o++) {
            const uint32_t bA = sb + (o ? UX_WH : UX_AH) + bOff;
            float q[16][4];
#pragma unroll
            for (int n = 0; n < 16; n++)
#pragma unroll
                for (int j = 0; j < 4; j++) q[n][j] = 0.f;
#pragma unroll
            for (int ks = 0; ks < 8; ks++) {
#pragma unroll
                for (int np = 0; np < 8; np++) {
                    uint32_t b0, b1, b2, b3;
                    ldsm4(b0, b1, b2, b3, bA + np * (16 * UXST) + ks * 32);
                    mma16816h(q[2 * np],     aH[ks][0], aH[ks][1], aH[ks][2], aH[ks][3], b0, b1);
                    mma16816h(q[2 * np + 1], aH[ks][0], aH[ks][1], aH[ks][2], aH[ks][3], b2, b3);
                }
            }
            float* out = o ? g_P3 : g_P1;
#pragma unroll
            for (int nt = 0; nt < 16; nt++) {
                int col = nt * 8 + cb;
                if (row0 < NN)
                    *(float2*)&out[(size_t)row0 * HID + col] = make_float2(q[nt][0], q[nt][1]);
                if (row1 < NN)
                    *(float2*)&out[(size_t)row1 * HID + col] = make_float2(q[nt][2], q[nt][3]);
            }
        }
    } else {
        uint32_t aH[8][4], aL[8][4];
#pragma unroll
        for (int nt = 0; nt < 16; nt++) {
            int ks = nt >> 1, j0 = (nt & 1) * 2;
            split2h(acc[nt][0], acc[nt][1], aH[ks][j0],     aL[ks][j0]);
            split2h(acc[nt][2], acc[nt][3], aH[ks][j0 + 1], aL[ks][j0 + 1]);
        }
        {
            const uint4* q1h = (const uint4*)g_Wq1h;
            const uint4* q1l = (const uint4*)g_Wq1l;
            const uint4* q3h = (const uint4*)g_Wq3h;
            const uint4* q3l = (const uint4*)g_Wq3l;
#pragma unroll
            for (int i = 0; i < 8; i++) {
                int g = tid + i * 256;
                int n = g >> 4, q = g & 15;
                *(uint4*)(smem + UX_AH + n * UXST + q * 16) = q1h[g];
                *(uint4*)(smem + UX_AL + n * UXST + q * 16) = q1l[g];
                *(uint4*)(smem + UX_WH + n * UXST + q * 16) = q3h[g];
                *(uint4*)(smem + UX_WL + n * UXST + q * 16) = q3l[g];
            }
        }
        __syncthreads();
#pragma unroll
        for (int o = 0; o < 2; o++) {
            const uint32_t bHA = sb + (o ? UX_WH : UX_AH) + bOff;
            const uint32_t bLA = sb + (o ? UX_WL : UX_AL) + bOff;
            float q[16][4];
#pragma unroll
            for (int n = 0; n < 16; n++)
#pragma unroll
                for (int j = 0; j < 4; j++) q[n][j] = 0.f;
#pragma unroll
            for (int ks = 0; ks < 8; ks++) {
#pragma unroll
                for (int np = 0; np < 8; np++) {
                    uint32_t bh0, bh1, bh2, bh3, bl0, bl1, bl2, bl3;
                    ldsm4(bh0, bh1, bh2, bh3, bHA + np * (16 * UXST) + ks * 32);
                    ldsm4(bl0, bl1, bl2, bl3, bLA + np * (16 * UXST) + ks * 32);
                    mma16816h(q[2 * np],     aH[ks][0], aH[ks][1], aH[ks][2], aH[ks][3], bh0, bh1);
                    mma16816h(q[2 * np],     aH[ks][0], aH[ks][1], aH[ks][2], aH[ks][3], bl0, bl1);
                    mma16816h(q[2 * np],     aL[ks][0], aL[ks][1], aL[ks][2], aL[ks][3], bh0, bh1);
                    mma16816h(q[2 * np + 1], aH[ks][0], aH[ks][1], aH[ks][2], aH[ks][3], bh2, bh3);
                    mma16816h(q[2 * np + 1], aH[ks][0], aH[ks][1], aH[ks][2], aH[ks][3], bl2, bl3);
                    mma16816h(q[2 * np + 1], aL[ks][0], aL[ks][1], aL[ks][2], aL[ks][3], bh2, bh3);
                }
            }
            float* out = o ? g_P3 : g_P1;
#pragma unroll
            for (int nt = 0; nt < 16; nt++) {
                int col = nt * 8 + cb;
                if (row0 < NN)
                    *(float2*)&out[(size_t)row0 * HID + col] = make_float2(q[nt][0], q[nt][1]);
                if (row1 < NN)
                    *(float2*)&out[(size_t)row1 * HID + col] = make_float2(q[nt][2], q[nt][3]);
            }
        }
    }
}

// ====================== pipelined fp16 MMA-chain edge kernel (M=96) =========
#define SM_BM    0
#define SM_BE    512
#define SM_IDX   1024
#define SM_WEH   2560
#define SM_EFH0  8704
#define SM_EFH1  13312
#define SM_BW    17920
#define SM_OUT   52736
#define SM_TOTAL 103424
#define TSTRIDE  272
#define EFST     48

__global__ void __launch_bounds__(192, 2)
msg_v11(int layer, const float* __restrict__ We, const float* __restrict__ be,
        const float* __restrict__ bm)
{
    extern __shared__ __align__(16) char smem[];
    const uint32_t sb = smem_u32(smem);
    const int tid = threadIdx.x;
    const int wid = tid >> 5, lane = tid & 31;

    float* sBm = (float*)(smem + SM_BM);
    float* beS = (float*)(smem + SM_BE);
    float* OUT = (float*)(smem + SM_OUT);

    if (tid < 128) {
        sBm[tid] = bm[tid]; beS[tid] = be[tid];
        int n = tid;
        uint32_t h8[8];
#pragma unroll
        for (int p = 0; p < 8; p++)
            h8[p] = pack2h(We[(2 * p) * 128 + n], We[(2 * p + 1) * 128 + n]);
        *(uint4*)(smem + SM_WEH + n * EFST)      = make_uint4(h8[0], h8[1], h8[2], h8[3]);
        *(uint4*)(smem + SM_WEH + n * EFST + 16) = make_uint4(h8[4], h8[5], h8[6], h8[7]);
    }
    {
        const uint4* wsrc = (const uint4*)g_Wh[layer];
#pragma unroll
        for (int u = 0; u < 11; u++) {
            int g = tid + u * 192;
            if (g < 2048) {
                int n = g >> 4, q = g & 15;
                *(uint4*)(smem + SM_BW + n * TSTRIDE + q * 16) = wsrc[g];
            }
        }
    }

    const int wm = wid * 16;
    const uint32_t aEfOff = (uint32_t)((wm + (lane & 7) + ((lane >> 3) & 1) * 8) * EFST
                                       + (lane >> 4) * 16);
    const uint32_t bEfOff = (uint32_t)(((lane & 7) + (lane >> 4) * 8) * EFST
                                       + ((lane >> 3) & 1) * 16);
    const uint32_t bMnOff = (uint32_t)(((lane & 7) + (lane >> 4) * 8) * TSTRIDE
                                       + (((lane >> 3) & 1) * 8) * 2);
    const uint32_t wehA = sb + SM_WEH + bEfOff;
    const uint32_t bwA  = sb + SM_BW + bMnOff;

    const int er0 = wm + (lane >> 2);
    const int cb  = (lane & 3) * 2;
    const int NT = NEP / 96;

    auto stage_async = [&](int t, int b) {
        const int eBase = t * 96;
        uint32_t efh = sb + (b ? SM_EFH1 : SM_EFH0);
        {
            int r = tid >> 1, u = tid & 1;
            cp16(efh + r * EFST + u * 16, (const char*)(g_efh + (size_t)(eBase + r) * 16) + u * 16);
        }
        if (tid < 24)
            cp16(sb + SM_IDX + b * 768 + tid * 16, (const char*)(g_srcp + eBase) + tid * 16);
        else if (tid < 48)
            cp16(sb + SM_IDX + b * 768 + 384 + (tid - 24) * 16, (const char*)(g_dstp + eBase) + (tid - 24) * 16);
    };

    int t = blockIdx.x;
    int buf = 0;
    if (t < NT) stage_async(t, 0);
    CP_COMMIT();

    for (; t < NT; t += gridDim.x, buf ^= 1) {
        CP_WAIT(0);
        __syncthreads();

        int* sSrc = (int*)(smem + SM_IDX + buf * 768);
        int* sDst = (int*)(smem + SM_IDX + buf * 768 + 384);

        {
#pragma unroll
            for (int i = 0; i < 16; i++) {
                int g = tid + i * 192;
                int r = g >> 5, c = g & 31;
                const char* src = (const char*)(g_P1 + (size_t)sSrc[r] * HID) + c * 16;
                cp16(sb + SM_OUT + r * 528 + c * 16, src);
            }
        }
        CP_COMMIT();

        int tn = t + gridDim.x;
        if (tn < NT) stage_async(tn, buf ^ 1);
        CP_COMMIT();

        const uint32_t efhA = sb + (buf ? SM_EFH1 : SM_EFH0) + aEfOff;
        float acc2[16][4];
#pragma unroll
        for (int n = 0; n < 16; n++)
#pragma unroll
            for (int j = 0; j < 4; j++) acc2[n][j] = 0.f;
        {
            uint32_t eh0, eh1, eh2, eh3;
            ldsm4(eh0, eh1, eh2, eh3, efhA);
#pragma unroll
            for (int g = 0; g < 8; g++) {
                uint32_t wh0, wh1, wh2, wh3;
                ldsm4(wh0, wh1, wh2, wh3, wehA + g * (16 * EFST));
                mma16816h(acc2[2 * g],     eh0, eh1, eh2, eh3, wh0, wh1);
                mma16816h(acc2[2 * g + 1], eh0, eh1, eh2, eh3, wh2, wh3);
            }
        }

        uint32_t aH[8][4];
#pragma unroll
        for (int nt = 0; nt < 16; nt++) {
            int col = nt * 8 + cb;
            float be0 = beS[col], be1 = beS[col + 1];
            float v0 = fmaxf(acc2[nt][0] + be0, 0.f);
            float v1 = fmaxf(acc2[nt][1] + be1, 0.f);
            float v2 = fmaxf(acc2[nt][2] + be0, 0.f);
            float v3 = fmaxf(acc2[nt][3] + be1, 0.f);
            int ks = nt >> 1, j0 = (nt & 1) * 2;
            aH[ks][j0]     = pack2h(v0, v1);
            aH[ks][j0 + 1] = pack2h(v2, v3);
        }

        float acc[16][4];
#pragma unroll
        for (int n = 0; n < 16; n++)
#pragma unroll
            for (int j = 0; j < 4; j++) acc[n][j] = 0.f;
#pragma unroll
        for (int ks = 0; ks < 8; ks++) {
#pragma unroll
            for (int np = 0; np < 8; np++) {
                uint32_t b0, b1, b2, b3;
                ldsm4(b0, b1, b2, b3, bwA + np * (16 * TSTRIDE) + ks * 32);
                mma16816h(acc[2 * np],     aH[ks][0], aH[ks][1], aH[ks][2], aH[ks][3], b0, b1);
                mma16816h(acc[2 * np + 1], aH[ks][0], aH[ks][1], aH[ks][2], aH[ks][3], b2, b3);
            }
        }

        CP_WAIT(1);
        __syncthreads();

        {
            int d0 = sDst[er0], d1 = sDst[er0 + 8];
            const float* p3a = g_P3 + (size_t)d0 * HID;
            const float* p3b = g_P3 + (size_t)d1 * HID;
            const float* p1a = &OUT[er0 * 132];
            const float* p1b = &OUT[(er0 + 8) * 132];
#pragma unroll
            for (int nt = 0; nt < 16; nt++) {
                int col = nt * 8 + cb;
                float2 q1 = *(const float2*)(p1a + col);
                float2 q3 = *(const float2*)(p3a + col);
                float2 o0;
                o0.x = fmaxf(acc[nt][0] + sBm[col]     + q1.x + q3.x, 0.f);
                o0.y = fmaxf(acc[nt][1] + sBm[col + 1] + q1.y + q3.y, 0.f);
                *(float2*)&OUT[er0 * 132 + col] = o0;
                float2 r1 = *(const float2*)(p1b + col);
                float2 r3 = *(const float2*)(p3b + col);
                float2 o1;
                o1.x = fmaxf(acc[nt][2] + sBm[col]     + r1.x + r3.x, 0.f);
                o1.y = fmaxf(acc[nt][3] + sBm[col + 1] + r1.y + r3.y, 0.f);
                *(float2*)&OUT[(er0 + 8) * 132 + col] = o1;
            }
        }
        __syncthreads();

        if (tid < 128) {
            int col = tid;
            float s = 0.f;
            int cur = sDst[0];
#pragma unroll 4
            for (int r2 = 0; r2 < 96; r2++) {
                int dn = sDst[r2];
                if (dn != cur) {
                    if (s != 0.f) atomicAdd(&g_agg[(size_t)cur * HID + col], s);
                    cur = dn; s = 0.f;
                }
                s += OUT[r2 * 132 + col];
            }
            if (s != 0.f) atomicAdd(&g_agg[(size_t)cur * HID + col], s);
        }
        __syncthreads();
    }
}

// --------------------------------------------- fused demand readout
__global__ void __launch_bounds__(256)
dem_v2(const int* __restrict__ pairs, const float* __restrict__ dfeat,
       const float* __restrict__ Wd, const float* __restrict__ br1,
       const float* __restrict__ w2, const float* __restrict__ b2,
       float* __restrict__ out)
{
    __shared__ __align__(16) float Wds[8][132];
    __shared__ float w2s[128], bs[128];
    int tid = threadIdx.x;
    if (tid < 128) { w2s[tid] = w2[tid]; bs[tid] = br1[tid]; }
    {
        int row = tid >> 5, c = (tid & 31) * 4;
        *(float4*)&Wds[row][c] = ((const float4*)Wd)[tid];
    }
    __syncthreads();

    int w = tid >> 5, lane = tid & 31;
    int d = blockIdx.x * 8 + w;
    int ds = pairs[2 * d], dd = pairs[2 * d + 1];
    int c0 = lane * 4;

    float4 q1 = *(const float4*)(g_P1 + (size_t)ds * HID + c0);
    float4 q2 = *(const float4*)(g_P3 + (size_t)dd * HID + c0);
    float s0 = bs[c0 + 0] + q1.x + q2.x;
    float s1 = bs[c0 + 1] + q1.y + q2.y;
    float s2 = bs[c0 + 2] + q1.z + q2.z;
    float s3 = bs[c0 + 3] + q1.w + q2.w;
#pragma unroll
    for (int q = 0; q < 8; q++) {
        float e = dfeat[(size_t)d * 8 + q];
        float4 wv = *(const float4*)&Wds[q][c0];
        s0 = fmaf(e, wv.x, s0); s1 = fmaf(e, wv.y, s1);
        s2 = fmaf(e, wv.z, s2); s3 = fmaf(e, wv.w, s3);
    }
    float p = fmaxf(s0, 0.f) * w2s[c0 + 0] + fmaxf(s1, 0.f) * w2s[c0 + 1]
            + fmaxf(s2, 0.f) * w2s[c0 + 2] + fmaxf(s3, 0.f) * w2s[c0 + 3];
#pragma unroll
    for (int o = 16; o > 0; o >>= 1) p += __shfl_xor_sync(0xffffffffu, p, o);
    if (lane == 0) out[d] = 1.f / (1.f + expf(-(p + b2[0])));
}

// ---------------------------------------------------------------- launch
extern "C" void kernel_launch(void* const* d_in, const int* in_sizes, int n_in,
                              void* d_out, int out_size)
{
    const float* node_feats = (const float*)d_in[0];
    const float* edge_feats = (const float*)d_in[1];
    const float* dem_feats  = (const float*)d_in[2];
    const int*   eidx       = (const int*)d_in[3];
    const int*   pairs      = (const int*)d_in[4];
    const float* W_node = (const float*)d_in[5];
    const float* b_node = (const float*)d_in[6];
    const float* W_edge = (const float*)d_in[7];
    const float* b_edge = (const float*)d_in[8];
    const float* W_msg0 = (const float*)d_in[9];
    const float* b_msg0 = (const float*)d_in[10];
    const float* W_upd0 = (const float*)d_in[11];
    const float* b_upd0 = (const float*)d_in[12];
    const float* W_msg1 = (const float*)d_in[13];
    const float* b_msg1 = (const float*)d_in[14];
    const float* W_upd1 = (const float*)d_in[15];
    const float* b_upd1 = (const float*)d_in[16];
    const float* W_r1   = (const float*)d_in[17];
    const float* b_r1   = (const float*)d_in[18];
    const float* W_r2   = (const float*)d_in[19];
    const float* b_r2   = (const float*)d_in[20];
    float* out = (float*)d_out;

    const int nTiles = (NN + 127) / 128;

    cudaFuncSetAttribute(msg_v11, cudaFuncAttributeMaxDynamicSharedMemorySize, SM_TOTAL);
    cudaFuncSetAttribute(embed_p, cudaFuncAttributeMaxDynamicSharedMemorySize, EB_TOTAL);
    cudaFuncSetAttribute(upd_x,   cudaFuncAttributeMaxDynamicSharedMemorySize, UX_TOTAL);

    // ---- fork a side stream for the node-side prologue (capture-safe pattern)
    cudaStream_t s2;
    cudaStreamCreateWithFlags(&s2, cudaStreamNonBlocking);
    cudaEvent_t evFork, evJoin;
    cudaEventCreateWithFlags(&evFork, cudaEventDisableTiming);
    cudaEventCreateWithFlags(&evJoin, cudaEventDisableTiming);

    cudaEventRecord(evFork, 0);
    cudaStreamWaitEvent(s2, evFork, 0);

    // stream s2: weight prep + fused embed/P-chain (+agg zero)
    prep_all<<<13, 256, 0, s2>>>(W_msg0, W_msg1, W_upd0, W_upd1, W_r1, W_node);
    embed_p<<<nTiles, 256, EB_TOTAL, s2>>>(node_feats, b_node);
    cudaEventRecord(evJoin, s2);

    // main stream: edge sort chain (+pads folded into scatter)
    zcnt<<<(NN + 256) / 256, 256>>>();
    hist<<<NE / 256, 256>>>(eidx);
    scan20k<<<1, 1024>>>();
    scatter<<<NE / 256, 256>>>(eidx, edge_feats);

    // join before the GNN layers
    cudaStreamWaitEvent(0, evJoin, 0);

    // ---- layer 0
    msg_v11<<<304, 192, SM_TOTAL>>>(0, W_edge, b_edge, b_msg0);
    upd_x<<<nTiles, 256, UX_TOTAL>>>(0, b_upd0);   // chains layer-1 P1/P3 + agg zero

    // ---- layer 1
    msg_v11<<<304, 192, SM_TOTAL>>>(1, W_edge, b_edge, b_msg1);
    upd_x<<<nTiles, 256, UX_TOTAL>>>(1, b_upd1);   // chains readout Q1/Q3

    // ---- readout
    dem_v2<<<ND / 8, 256>>>(pairs, dem_feats, W_r1 + 256 * HID, b_r1, W_r2, b_r2, out);

    cudaEventDestroy(evFork);
    cudaEventDestroy(evJoin);
    cudaStreamDestroy(s2);
}

// round 15
// speedup vs baseline: 1.2016x; 1.0864x over previous
#include <cuda_runtime.h>
#include <cuda_fp16.h>
#include <math.h>
#include <stdint.h>

#define HID 128
#define NN 20000
#define NE 640000
#define NEP 640032
#define ND 100000

// scratch (device globals: allocation-free contract)
__device__ float g_hn0[(size_t)NN * HID];
__device__ float g_hn1[(size_t)NN * HID];
__device__ float g_agg[(size_t)(NN + 1) * HID];
__device__ __align__(16) __half g_P1[(size_t)NN * HID];         // fp16 layer P-values
__device__ __align__(16) __half g_P3[(size_t)(NN + 1) * HID];   // sentinel row stays 0
__device__ float g_Q1[(size_t)NN * HID];   // fp32 readout values
__device__ float g_Q3[(size_t)NN * HID];
// fp16 weight images, [n][k] row-major
__device__ __align__(16) __half g_Wh [2][128 * 128];
__device__ __align__(16) __half g_Wp1[2][128 * 128];
__device__ __align__(16) __half g_Wp3[2][128 * 128];
__device__ __align__(16) __half g_Wuh[2][2][128 * 128];
__device__ __align__(16) __half g_Wul[2][2][128 * 128];
__device__ __align__(16) __half g_Wq1h[128 * 128];
__device__ __align__(16) __half g_Wq1l[128 * 128];
__device__ __align__(16) __half g_Wq3h[128 * 128];
__device__ __align__(16) __half g_Wq3l[128 * 128];
__device__ __align__(16) __half g_Wnh[128 * 32];
__device__ __align__(16) __half g_Wnl[128 * 32];
// edge sort-by-dst (+ pre-permuted fp16 edge features), padded
__device__ int g_cnt[NN + 1];
__device__ int g_srcp[NEP];
__device__ int g_dstp[NEP];
__device__ __align__(16) __half g_efh[(size_t)NEP * 16];

// ======================= helpers =======================
__device__ __forceinline__ uint32_t smem_u32(const void* p) {
    uint32_t a;
    asm("{ .reg .u64 t; cvta.to.shared.u64 t, %1; cvt.u32.u64 %0, t; }" : "=r"(a) : "l"(p));
    return a;
}
__device__ __forceinline__ void ldsm4(uint32_t& r0, uint32_t& r1, uint32_t& r2, uint32_t& r3,
                                      uint32_t addr) {
    asm volatile("ldmatrix.sync.aligned.m8n8.x4.shared.b16 {%0,%1,%2,%3}, [%4];"
                 : "=r"(r0), "=r"(r1), "=r"(r2), "=r"(r3) : "r"(addr));
}
__device__ __forceinline__ void mma16816h(float* c, uint32_t a0, uint32_t a1, uint32_t a2,
                                          uint32_t a3, uint32_t b0, uint32_t b1) {
    asm volatile("mma.sync.aligned.m16n8k16.row.col.f32.f16.f16.f32 "
                 "{%0,%1,%2,%3}, {%4,%5,%6,%7}, {%8,%9}, {%0,%1,%2,%3};"
                 : "+f"(c[0]), "+f"(c[1]), "+f"(c[2]), "+f"(c[3])
                 : "r"(a0), "r"(a1), "r"(a2), "r"(a3), "r"(b0), "r"(b1));
}
__device__ __forceinline__ uint32_t pack2h(float v0, float v1) {
    __half h0 = __float2half_rn(v0);
    __half h1 = __float2half_rn(v1);
    return (uint32_t)__half_as_ushort(h0) | ((uint32_t)__half_as_ushort(h1) << 16);
}
__device__ __forceinline__ void split2h(float v0, float v1, uint32_t& hi, uint32_t& lo) {
    __half h0 = __float2half_rn(v0);
    __half h1 = __float2half_rn(v1);
    __half m0 = __float2half_rn(v0 - __half2float(h0));
    __half m1 = __float2half_rn(v1 - __half2float(h1));
    hi = (uint32_t)__half_as_ushort(h0) | ((uint32_t)__half_as_ushort(h1) << 16);
    lo = (uint32_t)__half_as_ushort(m0) | ((uint32_t)__half_as_ushort(m1) << 16);
}
__device__ __forceinline__ void cp16(uint32_t smem_dst, const void* gsrc) {
    asm volatile("cp.async.cg.shared.global [%0], [%1], 16;"
                 :: "r"(smem_dst), "l"(gsrc) : "memory");
}
#define CP_COMMIT()  asm volatile("cp.async.commit_group;" ::: "memory")
#define CP_WAIT(N)   asm volatile("cp.async.wait_group %0;" :: "n"(N) : "memory")

// ---------------------------------------------------------------- sort by dst
__global__ void zcnt()
{
    int i = blockIdx.x * 256 + threadIdx.x;
    if (i <= NN) g_cnt[i] = 0;
}
__global__ void hist(const int* __restrict__ eidx)
{
    int e = blockIdx.x * 256 + threadIdx.x;
    atomicAdd(&g_cnt[eidx[NE + e]], 1);
}
__global__ void scan20k()
{
    __shared__ int part[1024];
    __shared__ int wsum[32];
    const int tid = threadIdx.x;
    const int CH = 20;
    int base = tid * CH;
    int loc[CH];
    int s = 0;
#pragma unroll
    for (int i = 0; i < CH; i++) {
        int v = (base + i <= NN) ? g_cnt[base + i] : 0;
        loc[i] = s; s += v;
    }
    part[tid] = s;
    __syncthreads();
    int lane = tid & 31, w = tid >> 5;
    int v = part[tid];
#pragma unroll
    for (int o = 1; o < 32; o <<= 1) { int t = __shfl_up_sync(~0u, v, o); if (lane >= o) v += t; }
    if (lane == 31) wsum[w] = v;
    __syncthreads();
    if (w == 0) {
        int x = wsum[lane];
#pragma unroll
        for (int o = 1; o < 32; o <<= 1) { int t = __shfl_up_sync(~0u, x, o); if (lane >= o) x += t; }
        wsum[lane] = x;
    }
    __syncthreads();
    int excl = v - part[tid] + (w ? wsum[w - 1] : 0);
#pragma unroll
    for (int i = 0; i < CH; i++)
        if (base + i <= NN) g_cnt[base + i] = excl + loc[i];
}
__global__ void scatter(const int* __restrict__ eidx, const float* __restrict__ ef)
{
    if (blockIdx.x == 0 && threadIdx.x < 32) {
        int i = threadIdx.x;
        g_srcp[NE + i] = 0;
        g_dstp[NE + i] = NN;
        uint4 z = make_uint4(0, 0, 0, 0);
        uint4* dh = (uint4*)(g_efh + (size_t)(NE + i) * 16);
        dh[0] = z; dh[1] = z;
    }
    int e = blockIdx.x * 256 + threadIdx.x;
    int s = eidx[e], d = eidx[NE + e];
    int p = atomicAdd(&g_cnt[d], 1);
    g_srcp[p] = s; g_dstp[p] = d;
    const float4* eg = (const float4*)(ef + (size_t)e * 16);
    float4 v0 = eg[0], v1 = eg[1], v2 = eg[2], v3 = eg[3];
    uint4* dh = (uint4*)(g_efh + (size_t)p * 16);
    dh[0] = make_uint4(pack2h(v0.x, v0.y), pack2h(v0.z, v0.w),
                       pack2h(v1.x, v1.y), pack2h(v1.z, v1.w));
    dh[1] = make_uint4(pack2h(v2.x, v2.y), pack2h(v2.z, v2.w),
                       pack2h(v3.x, v3.y), pack2h(v3.z, v3.w));
}

// ------------------------------ weight prep: fp16 [n][k] images
__global__ void prep_all(const float* __restrict__ Wm0, const float* __restrict__ Wm1,
                         const float* __restrict__ Wu0, const float* __restrict__ Wu1,
                         const float* __restrict__ Wr1, const float* __restrict__ Wn)
{
    int b = blockIdx.x;
    if (b < 6) {
        const float* src; __half* dst;
        switch (b) {
            case 0: src = Wm0 + 128 * 128; dst = g_Wh[0];  break;
            case 1: src = Wm1 + 128 * 128; dst = g_Wh[1];  break;
            case 2: src = Wm0;             dst = g_Wp1[0]; break;
            case 3: src = Wm1;             dst = g_Wp1[1]; break;
            case 4: src = Wm0 + 256 * 128; dst = g_Wp3[0]; break;
            default: src = Wm1 + 256 * 128; dst = g_Wp3[1]; break;
        }
        for (int idx = threadIdx.x; idx < 128 * 128; idx += 256) {
            int n = idx >> 7, k = idx & 127;
            dst[idx] = __float2half_rn(src[k * 128 + n]);
        }
    } else if (b < 10) {
        int l = (b - 6) >> 1, p = (b - 6) & 1;
        const float* src = (l ? Wu1 : Wu0) + p * 128 * 128;
        __half* dh = g_Wuh[l][p];
        __half* dl = g_Wul[l][p];
        for (int idx = threadIdx.x; idx < 128 * 128; idx += 256) {
            int n = idx >> 7, k = idx & 127;
            float w = src[k * 128 + n];
            __half h = __float2half_rn(w);
            dh[idx] = h;
            dl[idx] = __float2half_rn(w - __half2float(h));
        }
    } else if (b < 12) {
        const float* src = (b == 10) ? Wr1 : (Wr1 + 128 * 128);
        __half* dh = (b == 10) ? g_Wq1h : g_Wq3h;
        __half* dl = (b == 10) ? g_Wq1l : g_Wq3l;
        for (int idx = threadIdx.x; idx < 128 * 128; idx += 256) {
            int n = idx >> 7, k = idx & 127;
            float w = src[k * 128 + n];
            __half h = __float2half_rn(w);
            dh[idx] = h;
            dl[idx] = __float2half_rn(w - __half2float(h));
        }
    } else {
        for (int idx = threadIdx.x; idx < 128 * 32; idx += 256) {
            int n = idx >> 5, k = idx & 31;
            float w = Wn[k * 128 + n];
            __half h = __float2half_rn(w);
            g_Wnh[idx] = h;
            g_Wnl[idx] = __float2half_rn(w - __half2float(h));
        }
    }
}

// ---------------- fused node embed + layer0 P1/P3 chain (+agg zero)
#define EB_AH 0
#define EB_AL 10240
#define EB_WH 20480
#define EB_WL 30720
#define EB_P  40960
#define EB_B  110592
#define EB_TOTAL 111104
#define EBST  80

__global__ void __launch_bounds__(256)
embed_p(const float* __restrict__ x, const float* __restrict__ b)
{
    extern __shared__ __align__(16) char smem[];
    const uint32_t sb = smem_u32(smem);
    const int tid = threadIdx.x;
    const int wid = tid >> 5, lane = tid & 31;
    const int nBase = blockIdx.x * 128;
    float* sB = (float*)(smem + EB_B);
    if (tid < 128) sB[tid] = b[tid];

    {
        int r = tid >> 1, u = tid & 1;
        int nrow = min(nBase + r, NN - 1);
        const float4* src = (const float4*)(x + (size_t)nrow * 32) + u * 4;
        uint32_t hi[8], lo[8];
#pragma unroll
        for (int q = 0; q < 4; q++) {
            float4 a = src[q];
            split2h(a.x, a.y, hi[2 * q], lo[2 * q]);
            split2h(a.z, a.w, hi[2 * q + 1], lo[2 * q + 1]);
        }
        uint32_t off = (uint32_t)(r * EBST + u * 32);
        *(uint4*)(smem + EB_AH + off)      = make_uint4(hi[0], hi[1], hi[2], hi[3]);
        *(uint4*)(smem + EB_AH + off + 16) = make_uint4(hi[4], hi[5], hi[6], hi[7]);
        *(uint4*)(smem + EB_AL + off)      = make_uint4(lo[0], lo[1], lo[2], lo[3]);
        *(uint4*)(smem + EB_AL + off + 16) = make_uint4(lo[4], lo[5], lo[6], lo[7]);
    }
    {
        int r = tid >> 1, u = tid & 1;
        const uint4* wh = (const uint4*)(g_Wnh + r * 32) + u * 2;
        const uint4* wl = (const uint4*)(g_Wnl + r * 32) + u * 2;
        uint32_t off = (uint32_t)(r * EBST + u * 32);
        *(uint4*)(smem + EB_WH + off)      = wh[0];
        *(uint4*)(smem + EB_WH + off + 16) = wh[1];
        *(uint4*)(smem + EB_WL + off)      = wl[0];
        *(uint4*)(smem + EB_WL + off + 16) = wl[1];
    }
    {
        const uint4* w1 = (const uint4*)g_Wp1[0];
        const uint4* w3 = (const uint4*)g_Wp3[0];
#pragma unroll
        for (int i = 0; i < 8; i++) {
            int g = tid + i * 256;
            int n = g >> 4, q = g & 15;
            *(uint4*)(smem + EB_P + n * 272 + q * 16) = w1[g];
            *(uint4*)(smem + EB_P + 34816 + n * 272 + q * 16) = w3[g];
        }
    }
    {
#pragma unroll
        for (int i = 0; i < 16; i++) {
            int g = tid + i * 256;
            int r = g >> 5, c = (g & 31) * 4;
            int row = nBase + r;
            if (row < NN)
                *(float4*)&g_agg[(size_t)row * HID + c] = make_float4(0.f, 0.f, 0.f, 0.f);
        }
    }
    __syncthreads();

    const int wm = wid * 16;
    const uint32_t aOff = (uint32_t)((wm + (lane & 7) + ((lane >> 3) & 1) * 8) * EBST
                                     + (lane >> 4) * 16);
    const uint32_t bOffW = (uint32_t)(((lane & 7) + (lane >> 4) * 8) * EBST
                                      + ((lane >> 3) & 1) * 16);
    const uint32_t bOffP = (uint32_t)(((lane & 7) + (lane >> 4) * 8) * 272
                                      + (((lane >> 3) & 1) * 8) * 2);
    const int er0 = wm + (lane >> 2);
    const int cb  = (lane & 3) * 2;
    const int row0 = nBase + er0, row1 = row0 + 8;

    float acc[16][4];
#pragma unroll
    for (int n = 0; n < 16; n++)
#pragma unroll
        for (int j = 0; j < 4; j++) acc[n][j] = 0.f;
#pragma unroll
    for (int ks = 0; ks < 2; ks++) {
        uint32_t ah0, ah1, ah2, ah3, al0, al1, al2, al3;
        ldsm4(ah0, ah1, ah2, ah3, sb + EB_AH + aOff + ks * 32);
        ldsm4(al0, al1, al2, al3, sb + EB_AL + aOff + ks * 32);
#pragma unroll
        for (int np = 0; np < 8; np++) {
            uint32_t bh0, bh1, bh2, bh3, bl0, bl1, bl2, bl3;
            ldsm4(bh0, bh1, bh2, bh3, sb + EB_WH + bOffW + np * (16 * EBST) + ks * 32);
            ldsm4(bl0, bl1, bl2, bl3, sb + EB_WL + bOffW + np * (16 * EBST) + ks * 32);
            mma16816h(acc[2 * np],     ah0, ah1, ah2, ah3, bh0, bh1);
            mma16816h(acc[2 * np],     ah0, ah1, ah2, ah3, bl0, bl1);
            mma16816h(acc[2 * np],     al0, al1, al2, al3, bh0, bh1);
            mma16816h(acc[2 * np + 1], ah0, ah1, ah2, ah3, bh2, bh3);
            mma16816h(acc[2 * np + 1], ah0, ah1, ah2, ah3, bl2, bl3);
            mma16816h(acc[2 * np + 1], al0, al1, al2, al3, bh2, bh3);
        }
    }

    uint32_t aH[8][4];
#pragma unroll
    for (int nt = 0; nt < 16; nt++) {
        int col = nt * 8 + cb;
        float b0 = sB[col], b1 = sB[col + 1];
        float v0 = fmaxf(acc[nt][0] + b0, 0.f);
        float v1 = fmaxf(acc[nt][1] + b1, 0.f);
        float v2 = fmaxf(acc[nt][2] + b0, 0.f);
        float v3 = fmaxf(acc[nt][3] + b1, 0.f);
        if (row0 < NN)
            *(float2*)&g_hn0[(size_t)row0 * HID + col] = make_float2(v0, v1);
        if (row1 < NN)
            *(float2*)&g_hn0[(size_t)row1 * HID + col] = make_float2(v2, v3);
        int ks = nt >> 1, j0 = (nt & 1) * 2;
        aH[ks][j0]     = pack2h(v0, v1);
        aH[ks][j0 + 1] = pack2h(v2, v3);
    }

#pragma unroll
    for (int o = 0; o < 2; o++) {
        const uint32_t bA = sb + EB_P + o * 34816 + bOffP;
        float q[16][4];
#pragma unroll
        for (int n = 0; n < 16; n++)
#pragma unroll
            for (int j = 0; j < 4; j++) q[n][j] = 0.f;
#pragma unroll
        for (int ks = 0; ks < 8; ks++) {
#pragma unroll
            for (int np = 0; np < 8; np++) {
                uint32_t b0, b1, b2, b3;
                ldsm4(b0, b1, b2, b3, bA + np * (16 * 272) + ks * 32);
                mma16816h(q[2 * np],     aH[ks][0], aH[ks][1], aH[ks][2], aH[ks][3], b0, b1);
                mma16816h(q[2 * np + 1], aH[ks][0], aH[ks][1], aH[ks][2], aH[ks][3], b2, b3);
            }
        }
        __half* out = o ? g_P3 : g_P1;
#pragma unroll
        for (int nt = 0; nt < 16; nt++) {
            int col = nt * 8 + cb;
            if (row0 < NN)
                *(uint32_t*)&out[(size_t)row0 * HID + col] = pack2h(q[nt][0], q[nt][1]);
            if (row1 < NN)
                *(uint32_t*)&out[(size_t)row1 * HID + col] = pack2h(q[nt][2], q[nt][3]);
        }
    }
}

// ---------------- exact (3-product) update GEMM, split-K; chains P/Q GEMMs
#define UX_AH 0
#define UX_AL 34816
#define UX_WH 69632
#define UX_WL 104448
#define UX_B  139264
#define UX_TOTAL 139776
#define UXST 272

__global__ void __launch_bounds__(256)
upd_x(int layer, const float* __restrict__ bias)
{
    extern __shared__ __align__(16) char smem[];
    const uint32_t sb = smem_u32(smem);
    const float* __restrict__ hn   = layer ? g_hn1 : g_hn0;
    float*       __restrict__ hout = layer ? g_hn0 : g_hn1;
    const int tid = threadIdx.x;
    const int wid = tid >> 5, lane = tid & 31;
    const int nBase = blockIdx.x * 128;
    float* sB = (float*)(smem + UX_B);
    if (tid < 128) sB[tid] = bias[tid];

    const int wm = wid * 16;
    const uint32_t aOff = (uint32_t)((wm + (lane & 7) + ((lane >> 3) & 1) * 8) * UXST
                                     + (lane >> 4) * 16);
    const uint32_t bOff = (uint32_t)(((lane & 7) + (lane >> 4) * 8) * UXST
                                     + (((lane >> 3) & 1) * 8) * 2);
    const int er0 = wm + (lane >> 2);
    const int cb  = (lane & 3) * 2;
    const int row0 = nBase + er0, row1 = row0 + 8;

    float acc[16][4];
#pragma unroll
    for (int n = 0; n < 16; n++)
#pragma unroll
        for (int j = 0; j < 4; j++) acc[n][j] = 0.f;

    for (int p = 0; p < 2; p++) {
        {
            int r = tid >> 1, u = tid & 1;
            int nrow = min(nBase + r, NN - 1);
            const float4* src = (const float4*)((p ? g_agg : hn) + (size_t)nrow * HID) + u * 16;
            uint32_t da = (uint32_t)(UX_AH + r * UXST + u * 128);
            uint32_t dl = (uint32_t)(UX_AL + r * UXST + u * 128);
#pragma unroll
            for (int q = 0; q < 8; q++) {
                float4 a = src[2 * q], bv = src[2 * q + 1];
                uint32_t h0, l0, h1, l1, h2, l2, h3, l3;
                split2h(a.x, a.y, h0, l0);  split2h(a.z, a.w, h1, l1);
                split2h(bv.x, bv.y, h2, l2); split2h(bv.z, bv.w, h3, l3);
                *(uint4*)(smem + da + q * 16) = make_uint4(h0, h1, h2, h3);
                *(uint4*)(smem + dl + q * 16) = make_uint4(l0, l1, l2, l3);
            }
        }
        {
            const uint4* wh = (const uint4*)g_Wuh[layer][p];
            const uint4* wl = (const uint4*)g_Wul[layer][p];
#pragma unroll
            for (int i = 0; i < 8; i++) {
                int g = tid + i * 256;
                int n = g >> 4, q = g & 15;
                *(uint4*)(smem + UX_WH + n * UXST + q * 16) = wh[g];
                *(uint4*)(smem + UX_WL + n * UXST + q * 16) = wl[g];
            }
        }
        __syncthreads();

#pragma unroll
        for (int ks = 0; ks < 8; ks++) {
            uint32_t ah0, ah1, ah2, ah3, al0, al1, al2, al3;
            ldsm4(ah0, ah1, ah2, ah3, sb + UX_AH + aOff + ks * 32);
            ldsm4(al0, al1, al2, al3, sb + UX_AL + aOff + ks * 32);
#pragma unroll
            for (int np = 0; np < 8; np++) {
                uint32_t bh0, bh1, bh2, bh3, bl0, bl1, bl2, bl3;
                ldsm4(bh0, bh1, bh2, bh3, sb + UX_WH + bOff + np * (16 * UXST) + ks * 32);
                ldsm4(bl0, bl1, bl2, bl3, sb + UX_WL + bOff + np * (16 * UXST) + ks * 32);
                mma16816h(acc[2 * np],     ah0, ah1, ah2, ah3, bh0, bh1);
                mma16816h(acc[2 * np],     ah0, ah1, ah2, ah3, bl0, bl1);
                mma16816h(acc[2 * np],     al0, al1, al2, al3, bh0, bh1);
                mma16816h(acc[2 * np + 1], ah0, ah1, ah2, ah3, bh2, bh3);
                mma16816h(acc[2 * np + 1], ah0, ah1, ah2, ah3, bl2, bl3);
                mma16816h(acc[2 * np + 1], al0, al1, al2, al3, bh2, bh3);
            }
        }
        __syncthreads();
    }

#pragma unroll
    for (int nt = 0; nt < 16; nt++) {
        int col = nt * 8 + cb;
        float b0 = sB[col], b1 = sB[col + 1];
        acc[nt][0] = fmaxf(acc[nt][0] + b0, 0.f);
        acc[nt][1] = fmaxf(acc[nt][1] + b1, 0.f);
        acc[nt][2] = fmaxf(acc[nt][2] + b0, 0.f);
        acc[nt][3] = fmaxf(acc[nt][3] + b1, 0.f);
        if (row0 < NN)
            *(float2*)&hout[(size_t)row0 * HID + col] = make_float2(acc[nt][0], acc[nt][1]);
        if (row1 < NN)
            *(float2*)&hout[(size_t)row1 * HID + col] = make_float2(acc[nt][2], acc[nt][3]);
    }

    if (layer == 0) {
#pragma unroll
        for (int i = 0; i < 16; i++) {
            int g = tid + i * 256;
            int r = g >> 5, c = (g & 31) * 4;
            int row = nBase + r;
            if (row < NN)
                *(float4*)&g_agg[(size_t)row * HID + c] = make_float4(0.f, 0.f, 0.f, 0.f);
        }
        uint32_t aH[8][4];
#pragma unroll
        for (int nt = 0; nt < 16; nt++) {
            int ks = nt >> 1, j0 = (nt & 1) * 2;
            aH[ks][j0]     = pack2h(acc[nt][0], acc[nt][1]);
            aH[ks][j0 + 1] = pack2h(acc[nt][2], acc[nt][3]);
        }
        {
            const uint4* w1 = (const uint4*)g_Wp1[1];
            const uint4* w3 = (const uint4*)g_Wp3[1];
#pragma unroll
            for (int i = 0; i < 8; i++) {
                int g = tid + i * 256;
                int n = g >> 4, q = g & 15;
                *(uint4*)(smem + UX_AH + n * UXST + q * 16) = w1[g];
                *(uint4*)(smem + UX_WH + n * UXST + q * 16) = w3[g];
            }
        }
        __syncthreads();
#pragma unroll
        for (int o = 0; o < 2; o++) {
            const uint32_t bA = sb + (o ? UX_WH : UX_AH) + bOff;
            float q[16][4];
#pragma unroll
            for (int n = 0; n < 16; n++)
#pragma unroll
                for (int j = 0; j < 4; j++) q[n][j] = 0.f;
#pragma unroll
            for (int ks = 0; ks < 8; ks++) {
#pragma unroll
                for (int np = 0; np < 8; np++) {
                    uint32_t b0, b1, b2, b3;
                    ldsm4(b0, b1, b2, b3, bA + np * (16 * UXST) + ks * 32);
                    mma16816h(q[2 * np],     aH[ks][0], aH[ks][1], aH[ks][2], aH[ks][3], b0, b1);
                    mma16816h(q[2 * np + 1], aH[ks][0], aH[ks][1], aH[ks][2], aH[ks][3], b2, b3);
                }
            }
            __half* out = o ? g_P3 : g_P1;
#pragma unroll
            for (int nt = 0; nt < 16; nt++) {
                int col = nt * 8 + cb;
                if (row0 < NN)
                    *(uint32_t*)&out[(size_t)row0 * HID + col] = pack2h(q[nt][0], q[nt][1]);
                if (row1 < NN)
                    *(uint32_t*)&out[(size_t)row1 * HID + col] = pack2h(q[nt][2], q[nt][3]);
            }
        }
    } else {
        uint32_t aH[8][4], aL[8][4];
#pragma unroll
        for (int nt = 0; nt < 16; nt++) {
            int ks = nt >> 1, j0 = (nt & 1) * 2;
            split2h(acc[nt][0], acc[nt][1], aH[ks][j0],     aL[ks][j0]);
            split2h(acc[nt][2], acc[nt][3], aH[ks][j0 + 1], aL[ks][j0 + 1]);
        }
        {
            const uint4* q1h = (const uint4*)g_Wq1h;
            const uint4* q1l = (const uint4*)g_Wq1l;
            const uint4* q3h = (const uint4*)g_Wq3h;
            const uint4* q3l = (const uint4*)g_Wq3l;
#pragma unroll
            for (int i = 0; i < 8; i++) {
                int g = tid + i * 256;
                int n = g >> 4, q = g & 15;
                *(uint4*)(smem + UX_AH + n * UXST + q * 16) = q1h[g];
                *(uint4*)(smem + UX_AL + n * UXST + q * 16) = q1l[g];
                *(uint4*)(smem + UX_WH + n * UXST + q * 16) = q3h[g];
                *(uint4*)(smem + UX_WL + n * UXST + q * 16) = q3l[g];
            }
        }
        __syncthreads();
#pragma unroll
        for (int o = 0; o < 2; o++) {
            const uint32_t bHA = sb + (o ? UX_WH : UX_AH) + bOff;
            const uint32_t bLA = sb + (o ? UX_WL : UX_AL) + bOff;
            float q[16][4];
#pragma unroll
            for (int n = 0; n < 16; n++)
#pragma unroll
                for (int j = 0; j < 4; j++) q[n][j] = 0.f;
#pragma unroll
            for (int ks = 0; ks < 8; ks++) {
#pragma unroll
                for (int np = 0; np < 8; np++) {
                    uint32_t bh0, bh1, bh2, bh3, bl0, bl1, bl2, bl3;
                    ldsm4(bh0, bh1, bh2, bh3, bHA + np * (16 * UXST) + ks * 32);
                    ldsm4(bl0, bl1, bl2, bl3, bLA + np * (16 * UXST) + ks * 32);
                    mma16816h(q[2 * np],     aH[ks][0], aH[ks][1], aH[ks][2], aH[ks][3], bh0, bh1);
                    mma16816h(q[2 * np],     aH[ks][0], aH[ks][1], aH[ks][2], aH[ks][3], bl0, bl1);
                    mma16816h(q[2 * np],     aL[ks][0], aL[ks][1], aL[ks][2], aL[ks][3], bh0, bh1);
                    mma16816h(q[2 * np + 1], aH[ks][0], aH[ks][1], aH[ks][2], aH[ks][3], bh2, bh3);
                    mma16816h(q[2 * np + 1], aH[ks][0], aH[ks][1], aH[ks][2], aH[ks][3], bl2, bl3);
                    mma16816h(q[2 * np + 1], aL[ks][0], aL[ks][1], aL[ks][2], aL[ks][3], bh2, bh3);
                }
            }
            float* out = o ? g_Q3 : g_Q1;
#pragma unroll
            for (int nt = 0; nt < 16; nt++) {
                int col = nt * 8 + cb;
                if (row0 < NN)
                    *(float2*)&out[(size_t)row0 * HID + col] = make_float2(q[nt][0], q[nt][1]);
                if (row1 < NN)
                    *(float2*)&out[(size_t)row1 * HID + col] = make_float2(q[nt][2], q[nt][3]);
            }
        }
    }
}

// ====================== pipelined fp16 MMA-chain edge kernel (M=128) ========
// 256 threads (8 warps), 2 CTAs/SM -> 4 warps/SMSP; OUT/P1 buffer fp16
#define SM_BM    0
#define SM_BE    512
#define SM_IDX   1024            // 2 bufs x (src 512 + dst 512)
#define SM_WEH   3072            // fp16 [128][24]
#define SM_EFH0  9216            // fp16 [128][24] x2
#define SM_EFH1  15360
#define SM_BW    21504           // fp16 [128][136]
#define SM_OUT   56320           // fp16 [128][136] — doubles as P1 buffer
#define SM_TOTAL 91136
#define TSTRIDE  272
#define EFST     48

__global__ void __launch_bounds__(256, 2)
msg_v12(int layer, const float* __restrict__ We, const float* __restrict__ be,
        const float* __restrict__ bm)
{
    extern __shared__ __align__(16) char smem[];
    const uint32_t sb = smem_u32(smem);
    const int tid = threadIdx.x;
    const int wid = tid >> 5, lane = tid & 31;

    float* sBm = (float*)(smem + SM_BM);
    float* beS = (float*)(smem + SM_BE);
    __half* OUT = (__half*)(smem + SM_OUT);  // [128][136]

    if (tid < 128) {
        sBm[tid] = bm[tid]; beS[tid] = be[tid];
        int n = tid;
        uint32_t h8[8];
#pragma unroll
        for (int p = 0; p < 8; p++)
            h8[p] = pack2h(We[(2 * p) * 128 + n], We[(2 * p + 1) * 128 + n]);
        *(uint4*)(smem + SM_WEH + n * EFST)      = make_uint4(h8[0], h8[1], h8[2], h8[3]);
        *(uint4*)(smem + SM_WEH + n * EFST + 16) = make_uint4(h8[4], h8[5], h8[6], h8[7]);
    }
    {
        const uint4* wsrc = (const uint4*)g_Wh[layer];
#pragma unroll
        for (int u = 0; u < 8; u++) {
            int g = tid + u * 256;
            int n = g >> 4, q = g & 15;
            *(uint4*)(smem + SM_BW + n * TSTRIDE + q * 16) = wsrc[g];
        }
    }

    const int wm = wid * 16;                 // 0..112
    const uint32_t aEfOff = (uint32_t)((wm + (lane & 7) + ((lane >> 3) & 1) * 8) * EFST
                                       + (lane >> 4) * 16);
    const uint32_t bEfOff = (uint32_t)(((lane & 7) + (lane >> 4) * 8) * EFST
                                       + ((lane >> 3) & 1) * 16);
    const uint32_t bMnOff = (uint32_t)(((lane & 7) + (lane >> 4) * 8) * TSTRIDE
                                       + (((lane >> 3) & 1) * 8) * 2);
    const uint32_t wehA = sb + SM_WEH + bEfOff;
    const uint32_t bwA  = sb + SM_BW + bMnOff;

    const int er0 = wm + (lane >> 2);        // rows er0, er0+8 (0..127)
    const int cb  = (lane & 3) * 2;
    const int NT = NE / 128;                 // 5000

    auto stage_async = [&](int t, int b) {
        const int eBase = t * 128;
        uint32_t efh = sb + (b ? SM_EFH1 : SM_EFH0);
        {
            int r = tid >> 1, u = tid & 1;   // rows 0..127
            cp16(efh + r * EFST + u * 16, (const char*)(g_efh + (size_t)(eBase + r) * 16) + u * 16);
        }
        if (tid < 32)
            cp16(sb + SM_IDX + b * 1024 + tid * 16, (const char*)(g_srcp + eBase) + tid * 16);
        else if (tid < 64)
            cp16(sb + SM_IDX + b * 1024 + 512 + (tid - 32) * 16, (const char*)(g_dstp + eBase) + (tid - 32) * 16);
    };

    int t = blockIdx.x;
    int buf = 0;
    if (t < NT) stage_async(t, 0);
    CP_COMMIT();

    for (; t < NT; t += gridDim.x, buf ^= 1) {
        CP_WAIT(0);
        __syncthreads();

        int* sSrc = (int*)(smem + SM_IDX + buf * 1024);
        int* sDst = (int*)(smem + SM_IDX + buf * 1024 + 512);

        // ---- P1 (fp16) gather prefetch into OUT buffer: 128 rows x 16 chunks
        {
#pragma unroll
            for (int i = 0; i < 8; i++) {
                int g = tid + i * 256;
                int r = g >> 4, c = g & 15;
                const char* src = (const char*)(g_P1 + (size_t)sSrc[r] * HID) + c * 16;
                cp16(sb + SM_OUT + r * TSTRIDE + c * 16, src);
            }
        }
        CP_COMMIT();

        int tn = t + gridDim.x;
        if (tn < NT) stage_async(tn, buf ^ 1);
        CP_COMMIT();

        // ---- he GEMM (K=16, single fp16 product)
        const uint32_t efhA = sb + (buf ? SM_EFH1 : SM_EFH0) + aEfOff;
        float acc2[16][4];
#pragma unroll
        for (int n = 0; n < 16; n++)
#pragma unroll
            for (int j = 0; j < 4; j++) acc2[n][j] = 0.f;
        {
            uint32_t eh0, eh1, eh2, eh3;
            ldsm4(eh0, eh1, eh2, eh3, efhA);
#pragma unroll
            for (int g = 0; g < 8; g++) {
                uint32_t wh0, wh1, wh2, wh3;
                ldsm4(wh0, wh1, wh2, wh3, wehA + g * (16 * EFST));
                mma16816h(acc2[2 * g],     eh0, eh1, eh2, eh3, wh0, wh1);
                mma16816h(acc2[2 * g + 1], eh0, eh1, eh2, eh3, wh2, wh3);
            }
        }

        // ---- bias + relu + fp16 round -> main-GEMM A fragments
        uint32_t aH[8][4];
#pragma unroll
        for (int nt = 0; nt < 16; nt++) {
            int col = nt * 8 + cb;
            float be0 = beS[col], be1 = beS[col + 1];
            float v0 = fmaxf(acc2[nt][0] + be0, 0.f);
            float v1 = fmaxf(acc2[nt][1] + be1, 0.f);
            float v2 = fmaxf(acc2[nt][2] + be0, 0.f);
            float v3 = fmaxf(acc2[nt][3] + be1, 0.f);
            int ks = nt >> 1, j0 = (nt & 1) * 2;
            aH[ks][j0]     = pack2h(v0, v1);
            aH[ks][j0 + 1] = pack2h(v2, v3);
        }

        // ---- main GEMM: D = Ah*W
        float acc[16][4];
#pragma unroll
        for (int n = 0; n < 16; n++)
#pragma unroll
            for (int j = 0; j < 4; j++) acc[n][j] = 0.f;
#pragma unroll
        for (int ks = 0; ks < 8; ks++) {
#pragma unroll
            for (int np = 0; np < 8; np++) {
                uint32_t b0, b1, b2, b3;
                ldsm4(b0, b1, b2, b3, bwA + np * (16 * TSTRIDE) + ks * 32);
                mma16816h(acc[2 * np],     aH[ks][0], aH[ks][1], aH[ks][2], aH[ks][3], b0, b1);
                mma16816h(acc[2 * np + 1], aH[ks][0], aH[ks][1], aH[ks][2], aH[ks][3], b2, b3);
            }
        }

        CP_WAIT(1);
        __syncthreads();

        // ---- epilogue: P1 from smem (fp16), P3 from global (fp16), write OUT fp16
        {
            int d0 = sDst[er0], d1 = sDst[er0 + 8];
            const __half* p3a = g_P3 + (size_t)d0 * HID;
            const __half* p3b = g_P3 + (size_t)d1 * HID;
            const __half* p1a = OUT + er0 * 136;
            const __half* p1b = OUT + (er0 + 8) * 136;
#pragma unroll
            for (int nt = 0; nt < 16; nt++) {
                int col = nt * 8 + cb;
                float2 q1 = __half22float2(*(const __half2*)(p1a + col));
                float2 q3 = __half22float2(*(const __half2*)(p3a + col));
                float o0 = fmaxf(acc[nt][0] + sBm[col]     + q1.x + q3.x, 0.f);
                float o1 = fmaxf(acc[nt][1] + sBm[col + 1] + q1.y + q3.y, 0.f);
                *(uint32_t*)(OUT + er0 * 136 + col) = pack2h(o0, o1);
                float2 r1 = __half22float2(*(const __half2*)(p1b + col));
                float2 r3 = __half22float2(*(const __half2*)(p3b + col));
                float o2 = fmaxf(acc[nt][2] + sBm[col]     + r1.x + r3.x, 0.f);
                float o3 = fmaxf(acc[nt][3] + sBm[col + 1] + r1.y + r3.y, 0.f);
                *(uint32_t*)(OUT + (er0 + 8) * 136 + col) = pack2h(o2, o3);
            }
        }
        __syncthreads();

        // ---- segmented reduction (dst-sorted): threads 0..127, 128 rows
        if (tid < 128) {
            int col = tid;
            float s = 0.f;
            int cur = sDst[0];
#pragma unroll 4
            for (int r2 = 0; r2 < 128; r2++) {
                int dn = sDst[r2];
                if (dn != cur) {
                    if (s != 0.f) atomicAdd(&g_agg[(size_t)cur * HID + col], s);
                    cur = dn; s = 0.f;
                }
                s += __half2float(OUT[r2 * 136 + col]);
            }
            if (s != 0.f) atomicAdd(&g_agg[(size_t)cur * HID + col], s);
        }
        __syncthreads();
    }
}

// --------------------------------------------- fused demand readout
__global__ void __launch_bounds__(256)
dem_v2(const int* __restrict__ pairs, const float* __restrict__ dfeat,
       const float* __restrict__ Wd, const float* __restrict__ br1,
       const float* __restrict__ w2, const float* __restrict__ b2,
       float* __restrict__ out)
{
    __shared__ __align__(16) float Wds[8][132];
    __shared__ float w2s[128], bs[128];
    int tid = threadIdx.x;
    if (tid < 128) { w2s[tid] = w2[tid]; bs[tid] = br1[tid]; }
    {
        int row = tid >> 5, c = (tid & 31) * 4;
        *(float4*)&Wds[row][c] = ((const float4*)Wd)[tid];
    }
    __syncthreads();

    int w = tid >> 5, lane = tid & 31;
    int d = blockIdx.x * 8 + w;
    int ds = pairs[2 * d], dd = pairs[2 * d + 1];
    int c0 = lane * 4;

    float4 q1 = *(const float4*)(g_Q1 + (size_t)ds * HID + c0);
    float4 q2 = *(const float4*)(g_Q3 + (size_t)dd * HID + c0);
    float s0 = bs[c0 + 0] + q1.x + q2.x;
    float s1 = bs[c0 + 1] + q1.y + q2.y;
    float s2 = bs[c0 + 2] + q1.z + q2.z;
    float s3 = bs[c0 + 3] + q1.w + q2.w;
#pragma unroll
    for (int q = 0; q < 8; q++) {
        float e = dfeat[(size_t)d * 8 + q];
        float4 wv = *(const float4*)&Wds[q][c0];
        s0 = fmaf(e, wv.x, s0); s1 = fmaf(e, wv.y, s1);
        s2 = fmaf(e, wv.z, s2); s3 = fmaf(e, wv.w, s3);
    }
    float p = fmaxf(s0, 0.f) * w2s[c0 + 0] + fmaxf(s1, 0.f) * w2s[c0 + 1]
            + fmaxf(s2, 0.f) * w2s[c0 + 2] + fmaxf(s3, 0.f) * w2s[c0 + 3];
#pragma unroll
    for (int o = 16; o > 0; o >>= 1) p += __shfl_xor_sync(0xffffffffu, p, o);
    if (lane == 0) out[d] = 1.f / (1.f + expf(-(p + b2[0])));
}

// ---------------------------------------------------------------- launch
extern "C" void kernel_launch(void* const* d_in, const int* in_sizes, int n_in,
                              void* d_out, int out_size)
{
    const float* node_feats = (const float*)d_in[0];
    const float* edge_feats = (const float*)d_in[1];
    const float* dem_feats  = (const float*)d_in[2];
    const int*   eidx       = (const int*)d_in[3];
    const int*   pairs      = (const int*)d_in[4];
    const float* W_node = (const float*)d_in[5];
    const float* b_node = (const float*)d_in[6];
    const float* W_edge = (const float*)d_in[7];
    const float* b_edge = (const float*)d_in[8];
    const float* W_msg0 = (const float*)d_in[9];
    const float* b_msg0 = (const float*)d_in[10];
    const float* W_upd0 = (const float*)d_in[11];
    const float* b_upd0 = (const float*)d_in[12];
    const float* W_msg1 = (const float*)d_in[13];
    const float* b_msg1 = (const float*)d_in[14];
    const float* W_upd1 = (const float*)d_in[15];
    const float* b_upd1 = (const float*)d_in[16];
    const float* W_r1   = (const float*)d_in[17];
    const float* b_r1   = (const float*)d_in[18];
    const float* W_r2   = (const float*)d_in[19];
    const float* b_r2   = (const float*)d_in[20];
    float* out = (float*)d_out;

    const int nTiles = (NN + 127) / 128;

    cudaFuncSetAttribute(msg_v12, cudaFuncAttributeMaxDynamicSharedMemorySize, SM_TOTAL);
    cudaFuncSetAttribute(embed_p, cudaFuncAttributeMaxDynamicSharedMemorySize, EB_TOTAL);
    cudaFuncSetAttribute(upd_x,   cudaFuncAttributeMaxDynamicSharedMemorySize, UX_TOTAL);

    // ---- fork a side stream for the node-side prologue
    cudaStream_t s2;
    cudaStreamCreateWithFlags(&s2, cudaStreamNonBlocking);
    cudaEvent_t evFork, evJoin;
    cudaEventCreateWithFlags(&evFork, cudaEventDisableTiming);
    cudaEventCreateWithFlags(&evJoin, cudaEventDisableTiming);

    cudaEventRecord(evFork, 0);
    cudaStreamWaitEvent(s2, evFork, 0);

    prep_all<<<13, 256, 0, s2>>>(W_msg0, W_msg1, W_upd0, W_upd1, W_r1, W_node);
    embed_p<<<nTiles, 256, EB_TOTAL, s2>>>(node_feats, b_node);
    cudaEventRecord(evJoin, s2);

    zcnt<<<(NN + 256) / 256, 256>>>();
    hist<<<NE / 256, 256>>>(eidx);
    scan20k<<<1, 1024>>>();
    scatter<<<NE / 256, 256>>>(eidx, edge_feats);

    cudaStreamWaitEvent(0, evJoin, 0);

    // ---- layer 0
    msg_v12<<<304, 256, SM_TOTAL>>>(0, W_edge, b_edge, b_msg0);
    upd_x<<<nTiles, 256, UX_TOTAL>>>(0, b_upd0);   // chains layer-1 P1/P3 + agg zero

    // ---- layer 1
    msg_v12<<<304, 256, SM_TOTAL>>>(1, W_edge, b_edge, b_msg1);
    upd_x<<<nTiles, 256, UX_TOTAL>>>(1, b_upd1);   // chains readout Q1/Q3 (fp32)

    // ---- readout
    dem_v2<<<ND / 8, 256>>>(pairs, dem_feats, W_r1 + 256 * HID, b_r1, W_r2, b_r2, out);

    cudaEventDestroy(evFork);
    cudaEventDestroy(evJoin);
    cudaStreamDestroy(s2);
}

// round 16
// speedup vs baseline: 1.2686x; 1.0557x over previous
#include <cuda_runtime.h>
#include <cuda_fp16.h>
#include <math.h>
#include <stdint.h>

#define HID 128
#define NN 20000
#define NE 640000
#define NEP 640032
#define ND 100000

// scratch (device globals: allocation-free contract)
__device__ float g_hn0[(size_t)NN * HID];
__device__ float g_hn1[(size_t)NN * HID];
__device__ float g_agg[(size_t)(NN + 1) * HID];
__device__ __align__(16) __half g_P1[(size_t)NN * HID];
__device__ __align__(16) __half g_P3[(size_t)(NN + 1) * HID];   // sentinel row stays 0
__device__ float g_Q1[(size_t)NN * HID];
__device__ float g_Q3[(size_t)NN * HID];
// fp16 weight images, [n][k] row-major
__device__ __align__(16) __half g_Wh [2][128 * 128];
__device__ __align__(16) __half g_Wp1[2][128 * 128];
__device__ __align__(16) __half g_Wp3[2][128 * 128];
__device__ __align__(16) __half g_Wuh[2][2][128 * 128];
__device__ __align__(16) __half g_Wul[2][2][128 * 128];
__device__ __align__(16) __half g_Wq1h[128 * 128];
__device__ __align__(16) __half g_Wq1l[128 * 128];
__device__ __align__(16) __half g_Wq3h[128 * 128];
__device__ __align__(16) __half g_Wq3l[128 * 128];
__device__ __align__(16) __half g_Wnh[128 * 32];
__device__ __align__(16) __half g_Wnl[128 * 32];
// edge sort-by-dst (+ pre-permuted fp16 edge features), padded
__device__ int g_cnt[NN + 1];
__device__ int g_srcp[NEP];
__device__ int g_dstp[NEP];
__device__ __align__(16) __half g_efh[(size_t)NEP * 16];

// ======================= helpers =======================
__device__ __forceinline__ uint32_t smem_u32(const void* p) {
    uint32_t a;
    asm("{ .reg .u64 t; cvta.to.shared.u64 t, %1; cvt.u32.u64 %0, t; }" : "=r"(a) : "l"(p));
    return a;
}
__device__ __forceinline__ void ldsm4(uint32_t& r0, uint32_t& r1, uint32_t& r2, uint32_t& r3,
                                      uint32_t addr) {
    asm volatile("ldmatrix.sync.aligned.m8n8.x4.shared.b16 {%0,%1,%2,%3}, [%4];"
                 : "=r"(r0), "=r"(r1), "=r"(r2), "=r"(r3) : "r"(addr));
}
__device__ __forceinline__ void mma16816h(float* c, uint32_t a0, uint32_t a1, uint32_t a2,
                                          uint32_t a3, uint32_t b0, uint32_t b1) {
    asm volatile("mma.sync.aligned.m16n8k16.row.col.f32.f16.f16.f32 "
                 "{%0,%1,%2,%3}, {%4,%5,%6,%7}, {%8,%9}, {%0,%1,%2,%3};"
                 : "+f"(c[0]), "+f"(c[1]), "+f"(c[2]), "+f"(c[3])
                 : "r"(a0), "r"(a1), "r"(a2), "r"(a3), "r"(b0), "r"(b1));
}
__device__ __forceinline__ uint32_t pack2h(float v0, float v1) {
    __half h0 = __float2half_rn(v0);
    __half h1 = __float2half_rn(v1);
    return (uint32_t)__half_as_ushort(h0) | ((uint32_t)__half_as_ushort(h1) << 16);
}
__device__ __forceinline__ void split2h(float v0, float v1, uint32_t& hi, uint32_t& lo) {
    __half h0 = __float2half_rn(v0);
    __half h1 = __float2half_rn(v1);
    __half m0 = __float2half_rn(v0 - __half2float(h0));
    __half m1 = __float2half_rn(v1 - __half2float(h1));
    hi = (uint32_t)__half_as_ushort(h0) | ((uint32_t)__half_as_ushort(h1) << 16);
    lo = (uint32_t)__half_as_ushort(m0) | ((uint32_t)__half_as_ushort(m1) << 16);
}
__device__ __forceinline__ void cp16(uint32_t smem_dst, const void* gsrc) {
    asm volatile("cp.async.cg.shared.global [%0], [%1], 16;"
                 :: "r"(smem_dst), "l"(gsrc) : "memory");
}
#define CP_COMMIT()  asm volatile("cp.async.commit_group;" ::: "memory")
#define CP_WAIT(N)   asm volatile("cp.async.wait_group %0;" :: "n"(N) : "memory")

// ---------------------------------------------------------------- sort by dst
__global__ void zcnt()
{
    int i = blockIdx.x * 256 + threadIdx.x;
    if (i <= NN) g_cnt[i] = 0;
}
__global__ void hist(const int* __restrict__ eidx)
{
    int e = blockIdx.x * 256 + threadIdx.x;
    atomicAdd(&g_cnt[eidx[NE + e]], 1);
}
__global__ void scan20k()
{
    __shared__ int part[1024];
    __shared__ int wsum[32];
    const int tid = threadIdx.x;
    const int CH = 20;
    int base = tid * CH;
    int loc[CH];
    int s = 0;
#pragma unroll
    for (int i = 0; i < CH; i++) {
        int v = (base + i <= NN) ? g_cnt[base + i] : 0;
        loc[i] = s; s += v;
    }
    part[tid] = s;
    __syncthreads();
    int lane = tid & 31, w = tid >> 5;
    int v = part[tid];
#pragma unroll
    for (int o = 1; o < 32; o <<= 1) { int t = __shfl_up_sync(~0u, v, o); if (lane >= o) v += t; }
    if (lane == 31) wsum[w] = v;
    __syncthreads();
    if (w == 0) {
        int x = wsum[lane];
#pragma unroll
        for (int o = 1; o < 32; o <<= 1) { int t = __shfl_up_sync(~0u, x, o); if (lane >= o) x += t; }
        wsum[lane] = x;
    }
    __syncthreads();
    int excl = v - part[tid] + (w ? wsum[w - 1] : 0);
#pragma unroll
    for (int i = 0; i < CH; i++)
        if (base + i <= NN) g_cnt[base + i] = excl + loc[i];
}
__global__ void scatter(const int* __restrict__ eidx, const float* __restrict__ ef)
{
    if (blockIdx.x == 0 && threadIdx.x < 32) {
        int i = threadIdx.x;
        g_srcp[NE + i] = 0;
        g_dstp[NE + i] = NN;
        uint4 z = make_uint4(0, 0, 0, 0);
        uint4* dh = (uint4*)(g_efh + (size_t)(NE + i) * 16);
        dh[0] = z; dh[1] = z;
    }
    int e = blockIdx.x * 256 + threadIdx.x;
    int s = eidx[e], d = eidx[NE + e];
    int p = atomicAdd(&g_cnt[d], 1);
    g_srcp[p] = s; g_dstp[p] = d;
    const float4* eg = (const float4*)(ef + (size_t)e * 16);
    float4 v0 = eg[0], v1 = eg[1], v2 = eg[2], v3 = eg[3];
    uint4* dh = (uint4*)(g_efh + (size_t)p * 16);
    dh[0] = make_uint4(pack2h(v0.x, v0.y), pack2h(v0.z, v0.w),
                       pack2h(v1.x, v1.y), pack2h(v1.z, v1.w));
    dh[1] = make_uint4(pack2h(v2.x, v2.y), pack2h(v2.z, v2.w),
                       pack2h(v3.x, v3.y), pack2h(v3.z, v3.w));
}

// ------------------------------ weight prep: fp16 [n][k] images
__global__ void prep_all(const float* __restrict__ Wm0, const float* __restrict__ Wm1,
                         const float* __restrict__ Wu0, const float* __restrict__ Wu1,
                         const float* __restrict__ Wr1, const float* __restrict__ Wn)
{
    int b = blockIdx.x;
    if (b < 6) {
        const float* src; __half* dst;
        switch (b) {
            case 0: src = Wm0 + 128 * 128; dst = g_Wh[0];  break;
            case 1: src = Wm1 + 128 * 128; dst = g_Wh[1];  break;
            case 2: src = Wm0;             dst = g_Wp1[0]; break;
            case 3: src = Wm1;             dst = g_Wp1[1]; break;
            case 4: src = Wm0 + 256 * 128; dst = g_Wp3[0]; break;
            default: src = Wm1 + 256 * 128; dst = g_Wp3[1]; break;
        }
        for (int idx = threadIdx.x; idx < 128 * 128; idx += 256) {
            int n = idx >> 7, k = idx & 127;
            dst[idx] = __float2half_rn(src[k * 128 + n]);
        }
    } else if (b < 10) {
        int l = (b - 6) >> 1, p = (b - 6) & 1;
        const float* src = (l ? Wu1 : Wu0) + p * 128 * 128;
        __half* dh = g_Wuh[l][p];
        __half* dl = g_Wul[l][p];
        for (int idx = threadIdx.x; idx < 128 * 128; idx += 256) {
            int n = idx >> 7, k = idx & 127;
            float w = src[k * 128 + n];
            __half h = __float2half_rn(w);
            dh[idx] = h;
            dl[idx] = __float2half_rn(w - __half2float(h));
        }
    } else if (b < 12) {
        const float* src = (b == 10) ? Wr1 : (Wr1 + 128 * 128);
        __half* dh = (b == 10) ? g_Wq1h : g_Wq3h;
        __half* dl = (b == 10) ? g_Wq1l : g_Wq3l;
        for (int idx = threadIdx.x; idx < 128 * 128; idx += 256) {
            int n = idx >> 7, k = idx & 127;
            float w = src[k * 128 + n];
            __half h = __float2half_rn(w);
            dh[idx] = h;
            dl[idx] = __float2half_rn(w - __half2float(h));
        }
    } else {
        for (int idx = threadIdx.x; idx < 128 * 32; idx += 256) {
            int n = idx >> 5, k = idx & 31;
            float w = Wn[k * 128 + n];
            __half h = __float2half_rn(w);
            g_Wnh[idx] = h;
            g_Wnl[idx] = __float2half_rn(w - __half2float(h));
        }
    }
}

// ---------------- fused node embed + layer0 P1/P3 chain (+agg zero)
#define EB_AH 0
#define EB_AL 10240
#define EB_WH 20480
#define EB_WL 30720
#define EB_P  40960
#define EB_B  110592
#define EB_TOTAL 111104
#define EBST  80

__global__ void __launch_bounds__(256)
embed_p(const float* __restrict__ x, const float* __restrict__ b)
{
    extern __shared__ __align__(16) char smem[];
    const uint32_t sb = smem_u32(smem);
    const int tid = threadIdx.x;
    const int wid = tid >> 5, lane = tid & 31;
    const int nBase = blockIdx.x * 128;
    float* sB = (float*)(smem + EB_B);
    if (tid < 128) sB[tid] = b[tid];

    {
        int r = tid >> 1, u = tid & 1;
        int nrow = min(nBase + r, NN - 1);
        const float4* src = (const float4*)(x + (size_t)nrow * 32) + u * 4;
        uint32_t hi[8], lo[8];
#pragma unroll
        for (int q = 0; q < 4; q++) {
            float4 a = src[q];
            split2h(a.x, a.y, hi[2 * q], lo[2 * q]);
            split2h(a.z, a.w, hi[2 * q + 1], lo[2 * q + 1]);
        }
        uint32_t off = (uint32_t)(r * EBST + u * 32);
        *(uint4*)(smem + EB_AH + off)      = make_uint4(hi[0], hi[1], hi[2], hi[3]);
        *(uint4*)(smem + EB_AH + off + 16) = make_uint4(hi[4], hi[5], hi[6], hi[7]);
        *(uint4*)(smem + EB_AL + off)      = make_uint4(lo[0], lo[1], lo[2], lo[3]);
        *(uint4*)(smem + EB_AL + off + 16) = make_uint4(lo[4], lo[5], lo[6], lo[7]);
    }
    {
        int r = tid >> 1, u = tid & 1;
        const uint4* wh = (const uint4*)(g_Wnh + r * 32) + u * 2;
        const uint4* wl = (const uint4*)(g_Wnl + r * 32) + u * 2;
        uint32_t off = (uint32_t)(r * EBST + u * 32);
        *(uint4*)(smem + EB_WH + off)      = wh[0];
        *(uint4*)(smem + EB_WH + off + 16) = wh[1];
        *(uint4*)(smem + EB_WL + off)      = wl[0];
        *(uint4*)(smem + EB_WL + off + 16) = wl[1];
    }
    {
        const uint4* w1 = (const uint4*)g_Wp1[0];
        const uint4* w3 = (const uint4*)g_Wp3[0];
#pragma unroll
        for (int i = 0; i < 8; i++) {
            int g = tid + i * 256;
            int n = g >> 4, q = g & 15;
            *(uint4*)(smem + EB_P + n * 272 + q * 16) = w1[g];
            *(uint4*)(smem + EB_P + 34816 + n * 272 + q * 16) = w3[g];
        }
    }
    {
#pragma unroll
        for (int i = 0; i < 16; i++) {
            int g = tid + i * 256;
            int r = g >> 5, c = (g & 31) * 4;
            int row = nBase + r;
            if (row < NN)
                *(float4*)&g_agg[(size_t)row * HID + c] = make_float4(0.f, 0.f, 0.f, 0.f);
        }
    }
    __syncthreads();

    const int wm = wid * 16;
    const uint32_t aOff = (uint32_t)((wm + (lane & 7) + ((lane >> 3) & 1) * 8) * EBST
                                     + (lane >> 4) * 16);
    const uint32_t bOffW = (uint32_t)(((lane & 7) + (lane >> 4) * 8) * EBST
                                      + ((lane >> 3) & 1) * 16);
    const uint32_t bOffP = (uint32_t)(((lane & 7) + (lane >> 4) * 8) * 272
                                      + (((lane >> 3) & 1) * 8) * 2);
    const int er0 = wm + (lane >> 2);
    const int cb  = (lane & 3) * 2;
    const int row0 = nBase + er0, row1 = row0 + 8;

    float acc[16][4];
#pragma unroll
    for (int n = 0; n < 16; n++)
#pragma unroll
        for (int j = 0; j < 4; j++) acc[n][j] = 0.f;
#pragma unroll
    for (int ks = 0; ks < 2; ks++) {
        uint32_t ah0, ah1, ah2, ah3, al0, al1, al2, al3;
        ldsm4(ah0, ah1, ah2, ah3, sb + EB_AH + aOff + ks * 32);
        ldsm4(al0, al1, al2, al3, sb + EB_AL + aOff + ks * 32);
#pragma unroll
        for (int np = 0; np < 8; np++) {
            uint32_t bh0, bh1, bh2, bh3, bl0, bl1, bl2, bl3;
            ldsm4(bh0, bh1, bh2, bh3, sb + EB_WH + bOffW + np * (16 * EBST) + ks * 32);
            ldsm4(bl0, bl1, bl2, bl3, sb + EB_WL + bOffW + np * (16 * EBST) + ks * 32);
            mma16816h(acc[2 * np],     ah0, ah1, ah2, ah3, bh0, bh1);
            mma16816h(acc[2 * np],     ah0, ah1, ah2, ah3, bl0, bl1);
            mma16816h(acc[2 * np],     al0, al1, al2, al3, bh0, bh1);
            mma16816h(acc[2 * np + 1], ah0, ah1, ah2, ah3, bh2, bh3);
            mma16816h(acc[2 * np + 1], ah0, ah1, ah2, ah3, bl2, bl3);
            mma16816h(acc[2 * np + 1], al0, al1, al2, al3, bh2, bh3);
        }
    }

    uint32_t aH[8][4];
#pragma unroll
    for (int nt = 0; nt < 16; nt++) {
        int col = nt * 8 + cb;
        float b0 = sB[col], b1 = sB[col + 1];
        float v0 = fmaxf(acc[nt][0] + b0, 0.f);
        float v1 = fmaxf(acc[nt][1] + b1, 0.f);
        float v2 = fmaxf(acc[nt][2] + b0, 0.f);
        float v3 = fmaxf(acc[nt][3] + b1, 0.f);
        if (row0 < NN)
            *(float2*)&g_hn0[(size_t)row0 * HID + col] = make_float2(v0, v1);
        if (row1 < NN)
            *(float2*)&g_hn0[(size_t)row1 * HID + col] = make_float2(v2, v3);
        int ks = nt >> 1, j0 = (nt & 1) * 2;
        aH[ks][j0]     = pack2h(v0, v1);
        aH[ks][j0 + 1] = pack2h(v2, v3);
    }

#pragma unroll
    for (int o = 0; o < 2; o++) {
        const uint32_t bA = sb + EB_P + o * 34816 + bOffP;
        float q[16][4];
#pragma unroll
        for (int n = 0; n < 16; n++)
#pragma unroll
            for (int j = 0; j < 4; j++) q[n][j] = 0.f;
#pragma unroll
        for (int ks = 0; ks < 8; ks++) {
#pragma unroll
            for (int np = 0; np < 8; np++) {
                uint32_t b0, b1, b2, b3;
                ldsm4(b0, b1, b2, b3, bA + np * (16 * 272) + ks * 32);
                mma16816h(q[2 * np],     aH[ks][0], aH[ks][1], aH[ks][2], aH[ks][3], b0, b1);
                mma16816h(q[2 * np + 1], aH[ks][0], aH[ks][1], aH[ks][2], aH[ks][3], b2, b3);
            }
        }
        __half* out = o ? g_P3 : g_P1;
#pragma unroll
        for (int nt = 0; nt < 16; nt++) {
            int col = nt * 8 + cb;
            if (row0 < NN)
                *(uint32_t*)&out[(size_t)row0 * HID + col] = pack2h(q[nt][0], q[nt][1]);
            if (row1 < NN)
                *(uint32_t*)&out[(size_t)row1 * HID + col] = pack2h(q[nt][2], q[nt][3]);
        }
    }
}

// ---------------- exact (3-product) update GEMM, split-K; chains P/Q GEMMs
#define UX_AH 0
#define UX_AL 34816
#define UX_WH 69632
#define UX_WL 104448
#define UX_B  139264
#define UX_TOTAL 139776
#define UXST 272

__global__ void __launch_bounds__(256)
upd_x(int layer, const float* __restrict__ bias)
{
    extern __shared__ __align__(16) char smem[];
    const uint32_t sb = smem_u32(smem);
    const float* __restrict__ hn   = layer ? g_hn1 : g_hn0;
    float*       __restrict__ hout = layer ? g_hn0 : g_hn1;
    const int tid = threadIdx.x;
    const int wid = tid >> 5, lane = tid & 31;
    const int nBase = blockIdx.x * 128;
    float* sB = (float*)(smem + UX_B);
    if (tid < 128) sB[tid] = bias[tid];

    const int wm = wid * 16;
    const uint32_t aOff = (uint32_t)((wm + (lane & 7) + ((lane >> 3) & 1) * 8) * UXST
                                     + (lane >> 4) * 16);
    const uint32_t bOff = (uint32_t)(((lane & 7) + (lane >> 4) * 8) * UXST
                                     + (((lane >> 3) & 1) * 8) * 2);
    const int er0 = wm + (lane >> 2);
    const int cb  = (lane & 3) * 2;
    const int row0 = nBase + er0, row1 = row0 + 8;

    float acc[16][4];
#pragma unroll
    for (int n = 0; n < 16; n++)
#pragma unroll
        for (int j = 0; j < 4; j++) acc[n][j] = 0.f;

    for (int p = 0; p < 2; p++) {
        {
            int r = tid >> 1, u = tid & 1;
            int nrow = min(nBase + r, NN - 1);
            const float4* src = (const float4*)((p ? g_agg : hn) + (size_t)nrow * HID) + u * 16;
            uint32_t da = (uint32_t)(UX_AH + r * UXST + u * 128);
            uint32_t dl = (uint32_t)(UX_AL + r * UXST + u * 128);
#pragma unroll
            for (int q = 0; q < 8; q++) {
                float4 a = src[2 * q], bv = src[2 * q + 1];
                uint32_t h0, l0, h1, l1, h2, l2, h3, l3;
                split2h(a.x, a.y, h0, l0);  split2h(a.z, a.w, h1, l1);
                split2h(bv.x, bv.y, h2, l2); split2h(bv.z, bv.w, h3, l3);
                *(uint4*)(smem + da + q * 16) = make_uint4(h0, h1, h2, h3);
                *(uint4*)(smem + dl + q * 16) = make_uint4(l0, l1, l2, l3);
            }
        }
        {
            const uint4* wh = (const uint4*)g_Wuh[layer][p];
            const uint4* wl = (const uint4*)g_Wul[layer][p];
#pragma unroll
            for (int i = 0; i < 8; i++) {
                int g = tid + i * 256;
                int n = g >> 4, q = g & 15;
                *(uint4*)(smem + UX_WH + n * UXST + q * 16) = wh[g];
                *(uint4*)(smem + UX_WL + n * UXST + q * 16) = wl[g];
            }
        }
        __syncthreads();

#pragma unroll
        for (int ks = 0; ks < 8; ks++) {
            uint32_t ah0, ah1, ah2, ah3, al0, al1, al2, al3;
            ldsm4(ah0, ah1, ah2, ah3, sb + UX_AH + aOff + ks * 32);
            ldsm4(al0, al1, al2, al3, sb + UX_AL + aOff + ks * 32);
#pragma unroll
            for (int np = 0; np < 8; np++) {
                uint32_t bh0, bh1, bh2, bh3, bl0, bl1, bl2, bl3;
                ldsm4(bh0, bh1, bh2, bh3, sb + UX_WH + bOff + np * (16 * UXST) + ks * 32);
                ldsm4(bl0, bl1, bl2, bl3, sb + UX_WL + bOff + np * (16 * UXST) + ks * 32);
                mma16816h(acc[2 * np],     ah0, ah1, ah2, ah3, bh0, bh1);
                mma16816h(acc[2 * np],     ah0, ah1, ah2, ah3, bl0, bl1);
                mma16816h(acc[2 * np],     al0, al1, al2, al3, bh0, bh1);
                mma16816h(acc[2 * np + 1], ah0, ah1, ah2, ah3, bh2, bh3);
                mma16816h(acc[2 * np + 1], ah0, ah1, ah2, ah3, bl2, bl3);
                mma16816h(acc[2 * np + 1], al0, al1, al2, al3, bh2, bh3);
            }
        }
        __syncthreads();
    }

#pragma unroll
    for (int nt = 0; nt < 16; nt++) {
        int col = nt * 8 + cb;
        float b0 = sB[col], b1 = sB[col + 1];
        acc[nt][0] = fmaxf(acc[nt][0] + b0, 0.f);
        acc[nt][1] = fmaxf(acc[nt][1] + b1, 0.f);
        acc[nt][2] = fmaxf(acc[nt][2] + b0, 0.f);
        acc[nt][3] = fmaxf(acc[nt][3] + b1, 0.f);
        if (row0 < NN)
            *(float2*)&hout[(size_t)row0 * HID + col] = make_float2(acc[nt][0], acc[nt][1]);
        if (row1 < NN)
            *(float2*)&hout[(size_t)row1 * HID + col] = make_float2(acc[nt][2], acc[nt][3]);
    }

    if (layer == 0) {
#pragma unroll
        for (int i = 0; i < 16; i++) {
            int g = tid + i * 256;
            int r = g >> 5, c = (g & 31) * 4;
            int row = nBase + r;
            if (row < NN)
                *(float4*)&g_agg[(size_t)row * HID + c] = make_float4(0.f, 0.f, 0.f, 0.f);
        }
        uint32_t aH[8][4];
#pragma unroll
        for (int nt = 0; nt < 16; nt++) {
            int ks = nt >> 1, j0 = (nt & 1) * 2;
            aH[ks][j0]     = pack2h(acc[nt][0], acc[nt][1]);
            aH[ks][j0 + 1] = pack2h(acc[nt][2], acc[nt][3]);
        }
        {
            const uint4* w1 = (const uint4*)g_Wp1[1];
            const uint4* w3 = (const uint4*)g_Wp3[1];
#pragma unroll
            for (int i = 0; i < 8; i++) {
                int g = tid + i * 256;
                int n = g >> 4, q = g & 15;
                *(uint4*)(smem + UX_AH + n * UXST + q * 16) = w1[g];
                *(uint4*)(smem + UX_WH + n * UXST + q * 16) = w3[g];
            }
        }
        __syncthreads();
#pragma unroll
        for (int o = 0; o < 2; o++) {
            const uint32_t bA = sb + (o ? UX_WH : UX_AH) + bOff;
            float q[16][4];
#pragma unroll
            for (int n = 0; n < 16; n++)
#pragma unroll
                for (int j = 0; j < 4; j++) q[n][j] = 0.f;
#pragma unroll
            for (int ks = 0; ks < 8; ks++) {
#pragma unroll
                for (int np = 0; np < 8; np++) {
                    uint32_t b0, b1, b2, b3;
                    ldsm4(b0, b1, b2, b3, bA + np * (16 * UXST) + ks * 32);
                    mma16816h(q[2 * np],     aH[ks][0], aH[ks][1], aH[ks][2], aH[ks][3], b0, b1);
                    mma16816h(q[2 * np + 1], aH[ks][0], aH[ks][1], aH[ks][2], aH[ks][3], b2, b3);
                }
            }
            __half* out = o ? g_P3 : g_P1;
#pragma unroll
            for (int nt = 0; nt < 16; nt++) {
                int col = nt * 8 + cb;
                if (row0 < NN)
                    *(uint32_t*)&out[(size_t)row0 * HID + col] = pack2h(q[nt][0], q[nt][1]);
                if (row1 < NN)
                    *(uint32_t*)&out[(size_t)row1 * HID + col] = pack2h(q[nt][2], q[nt][3]);
            }
        }
    } else {
        uint32_t aH[8][4], aL[8][4];
#pragma unroll
        for (int nt = 0; nt < 16; nt++) {
            int ks = nt >> 1, j0 = (nt & 1) * 2;
            split2h(acc[nt][0], acc[nt][1], aH[ks][j0],     aL[ks][j0]);
            split2h(acc[nt][2], acc[nt][3], aH[ks][j0 + 1], aL[ks][j0 + 1]);
        }
        {
            const uint4* q1h = (const uint4*)g_Wq1h;
            const uint4* q1l = (const uint4*)g_Wq1l;
            const uint4* q3h = (const uint4*)g_Wq3h;
            const uint4* q3l = (const uint4*)g_Wq3l;
#pragma unroll
            for (int i = 0; i < 8; i++) {
                int g = tid + i * 256;
                int n = g >> 4, q = g & 15;
                *(uint4*)(smem + UX_AH + n * UXST + q * 16) = q1h[g];
                *(uint4*)(smem + UX_AL + n * UXST + q * 16) = q1l[g];
                *(uint4*)(smem + UX_WH + n * UXST + q * 16) = q3h[g];
                *(uint4*)(smem + UX_WL + n * UXST + q * 16) = q3l[g];
            }
        }
        __syncthreads();
#pragma unroll
        for (int o = 0; o < 2; o++) {
            const uint32_t bHA = sb + (o ? UX_WH : UX_AH) + bOff;
            const uint32_t bLA = sb + (o ? UX_WL : UX_AL) + bOff;
            float q[16][4];
#pragma unroll
            for (int n = 0; n < 16; n++)
#pragma unroll
                for (int j = 0; j < 4; j++) q[n][j] = 0.f;
#pragma unroll
            for (int ks = 0; ks < 8; ks++) {
#pragma unroll
                for (int np = 0; np < 8; np++) {
                    uint32_t bh0, bh1, bh2, bh3, bl0, bl1, bl2, bl3;
                    ldsm4(bh0, bh1, bh2, bh3, bHA + np * (16 * UXST) + ks * 32);
                    ldsm4(bl0, bl1, bl2, bl3, bLA + np * (16 * UXST) + ks * 32);
                    mma16816h(q[2 * np],     aH[ks][0], aH[ks][1], aH[ks][2], aH[ks][3], bh0, bh1);
                    mma16816h(q[2 * np],     aH[ks][0], aH[ks][1], aH[ks][2], aH[ks][3], bl0, bl1);
                    mma16816h(q[2 * np],     aL[ks][0], aL[ks][1], aL[ks][2], aL[ks][3], bh0, bh1);
                    mma16816h(q[2 * np + 1], aH[ks][0], aH[ks][1], aH[ks][2], aH[ks][3], bh2, bh3);
                    mma16816h(q[2 * np + 1], aH[ks][0], aH[ks][1], aH[ks][2], aH[ks][3], bl2, bl3);
                    mma16816h(q[2 * np + 1], aL[ks][0], aL[ks][1], aL[ks][2], aL[ks][3], bh2, bh3);
                }
            }
            float* out = o ? g_Q3 : g_Q1;
#pragma unroll
            for (int nt = 0; nt < 16; nt++) {
                int col = nt * 8 + cb;
                if (row0 < NN)
                    *(float2*)&out[(size_t)row0 * HID + col] = make_float2(q[nt][0], q[nt][1]);
                if (row1 < NN)
                    *(float2*)&out[(size_t)row1 * HID + col] = make_float2(q[nt][2], q[nt][3]);
            }
        }
    }
}

// ====================== pipelined fp16 MMA-chain edge kernel (M=128) ========
#define SM_BM    0
#define SM_BE    512
#define SM_IDX   1024
#define SM_WEH   3072
#define SM_EFH0  9216
#define SM_EFH1  15360
#define SM_BW    21504
#define SM_OUT   56320
#define SM_TOTAL 91136
#define TSTRIDE  272
#define EFST     48

__global__ void __launch_bounds__(256, 2)
msg_v13(int layer, const float* __restrict__ We, const float* __restrict__ be,
        const float* __restrict__ bm)
{
    extern __shared__ __align__(16) char smem[];
    const uint32_t sb = smem_u32(smem);
    const int tid = threadIdx.x;
    const int wid = tid >> 5, lane = tid & 31;

    float* sBm = (float*)(smem + SM_BM);
    float* beS = (float*)(smem + SM_BE);
    __half* OUT = (__half*)(smem + SM_OUT);

    if (tid < 128) {
        sBm[tid] = bm[tid]; beS[tid] = be[tid];
        int n = tid;
        uint32_t h8[8];
#pragma unroll
        for (int p = 0; p < 8; p++)
            h8[p] = pack2h(We[(2 * p) * 128 + n], We[(2 * p + 1) * 128 + n]);
        *(uint4*)(smem + SM_WEH + n * EFST)      = make_uint4(h8[0], h8[1], h8[2], h8[3]);
        *(uint4*)(smem + SM_WEH + n * EFST + 16) = make_uint4(h8[4], h8[5], h8[6], h8[7]);
    }
    {
        const uint4* wsrc = (const uint4*)g_Wh[layer];
#pragma unroll
        for (int u = 0; u < 8; u++) {
            int g = tid + u * 256;
            int n = g >> 4, q = g & 15;
            *(uint4*)(smem + SM_BW + n * TSTRIDE + q * 16) = wsrc[g];
        }
    }

    const int wm = wid * 16;
    const uint32_t aEfOff = (uint32_t)((wm + (lane & 7) + ((lane >> 3) & 1) * 8) * EFST
                                       + (lane >> 4) * 16);
    const uint32_t bEfOff = (uint32_t)(((lane & 7) + (lane >> 4) * 8) * EFST
                                       + ((lane >> 3) & 1) * 16);
    const uint32_t bMnOff = (uint32_t)(((lane & 7) + (lane >> 4) * 8) * TSTRIDE
                                       + (((lane >> 3) & 1) * 8) * 2);
    const uint32_t wehA = sb + SM_WEH + bEfOff;
    const uint32_t bwA  = sb + SM_BW + bMnOff;

    const int er0 = wm + (lane >> 2);
    const int cb  = (lane & 3) * 2;
    const int NT = NE / 128;

    auto stage_async = [&](int t, int b) {
        const int eBase = t * 128;
        uint32_t efh = sb + (b ? SM_EFH1 : SM_EFH0);
        {
            int r = tid >> 1, u = tid & 1;
            cp16(efh + r * EFST + u * 16, (const char*)(g_efh + (size_t)(eBase + r) * 16) + u * 16);
        }
        if (tid < 32)
            cp16(sb + SM_IDX + b * 1024 + tid * 16, (const char*)(g_srcp + eBase) + tid * 16);
        else if (tid < 64)
            cp16(sb + SM_IDX + b * 1024 + 512 + (tid - 32) * 16, (const char*)(g_dstp + eBase) + (tid - 32) * 16);
    };

    int t = blockIdx.x;
    int buf = 0;
    if (t < NT) stage_async(t, 0);
    CP_COMMIT();

    for (; t < NT; t += gridDim.x, buf ^= 1) {
        CP_WAIT(0);
        __syncthreads();

        int* sSrc = (int*)(smem + SM_IDX + buf * 1024);
        int* sDst = (int*)(smem + SM_IDX + buf * 1024 + 512);

        {
#pragma unroll
            for (int i = 0; i < 8; i++) {
                int g = tid + i * 256;
                int r = g >> 4, c = g & 15;
                const char* src = (const char*)(g_P1 + (size_t)sSrc[r] * HID) + c * 16;
                cp16(sb + SM_OUT + r * TSTRIDE + c * 16, src);
            }
        }
        CP_COMMIT();

        int tn = t + gridDim.x;
        if (tn < NT) stage_async(tn, buf ^ 1);
        CP_COMMIT();

        const uint32_t efhA = sb + (buf ? SM_EFH1 : SM_EFH0) + aEfOff;
        float acc2[16][4];
#pragma unroll
        for (int n = 0; n < 16; n++)
#pragma unroll
            for (int j = 0; j < 4; j++) acc2[n][j] = 0.f;
        {
            uint32_t eh0, eh1, eh2, eh3;
            ldsm4(eh0, eh1, eh2, eh3, efhA);
#pragma unroll
            for (int g = 0; g < 8; g++) {
                uint32_t wh0, wh1, wh2, wh3;
                ldsm4(wh0, wh1, wh2, wh3, wehA + g * (16 * EFST));
                mma16816h(acc2[2 * g],     eh0, eh1, eh2, eh3, wh0, wh1);
                mma16816h(acc2[2 * g + 1], eh0, eh1, eh2, eh3, wh2, wh3);
            }
        }

        uint32_t aH[8][4];
#pragma unroll
        for (int nt = 0; nt < 16; nt++) {
            int col = nt * 8 + cb;
            float be0 = beS[col], be1 = beS[col + 1];
            float v0 = fmaxf(acc2[nt][0] + be0, 0.f);
            float v1 = fmaxf(acc2[nt][1] + be1, 0.f);
            float v2 = fmaxf(acc2[nt][2] + be0, 0.f);
            float v3 = fmaxf(acc2[nt][3] + be1, 0.f);
            int ks = nt >> 1, j0 = (nt & 1) * 2;
            aH[ks][j0]     = pack2h(v0, v1);
            aH[ks][j0 + 1] = pack2h(v2, v3);
        }

        float acc[16][4];
#pragma unroll
        for (int n = 0; n < 16; n++)
#pragma unroll
            for (int j = 0; j < 4; j++) acc[n][j] = 0.f;
#pragma unroll
        for (int ks = 0; ks < 8; ks++) {
#pragma unroll
            for (int np = 0; np < 8; np++) {
                uint32_t b0, b1, b2, b3;
                ldsm4(b0, b1, b2, b3, bwA + np * (16 * TSTRIDE) + ks * 32);
                mma16816h(acc[2 * np],     aH[ks][0], aH[ks][1], aH[ks][2], aH[ks][3], b0, b1);
                mma16816h(acc[2 * np + 1], aH[ks][0], aH[ks][1], aH[ks][2], aH[ks][3], b2, b3);
            }
        }

        CP_WAIT(1);
        __syncthreads();

        {
            int d0 = sDst[er0], d1 = sDst[er0 + 8];
            const __half* p3a = g_P3 + (size_t)d0 * HID;
            const __half* p3b = g_P3 + (size_t)d1 * HID;
            const __half* p1a = OUT + er0 * 136;
            const __half* p1b = OUT + (er0 + 8) * 136;
#pragma unroll
            for (int nt = 0; nt < 16; nt++) {
                int col = nt * 8 + cb;
                float2 q1 = __half22float2(*(const __half2*)(p1a + col));
                float2 q3 = __half22float2(*(const __half2*)(p3a + col));
                float o0 = fmaxf(acc[nt][0] + sBm[col]     + q1.x + q3.x, 0.f);
                float o1 = fmaxf(acc[nt][1] + sBm[col + 1] + q1.y + q3.y, 0.f);
                *(uint32_t*)(OUT + er0 * 136 + col) = pack2h(o0, o1);
                float2 r1 = __half22float2(*(const __half2*)(p1b + col));
                float2 r3 = __half22float2(*(const __half2*)(p3b + col));
                float o2 = fmaxf(acc[nt][2] + sBm[col]     + r1.x + r3.x, 0.f);
                float o3 = fmaxf(acc[nt][3] + sBm[col + 1] + r1.y + r3.y, 0.f);
                *(uint32_t*)(OUT + (er0 + 8) * 136 + col) = pack2h(o2, o3);
            }
        }
        __syncthreads();

        // ---- segmented reduction: 256 threads, rows split in 2 halves
        {
            int col = tid & 127;
            int rh  = tid >> 7;              // 0/1
            int rbase = rh * 64;
            float s = 0.f;
            int cur = sDst[rbase];
#pragma unroll 4
            for (int r2 = rbase; r2 < rbase + 64; r2++) {
                int dn = sDst[r2];
                if (dn != cur) {
                    if (s != 0.f) atomicAdd(&g_agg[(size_t)cur * HID + col], s);
                    cur = dn; s = 0.f;
                }
                s += __half2float(OUT[r2 * 136 + col]);
            }
            if (s != 0.f) atomicAdd(&g_agg[(size_t)cur * HID + col], s);
        }
        __syncthreads();
    }
}

// --------------------------------------------- fused demand readout
__global__ void __launch_bounds__(256)
dem_v2(const int* __restrict__ pairs, const float* __restrict__ dfeat,
       const float* __restrict__ Wd, const float* __restrict__ br1,
       const float* __restrict__ w2, const float* __restrict__ b2,
       float* __restrict__ out)
{
    __shared__ __align__(16) float Wds[8][132];
    __shared__ float w2s[128], bs[128];
    int tid = threadIdx.x;
    if (tid < 128) { w2s[tid] = w2[tid]; bs[tid] = br1[tid]; }
    {
        int row = tid >> 5, c = (tid & 31) * 4;
        *(float4*)&Wds[row][c] = ((const float4*)Wd)[tid];
    }
    __syncthreads();

    int w = tid >> 5, lane = tid & 31;
    int d = blockIdx.x * 8 + w;
    int ds = pairs[2 * d], dd = pairs[2 * d + 1];
    int c0 = lane * 4;

    float4 q1 = *(const float4*)(g_Q1 + (size_t)ds * HID + c0);
    float4 q2 = *(const float4*)(g_Q3 + (size_t)dd * HID + c0);
    float s0 = bs[c0 + 0] + q1.x + q2.x;
    float s1 = bs[c0 + 1] + q1.y + q2.y;
    float s2 = bs[c0 + 2] + q1.z + q2.z;
    float s3 = bs[c0 + 3] + q1.w + q2.w;
#pragma unroll
    for (int q = 0; q < 8; q++) {
        float e = dfeat[(size_t)d * 8 + q];
        float4 wv = *(const float4*)&Wds[q][c0];
        s0 = fmaf(e, wv.x, s0); s1 = fmaf(e, wv.y, s1);
        s2 = fmaf(e, wv.z, s2); s3 = fmaf(e, wv.w, s3);
    }
    float p = fmaxf(s0, 0.f) * w2s[c0 + 0] + fmaxf(s1, 0.f) * w2s[c0 + 1]
            + fmaxf(s2, 0.f) * w2s[c0 + 2] + fmaxf(s3, 0.f) * w2s[c0 + 3];
#pragma unroll
    for (int o = 16; o > 0; o >>= 1) p += __shfl_xor_sync(0xffffffffu, p, o);
    if (lane == 0) out[d] = 1.f / (1.f + expf(-(p + b2[0])));
}

// ---------------------------------------------------------------- launch
extern "C" void kernel_launch(void* const* d_in, const int* in_sizes, int n_in,
                              void* d_out, int out_size)
{
    const float* node_feats = (const float*)d_in[0];
    const float* edge_feats = (const float*)d_in[1];
    const float* dem_feats  = (const float*)d_in[2];
    const int*   eidx       = (const int*)d_in[3];
    const int*   pairs      = (const int*)d_in[4];
    const float* W_node = (const float*)d_in[5];
    const float* b_node = (const float*)d_in[6];
    const float* W_edge = (const float*)d_in[7];
    const float* b_edge = (const float*)d_in[8];
    const float* W_msg0 = (const float*)d_in[9];
    const float* b_msg0 = (const float*)d_in[10];
    const float* W_upd0 = (const float*)d_in[11];
    const float* b_upd0 = (const float*)d_in[12];
    const float* W_msg1 = (const float*)d_in[13];
    const float* b_msg1 = (const float*)d_in[14];
    const float* W_upd1 = (const float*)d_in[15];
    const float* b_upd1 = (const float*)d_in[16];
    const float* W_r1   = (const float*)d_in[17];
    const float* b_r1   = (const float*)d_in[18];
    const float* W_r2   = (const float*)d_in[19];
    const float* b_r2   = (const float*)d_in[20];
    float* out = (float*)d_out;

    const int nTiles = (NN + 127) / 128;

    cudaFuncSetAttribute(msg_v13, cudaFuncAttributeMaxDynamicSharedMemorySize, SM_TOTAL);
    cudaFuncSetAttribute(embed_p, cudaFuncAttributeMaxDynamicSharedMemorySize, EB_TOTAL);
    cudaFuncSetAttribute(upd_x,   cudaFuncAttributeMaxDynamicSharedMemorySize, UX_TOTAL);

    // ---- fork a side stream for the node-side prologue
    cudaStream_t s2;
    cudaStreamCreateWithFlags(&s2, cudaStreamNonBlocking);
    cudaEvent_t evFork, evJoin;
    cudaEventCreateWithFlags(&evFork, cudaEventDisableTiming);
    cudaEventCreateWithFlags(&evJoin, cudaEventDisableTiming);

    cudaEventRecord(evFork, 0);
    cudaStreamWaitEvent(s2, evFork, 0);

    prep_all<<<13, 256, 0, s2>>>(W_msg0, W_msg1, W_upd0, W_upd1, W_r1, W_node);
    embed_p<<<nTiles, 256, EB_TOTAL, s2>>>(node_feats, b_node);
    cudaEventRecord(evJoin, s2);

    zcnt<<<(NN + 256) / 256, 256>>>();
    hist<<<NE / 256, 256>>>(eidx);
    scan20k<<<1, 1024>>>();
    scatter<<<NE / 256, 256>>>(eidx, edge_feats);

    cudaStreamWaitEvent(0, evJoin, 0);

    // ---- layer 0
    msg_v13<<<304, 256, SM_TOTAL>>>(0, W_edge, b_edge, b_msg0);
    upd_x<<<nTiles, 256, UX_TOTAL>>>(0, b_upd0);   // chains layer-1 P1/P3 + agg zero

    // ---- layer 1
    msg_v13<<<304, 256, SM_TOTAL>>>(1, W_edge, b_edge, b_msg1);
    upd_x<<<nTiles, 256, UX_TOTAL>>>(1, b_upd1);   // chains readout Q1/Q3 (fp32)

    // ---- readout
    dem_v2<<<ND / 8, 256>>>(pairs, dem_feats, W_r1 + 256 * HID, b_r1, W_r2, b_r2, out);

    cudaEventDestroy(evFork);
    cudaEventDestroy(evJoin);
    cudaStreamDestroy(s2);
}